// round 8
// baseline (speedup 1.0000x reference)
#include <cuda_runtime.h>
#include <cuda_bf16.h>
#include <cstdint>

#define N_NODES   20000
#define N_EDGES   320000
#define NUM_HEADS 8
#define NEG_SLOPE 0.2f

// ---------------- device scratch ----------------
__device__ float g_node_tbl[N_NODES * 640];   // [0:256)=ni_h, [256:512)=nj_h, [512:640)=node msg part
__device__ float g_ex[N_EDGES * NUM_HEADS];
__device__ float g_msg[N_EDGES * 128];
__device__ float g_node_sum[N_NODES * NUM_HEADS];
__device__ float g_agg[N_NODES * 128];
// prepacked weights (bf16 hi/lo splits, [n][k] k-contiguous == col-major B for mma)
__device__ __nv_bfloat16 g_WNh[640 * 128];
__device__ __nv_bfloat16 g_WNl[640 * 128];
__device__ __nv_bfloat16 g_WEh[384 * 128];
__device__ __nv_bfloat16 g_WEl[384 * 128];
__device__ float g_bN[640];
__device__ float g_bE[384];
__device__ float g_WO[128 * 128];             // [k][n] for FFMA out gemm

// ---------------- helpers ----------------
__device__ __forceinline__ uint32_t smem_u32(const void* p) {
    uint32_t a;
    asm("{ .reg .u64 t; cvta.to.shared.u64 t, %1; cvt.u32.u64 %0, t; }" : "=r"(a) : "l"(p));
    return a;
}

#define LDSM_X4(r0, r1, r2, r3, addr) \
    asm volatile("ldmatrix.sync.aligned.m8n8.x4.shared.b16 {%0,%1,%2,%3}, [%4];" \
                 : "=r"(r0), "=r"(r1), "=r"(r2), "=r"(r3) : "r"(addr))

#define MMA_BF16(c, a, b) \
    asm volatile("mma.sync.aligned.m16n8k16.row.col.f32.bf16.bf16.f32 " \
                 "{%0,%1,%2,%3}, {%4,%5,%6,%7}, {%8,%9}, {%0,%1,%2,%3};" \
                 : "+f"((c)[0]), "+f"((c)[1]), "+f"((c)[2]), "+f"((c)[3]) \
                 : "r"((a)[0]), "r"((a)[1]), "r"((a)[2]), "r"((a)[3]), \
                   "r"((b)[0]), "r"((b)[1]))

#define CP_ASYNC16(dst, src) \
    asm volatile("cp.async.ca.shared.global [%0], [%1], 16;" :: "r"(dst), "l"(src))
#define CP_COMMIT()  asm volatile("cp.async.commit_group;" ::: "memory")
#define CP_WAIT0()   asm volatile("cp.async.wait_group 0;" ::: "memory")

// smem layout (bytes): pitch 272 B (128 bf16 + 16B pad)
// A hi/lo 128x128, B double-buffered 128(N) x 128(K) hi/lo
#define APITCH_B 272
#define SM_AH 0
#define SM_AL 34816
#define SM_B0 69632          // buffer 0: H at +0, L at +34816
#define SM_B1 139264         // buffer 1
#define SM_BSZ 69632
#define SM_TOT 208896        // <= 227 KB, 1 CTA of 1024 threads per SM

// ---------------- init kernels ----------------
__global__ void zero_kernel() {
    int i = blockIdx.x * blockDim.x + threadIdx.x;
    const int NS = N_NODES * NUM_HEADS;
    const int TOT = NS + N_NODES * 128;
    if (i < NS) g_node_sum[i] = 0.f;
    else if (i < TOT) g_agg[i - NS] = 0.f;
}

__device__ __forceinline__ void split_store(float v, __nv_bfloat16* hi, __nv_bfloat16* lo, int i) {
    __nv_bfloat16 h = __float2bfloat16(v);
    hi[i] = h;
    lo[i] = __float2bfloat16(v - __bfloat162float(h));
}

__global__ void prepack_kernel(const float* __restrict__ Wni, const float* __restrict__ bni,
                               const float* __restrict__ Wnj, const float* __restrict__ bnj,
                               const float* __restrict__ We,  const float* __restrict__ be,
                               const float* __restrict__ Wm,  const float* __restrict__ bm,
                               const float* __restrict__ Wo) {
    int i = blockIdx.x * blockDim.x + threadIdx.x;
    if (i < 81920) {                       // WN [640][128]
        int n = i >> 7, k = i & 127;
        float v;
        if (n < 256)      v = Wni[n * 128 + k];
        else if (n < 512) v = Wnj[(n - 256) * 128 + k];
        else              v = Wm[(n - 512) * 256 + k];
        split_store(v, g_WNh, g_WNl, i);
    }
    if (i < 49152) {                       // WE [384][128]
        int n = i >> 7, k = i & 127;
        float v = (n < 256) ? We[n * 128 + k] : Wm[(n - 256) * 256 + 128 + k];
        split_store(v, g_WEh, g_WEl, i);
    }
    if (i < 640) g_bN[i] = (i < 256) ? bni[i] : (i < 512 ? bnj[i - 256] : 0.f);
    if (i < 384) g_bE[i] = (i < 256) ? be[i] : bm[i - 256];
    if (i < 16384) {                       // WO [k][n]
        int k = i >> 7, n = i & 127;
        g_WO[i] = Wo[n * 128 + k];
    }
}

// issue cp.async fills for one 128-row B tile (hi+lo) into buffer at smem byte offset bbase
__device__ __forceinline__ void issue_b(uint32_t sb, uint32_t bbase,
                                        const __nv_bfloat16* Bh, const __nv_bfloat16* Bl,
                                        int nt, int tid) {
    const __nv_bfloat16* bh = Bh + (size_t)nt * 128 * 128;
    const __nv_bfloat16* bl = Bl + (size_t)nt * 128 * 128;
#pragma unroll
    for (int u = tid; u < 2048; u += 1024) {
        int r = u >> 4, c16 = u & 15;      // row, 16B-chunk (8 bf16)
        uint32_t doff = bbase + r * APITCH_B + c16 * 16;
        CP_ASYNC16(sb + doff,          bh + (size_t)r * 128 + c16 * 8);
        CP_ASYNC16(sb + doff + 34816,  bl + (size_t)r * 128 + c16 * 8);
    }
    CP_COMMIT();
}

// ---------------- HMMA split-bf16 GEMM, cp.async double-buffered B ----------------
// 1024 threads = 32 warps: wm = wid>>2 (16-row strip, 0..7), wn = wid&3 (32-col group, 0..3)
// mode 0: node tables, NB=5 (128-wide tiles) -> g_node_tbl (+bias)
// mode 1: edge pass,  NB=3; nt 0,1 -> attention epilogue (head = nt*4+wn); nt 2 -> messages
__global__ void __launch_bounds__(1024, 1) mma_kernel(
    int mode, const float* __restrict__ A, int M, int NB,
    const int* __restrict__ EI, const float* __restrict__ AP) {
    extern __shared__ char smem[];
    uint32_t sb = smem_u32(smem);
    int tid = threadIdx.x;
    int wid = tid >> 5, lid = tid & 31;
    int m0 = blockIdx.x * 128;

    const __nv_bfloat16* BhBase = (mode == 0) ? g_WNh : g_WEh;
    const __nv_bfloat16* BlBase = (mode == 0) ? g_WNl : g_WEl;

    // prefetch B(0) first (cp.async, no regs), then build A while it flies
    issue_b(sb, SM_B0, BhBase, BlBase, 0, tid);

    // ---- fill A tile once: f32 -> hi/lo bf16 ----
#pragma unroll
    for (int u = tid; u < 4096; u += 1024) {
        int r = u >> 5, c = (u & 31) << 2;
        int row = m0 + r;
        float4 v = make_float4(0.f, 0.f, 0.f, 0.f);
        if (row < M) v = *(const float4*)(A + (size_t)row * 128 + c);
        __nv_bfloat162 h01 = __floats2bfloat162_rn(v.x, v.y);
        __nv_bfloat162 h23 = __floats2bfloat162_rn(v.z, v.w);
        float2 f01 = __bfloat1622float2(h01);
        float2 f23 = __bfloat1622float2(h23);
        __nv_bfloat162 l01 = __floats2bfloat162_rn(v.x - f01.x, v.y - f01.y);
        __nv_bfloat162 l23 = __floats2bfloat162_rn(v.z - f23.x, v.w - f23.y);
        uint32_t off = r * APITCH_B + c * 2;
        *(uint2*)(smem + SM_AH + off) = make_uint2(*(uint32_t*)&h01, *(uint32_t*)&h23);
        *(uint2*)(smem + SM_AL + off) = make_uint2(*(uint32_t*)&l01, *(uint32_t*)&l23);
    }

    int wm = wid >> 2, wn = wid & 3;
    int lr = lid & 15, lc = lid >> 4;
    int q  = lid >> 2, lq = lid & 3;

    // per-lane edge rows (fixed across tiles)
    int r0 = m0 + wm * 16 + q;
    int r1 = r0 + 8;
    int s0 = 0, d0 = 0, s1 = 0, d1 = 0;
    if (mode == 1) {
        s0 = EI[r0]; d0 = EI[N_EDGES + r0];
        s1 = EI[r1]; d1 = EI[N_EDGES + r1];
    }

    for (int nt = 0; nt < NB; nt++) {
        uint32_t bbase = (nt & 1) ? SM_B1 : SM_B0;
        CP_WAIT0();          // B(nt) slices issued by this thread have landed
        __syncthreads();     // whole tile visible; all warps done with other buffer

        // prefetch B(nt+1) into the other buffer (overlaps MMA + epilogue below)
        if (nt + 1 < NB)
            issue_b(sb, (nt & 1) ? SM_B0 : SM_B1, BhBase, BlBase, nt + 1, tid);

        // ---- MMA over K=128: warp tile 16 rows x 32 cols ----
        float acc[4][4];
#pragma unroll
        for (int f = 0; f < 4; f++)
#pragma unroll
            for (int j = 0; j < 4; j++) acc[f][j] = 0.f;

#pragma unroll
        for (int ks = 0; ks < 8; ks++) {
            int kc = ks * 16;
            uint32_t ah[4], al[4], bhf[4][2], blf[4][2];
            uint32_t aoff = (uint32_t)((wm * 16 + lr) * APITCH_B + (kc + lc * 8) * 2);
            LDSM_X4(ah[0], ah[1], ah[2], ah[3], sb + SM_AH + aoff);
            LDSM_X4(al[0], al[1], al[2], al[3], sb + SM_AL + aoff);
#pragma unroll
            for (int g = 0; g < 2; g++) {
                uint32_t boff = bbase + (uint32_t)((wn * 32 + g * 16 + lr) * APITCH_B + (kc + lc * 8) * 2);
                uint32_t t0, t1, t2, t3;
                LDSM_X4(t0, t1, t2, t3, sb + boff);
                bhf[2 * g][0] = t0; bhf[2 * g][1] = t2;
                bhf[2 * g + 1][0] = t1; bhf[2 * g + 1][1] = t3;
                LDSM_X4(t0, t1, t2, t3, sb + boff + 34816);
                blf[2 * g][0] = t0; blf[2 * g][1] = t2;
                blf[2 * g + 1][0] = t1; blf[2 * g + 1][1] = t3;
            }
#pragma unroll
            for (int f = 0; f < 4; f++) MMA_BF16(acc[f], ah, bhf[f]);
#pragma unroll
            for (int f = 0; f < 4; f++) MMA_BF16(acc[f], ah, blf[f]);
#pragma unroll
            for (int f = 0; f < 4; f++) MMA_BF16(acc[f], al, bhf[f]);
        }

        // ---- register epilogue (no smem use; overlaps in-flight cp.async) ----
        if (mode == 0) {
            int cg0 = nt * 128 + wn * 32;
#pragma unroll
            for (int f = 0; f < 4; f++) {
                int cg = cg0 + f * 8 + lq * 2;
                float2 b2 = *(const float2*)(g_bN + cg);
                if (r0 < M)
                    *(float2*)(g_node_tbl + (size_t)r0 * 640 + cg) =
                        make_float2(acc[f][0] + b2.x, acc[f][1] + b2.y);
                if (r1 < M)
                    *(float2*)(g_node_tbl + (size_t)r1 * 640 + cg) =
                        make_float2(acc[f][2] + b2.x, acc[f][3] + b2.y);
            }
        } else if (nt < 2) {
            int head = nt * 4 + wn;
            int cg0 = nt * 128 + wn * 32;
            float p0 = 0.f, p1 = 0.f;
#pragma unroll
            for (int f = 0; f < 4; f++) {
                int cl = f * 8 + lq * 2;
                int cg = cg0 + cl;
                float2 b2  = *(const float2*)(g_bE + cg);
                float2 ap2 = *(const float2*)(AP + head * 32 + cl);
                float2 ni0 = *(const float2*)(g_node_tbl + (size_t)s0 * 640 + cg);
                float2 nj0 = *(const float2*)(g_node_tbl + (size_t)d0 * 640 + 256 + cg);
                float2 ni1 = *(const float2*)(g_node_tbl + (size_t)s1 * 640 + cg);
                float2 nj1 = *(const float2*)(g_node_tbl + (size_t)d1 * 640 + 256 + cg);
                float h;
                h = acc[f][0] + b2.x + ni0.x + nj0.x; h = (h >= 0.f) ? h : NEG_SLOPE * h; p0 += h * ap2.x;
                h = acc[f][1] + b2.y + ni0.y + nj0.y; h = (h >= 0.f) ? h : NEG_SLOPE * h; p0 += h * ap2.y;
                h = acc[f][2] + b2.x + ni1.x + nj1.x; h = (h >= 0.f) ? h : NEG_SLOPE * h; p1 += h * ap2.x;
                h = acc[f][3] + b2.y + ni1.y + nj1.y; h = (h >= 0.f) ? h : NEG_SLOPE * h; p1 += h * ap2.y;
            }
            p0 += __shfl_xor_sync(0xffffffffu, p0, 1);
            p0 += __shfl_xor_sync(0xffffffffu, p0, 2);
            p1 += __shfl_xor_sync(0xffffffffu, p1, 1);
            p1 += __shfl_xor_sync(0xffffffffu, p1, 2);
            if (lq == 0) {
                float e0 = expf(p0), e1 = expf(p1);
                g_ex[r0 * 8 + head] = e0;
                g_ex[r1 * 8 + head] = e1;
                atomicAdd(&g_node_sum[s0 * 8 + head], e0);
                atomicAdd(&g_node_sum[s1 * 8 + head], e1);
            }
        } else {
            int cm0 = wn * 32;
#pragma unroll
            for (int f = 0; f < 4; f++) {
                int cm = cm0 + f * 8 + lq * 2;
                float2 b2  = *(const float2*)(g_bE + 256 + cm);
                float2 nm0 = *(const float2*)(g_node_tbl + (size_t)d0 * 640 + 512 + cm);
                float2 nm1 = *(const float2*)(g_node_tbl + (size_t)d1 * 640 + 512 + cm);
                *(float2*)(g_msg + (size_t)r0 * 128 + cm) =
                    make_float2(acc[f][0] + b2.x + nm0.x, acc[f][1] + b2.y + nm0.y);
                *(float2*)(g_msg + (size_t)r1 * 128 + cm) =
                    make_float2(acc[f][2] + b2.x + nm1.x, acc[f][3] + b2.y + nm1.y);
            }
        }
    }
}

// ---------------- softmax-weight + scatter-aggregate ----------------
__global__ void agg_kernel(const int* __restrict__ EI) {
    int e = (blockIdx.x * blockDim.x + threadIdx.x) >> 5;
    int lane = threadIdx.x & 31;
    if (e >= N_EDGES) return;
    int s = EI[e];
    int head = lane >> 2;
    float ex = g_ex[e * 8 + head];
    float sum = g_node_sum[s * 8 + head];
    float w = ex / sum;
    float4 m = *(const float4*)(g_msg + (size_t)e * 128 + lane * 4);
    float* dst = g_agg + (size_t)s * 128 + lane * 4;
    asm volatile("red.global.add.v4.f32 [%0], {%1,%2,%3,%4};"
                 :: "l"(dst), "f"(m.x * w), "f"(m.y * w), "f"(m.z * w), "f"(m.w * w)
                 : "memory");
}

// ---------------- FFMA GEMM for the small output projection ----------------
__global__ void gemm_kernel(const float* __restrict__ A, const float* __restrict__ B,
                            const float* __restrict__ bias, float* __restrict__ C,
                            int M, int N, int K) {
    __shared__ float As[16][64];
    __shared__ float Bs[16][64];
    int tid = threadIdx.x;
    int rt = tid >> 4, ct = tid & 15;
    int m0 = blockIdx.x * 64, n0 = blockIdx.y * 64;
    float acc[4][4] = {};
    int arow = tid >> 2, aq = tid & 3;
    int bk = tid >> 4, bq = tid & 15;
    for (int k0 = 0; k0 < K; k0 += 16) {
        float4 av = make_float4(0.f, 0.f, 0.f, 0.f);
        if (m0 + arow < M)
            av = *(const float4*)(A + (size_t)(m0 + arow) * K + k0 + aq * 4);
        As[aq * 4 + 0][arow] = av.x; As[aq * 4 + 1][arow] = av.y;
        As[aq * 4 + 2][arow] = av.z; As[aq * 4 + 3][arow] = av.w;
        float4 bv = *(const float4*)(B + (size_t)(k0 + bk) * N + n0 + bq * 4);
        *(float4*)&Bs[bk][bq * 4] = bv;
        __syncthreads();
#pragma unroll
        for (int kk = 0; kk < 16; kk++) {
            float a[4], b[4];
            *(float4*)a = *(float4*)&As[kk][rt * 4];
            *(float4*)b = *(float4*)&Bs[kk][ct * 4];
#pragma unroll
            for (int i = 0; i < 4; i++)
#pragma unroll
                for (int j = 0; j < 4; j++)
                    acc[i][j] += a[i] * b[j];
        }
        __syncthreads();
    }
#pragma unroll
    for (int i = 0; i < 4; i++) {
        int m = m0 + rt * 4 + i;
        if (m < M) {
            int n = n0 + ct * 4;
            float4 o;
            o.x = acc[i][0] + bias[n + 0];
            o.y = acc[i][1] + bias[n + 1];
            o.z = acc[i][2] + bias[n + 2];
            o.w = acc[i][3] + bias[n + 3];
            *(float4*)(C + (size_t)m * N + n) = o;
        }
    }
}

// ---------------- launch ----------------
extern "C" void kernel_launch(void* const* d_in, const int* in_sizes, int n_in,
                              void* d_out, int out_size) {
    const float* node_features = (const float*)d_in[0];
    const float* edge_features = (const float*)d_in[1];
    const int*   edge_index    = (const int*)d_in[2];
    const float* Wni = (const float*)d_in[3];
    const float* bni = (const float*)d_in[4];
    const float* Wnj = (const float*)d_in[5];
    const float* bnj = (const float*)d_in[6];
    const float* We  = (const float*)d_in[7];
    const float* be  = (const float*)d_in[8];
    const float* attn_proj = (const float*)d_in[9];
    const float* Wm  = (const float*)d_in[10];
    const float* bm  = (const float*)d_in[11];
    const float* Wo  = (const float*)d_in[12];
    const float* bo  = (const float*)d_in[13];
    float* out = (float*)d_out;

    float *pAgg, *pWO;
    cudaGetSymbolAddress((void**)&pAgg, g_agg);
    cudaGetSymbolAddress((void**)&pWO,  g_WO);

    static bool attr_set = false;
    if (!attr_set) {
        cudaFuncSetAttribute(mma_kernel, cudaFuncAttributeMaxDynamicSharedMemorySize, SM_TOT);
        attr_set = true;
    }

    const int ZTOT = N_NODES * NUM_HEADS + N_NODES * 128;
    zero_kernel<<<(ZTOT + 255) / 256, 256>>>();
    prepack_kernel<<<(81920 + 255) / 256, 256>>>(Wni, bni, Wnj, bnj, We, be, Wm, bm, Wo);

    // node tables: 157 M-tiles, 5 N-tiles of 128 looped in-kernel
    mma_kernel<<<(N_NODES + 127) / 128, 1024, SM_TOT>>>(
        0, node_features, N_NODES, 5, edge_index, attn_proj);

    // edge pass: 2500 M-tiles, 3 N-tiles of 128 looped in-kernel
    mma_kernel<<<N_EDGES / 128, 1024, SM_TOT>>>(
        1, edge_features, N_EDGES, 3, edge_index, attn_proj);

    // aggregate: one warp per edge
    agg_kernel<<<N_EDGES / 8, 256>>>(edge_index);

    // output projection
    gemm_kernel<<<dim3((N_NODES + 63) / 64, 2), 256>>>(pAgg, pWO, bo, out, N_NODES, 128, 128);
}

// round 9
// speedup vs baseline: 1.2220x; 1.2220x over previous
#include <cuda_runtime.h>
#include <cuda_bf16.h>
#include <cstdint>

#define N_NODES   20000
#define N_EDGES   320000
#define NUM_HEADS 8
#define NEG_SLOPE 0.2f

// ---------------- device scratch ----------------
__device__ float g_node_tbl[N_NODES * 640];   // [0:256)=ni_h, [256:512)=nj_h, [512:640)=node msg part
__device__ float g_node_sum[N_NODES * NUM_HEADS];   // softmax denominators
__device__ float g_agg[N_NODES * 128];              // UNNORMALIZED sum of ex*msg
// prepacked weights (bf16 hi/lo splits, [n][k] k-contiguous == col-major B for mma)
__device__ __nv_bfloat16 g_WNh[640 * 128];
__device__ __nv_bfloat16 g_WNl[640 * 128];
__device__ __nv_bfloat16 g_WEh[384 * 128];
__device__ __nv_bfloat16 g_WEl[384 * 128];
__device__ float g_bN[640];
__device__ float g_bE[384];
__device__ float g_WO[128 * 128];             // [k][n] for FFMA out gemm

// ---------------- helpers ----------------
__device__ __forceinline__ uint32_t smem_u32(const void* p) {
    uint32_t a;
    asm("{ .reg .u64 t; cvta.to.shared.u64 t, %1; cvt.u32.u64 %0, t; }" : "=r"(a) : "l"(p));
    return a;
}

#define LDSM_X4(r0, r1, r2, r3, addr) \
    asm volatile("ldmatrix.sync.aligned.m8n8.x4.shared.b16 {%0,%1,%2,%3}, [%4];" \
                 : "=r"(r0), "=r"(r1), "=r"(r2), "=r"(r3) : "r"(addr))

#define MMA_BF16(c, a, b) \
    asm volatile("mma.sync.aligned.m16n8k16.row.col.f32.bf16.bf16.f32 " \
                 "{%0,%1,%2,%3}, {%4,%5,%6,%7}, {%8,%9}, {%0,%1,%2,%3};" \
                 : "+f"((c)[0]), "+f"((c)[1]), "+f"((c)[2]), "+f"((c)[3]) \
                 : "r"((a)[0]), "r"((a)[1]), "r"((a)[2]), "r"((a)[3]), \
                   "r"((b)[0]), "r"((b)[1]))

// smem layout (bytes): A hi/lo 128x128 bf16 (pitch 272 B), B hi/lo 64x128 bf16, sEX
#define APITCH_B 272
#define SM_AH 0
#define SM_AL 34816
#define SM_BH 69632
#define SM_BL 87040
#define SM_EX 104448      // float sEX[128][8] = 4096 B
#define SM_TOT 108544     // <= ~113 KB -> 2 CTAs/SM

// ---------------- init kernels ----------------
__global__ void zero_kernel() {
    int i = blockIdx.x * blockDim.x + threadIdx.x;
    const int NS = N_NODES * NUM_HEADS;
    const int TOT = NS + N_NODES * 128;
    if (i < NS) g_node_sum[i] = 0.f;
    else if (i < TOT) g_agg[i - NS] = 0.f;
}

__device__ __forceinline__ void split_store(float v, __nv_bfloat16* hi, __nv_bfloat16* lo, int i) {
    __nv_bfloat16 h = __float2bfloat16(v);
    hi[i] = h;
    lo[i] = __float2bfloat16(v - __bfloat162float(h));
}

__global__ void prepack_kernel(const float* __restrict__ Wni, const float* __restrict__ bni,
                               const float* __restrict__ Wnj, const float* __restrict__ bnj,
                               const float* __restrict__ We,  const float* __restrict__ be,
                               const float* __restrict__ Wm,  const float* __restrict__ bm,
                               const float* __restrict__ Wo) {
    int i = blockIdx.x * blockDim.x + threadIdx.x;
    if (i < 81920) {                       // WN [640][128]
        int n = i >> 7, k = i & 127;
        float v;
        if (n < 256)      v = Wni[n * 128 + k];
        else if (n < 512) v = Wnj[(n - 256) * 128 + k];
        else              v = Wm[(n - 512) * 256 + k];
        split_store(v, g_WNh, g_WNl, i);
    }
    if (i < 49152) {                       // WE [384][128]
        int n = i >> 7, k = i & 127;
        float v = (n < 256) ? We[n * 128 + k] : Wm[(n - 256) * 256 + 128 + k];
        split_store(v, g_WEh, g_WEl, i);
    }
    if (i < 640) g_bN[i] = (i < 256) ? bni[i] : (i < 512 ? bnj[i - 256] : 0.f);
    if (i < 384) g_bE[i] = (i < 256) ? be[i] : bm[i - 256];
    if (i < 16384) {                       // WO [k][n]
        int k = i >> 7, n = i & 127;
        g_WO[i] = Wo[n * 128 + k];
    }
}

// ---------------- HMMA split-bf16 GEMM, register epilogue, 2 CTAs/SM ----------------
// 512 threads = 16 warps: wm = wid>>1 (16-row strip), wn = wid&1 (32-col half of 64-wide N-tile)
// mode 0: node tables, NB=10 -> g_node_tbl (+bias)
// mode 1: edge pass, NB=6; nt 0..3 -> attention (head = nt*2+wn) stores ex to smem + denom atomic;
//                    nt 4,5 -> messages scaled by ex, red.add into g_agg (fused aggregation)
__global__ void __launch_bounds__(512, 2) mma_kernel(
    int mode, const float* __restrict__ A, int M, int NB,
    const int* __restrict__ EI, const float* __restrict__ AP) {
    extern __shared__ char smem[];
    uint32_t sb = smem_u32(smem);
    float* sEX = (float*)(smem + SM_EX);
    int tid = threadIdx.x;
    int wid = tid >> 5, lid = tid & 31;
    int m0 = blockIdx.x * 128;

    const __nv_bfloat16* BhBase = (mode == 0) ? g_WNh : g_WEh;
    const __nv_bfloat16* BlBase = (mode == 0) ? g_WNl : g_WEl;

    // ---- fill A tile once: f32 -> hi/lo bf16 ----
#pragma unroll
    for (int u = tid; u < 4096; u += 512) {
        int r = u >> 5, c = (u & 31) << 2;
        int row = m0 + r;
        float4 v = make_float4(0.f, 0.f, 0.f, 0.f);
        if (row < M) v = *(const float4*)(A + (size_t)row * 128 + c);
        __nv_bfloat162 h01 = __floats2bfloat162_rn(v.x, v.y);
        __nv_bfloat162 h23 = __floats2bfloat162_rn(v.z, v.w);
        float2 f01 = __bfloat1622float2(h01);
        float2 f23 = __bfloat1622float2(h23);
        __nv_bfloat162 l01 = __floats2bfloat162_rn(v.x - f01.x, v.y - f01.y);
        __nv_bfloat162 l23 = __floats2bfloat162_rn(v.z - f23.x, v.w - f23.y);
        uint32_t off = r * APITCH_B + c * 2;
        *(uint2*)(smem + SM_AH + off) = make_uint2(*(uint32_t*)&h01, *(uint32_t*)&h23);
        *(uint2*)(smem + SM_AL + off) = make_uint2(*(uint32_t*)&l01, *(uint32_t*)&l23);
    }

    int wm = wid >> 1, wn = wid & 1;
    int lr = lid & 15, lc = lid >> 4;
    int q  = lid >> 2, lq = lid & 3;          // C-frag: rows wm*16+q, +8; cols 2*lq within 8-col frag

    // per-lane edge/node rows (fixed across tiles)
    int r0 = m0 + wm * 16 + q;
    int r1 = r0 + 8;
    int s0 = 0, d0 = 0, s1 = 0, d1 = 0;
    if (mode == 1) {
        s0 = EI[r0]; d0 = EI[N_EDGES + r0];
        s1 = EI[r1]; d1 = EI[N_EDGES + r1];
    }

    for (int nt = 0; nt < NB; nt++) {
        __syncthreads();   // previous tile's ldsm/epilogue done (A ready on first iter)
        // ---- fill B(nt): 64 rows x 128 cols hi/lo ----
        {
            const __nv_bfloat16* Bh = BhBase + (size_t)nt * 64 * 128;
            const __nv_bfloat16* Bl = BlBase + (size_t)nt * 64 * 128;
#pragma unroll
            for (int u = tid; u < 1024; u += 512) {
                int r = u >> 4, c = (u & 15) << 3;
                uint32_t off = r * APITCH_B + c * 2;
                *(uint4*)(smem + SM_BH + off) = *(const uint4*)(Bh + (size_t)r * 128 + c);
                *(uint4*)(smem + SM_BL + off) = *(const uint4*)(Bl + (size_t)r * 128 + c);
            }
        }
        __syncthreads();

        // ---- MMA over K=128: warp tile 16 rows x 32 cols ----
        float acc[4][4];
#pragma unroll
        for (int f = 0; f < 4; f++)
#pragma unroll
            for (int j = 0; j < 4; j++) acc[f][j] = 0.f;

#pragma unroll
        for (int ks = 0; ks < 8; ks++) {
            int kc = ks * 16;
            uint32_t ah[4], al[4], bhf[4][2], blf[4][2];
            uint32_t aoff = (uint32_t)((wm * 16 + lr) * APITCH_B + (kc + lc * 8) * 2);
            LDSM_X4(ah[0], ah[1], ah[2], ah[3], sb + SM_AH + aoff);
            LDSM_X4(al[0], al[1], al[2], al[3], sb + SM_AL + aoff);
#pragma unroll
            for (int g = 0; g < 2; g++) {
                uint32_t boff = (uint32_t)((wn * 32 + g * 16 + lr) * APITCH_B + (kc + lc * 8) * 2);
                uint32_t t0, t1, t2, t3;
                LDSM_X4(t0, t1, t2, t3, sb + SM_BH + boff);
                bhf[2 * g][0] = t0; bhf[2 * g][1] = t2;
                bhf[2 * g + 1][0] = t1; bhf[2 * g + 1][1] = t3;
                LDSM_X4(t0, t1, t2, t3, sb + SM_BL + boff);
                blf[2 * g][0] = t0; blf[2 * g][1] = t2;
                blf[2 * g + 1][0] = t1; blf[2 * g + 1][1] = t3;
            }
#pragma unroll
            for (int f = 0; f < 4; f++) {
                MMA_BF16(acc[f], ah, bhf[f]);
                MMA_BF16(acc[f], ah, blf[f]);
                MMA_BF16(acc[f], al, bhf[f]);
            }
        }

        // ---- register epilogue ----
        if (mode == 0) {
            int cg0 = nt * 64 + wn * 32;
#pragma unroll
            for (int f = 0; f < 4; f++) {
                int cg = cg0 + f * 8 + lq * 2;
                float2 b2 = *(const float2*)(g_bN + cg);
                if (r0 < M)
                    *(float2*)(g_node_tbl + (size_t)r0 * 640 + cg) =
                        make_float2(acc[f][0] + b2.x, acc[f][1] + b2.y);
                if (r1 < M)
                    *(float2*)(g_node_tbl + (size_t)r1 * 640 + cg) =
                        make_float2(acc[f][2] + b2.x, acc[f][3] + b2.y);
            }
        } else if (nt < 4) {
            int head = nt * 2 + wn;
            int cg0 = nt * 64 + wn * 32;          // hidden col base (0..224)
            float p0 = 0.f, p1 = 0.f;
#pragma unroll
            for (int f = 0; f < 4; f++) {
                int cl = f * 8 + lq * 2;          // col within head (0..30)
                int cg = cg0 + cl;
                float2 b2  = *(const float2*)(g_bE + cg);
                float2 ap2 = *(const float2*)(AP + head * 32 + cl);
                float2 ni0 = *(const float2*)(g_node_tbl + (size_t)s0 * 640 + cg);
                float2 nj0 = *(const float2*)(g_node_tbl + (size_t)d0 * 640 + 256 + cg);
                float2 ni1 = *(const float2*)(g_node_tbl + (size_t)s1 * 640 + cg);
                float2 nj1 = *(const float2*)(g_node_tbl + (size_t)d1 * 640 + 256 + cg);
                float h;
                h = acc[f][0] + b2.x + ni0.x + nj0.x; h = (h >= 0.f) ? h : NEG_SLOPE * h; p0 += h * ap2.x;
                h = acc[f][1] + b2.y + ni0.y + nj0.y; h = (h >= 0.f) ? h : NEG_SLOPE * h; p0 += h * ap2.y;
                h = acc[f][2] + b2.x + ni1.x + nj1.x; h = (h >= 0.f) ? h : NEG_SLOPE * h; p1 += h * ap2.x;
                h = acc[f][3] + b2.y + ni1.y + nj1.y; h = (h >= 0.f) ? h : NEG_SLOPE * h; p1 += h * ap2.y;
            }
            p0 += __shfl_xor_sync(0xffffffffu, p0, 1);
            p0 += __shfl_xor_sync(0xffffffffu, p0, 2);
            p1 += __shfl_xor_sync(0xffffffffu, p1, 1);
            p1 += __shfl_xor_sync(0xffffffffu, p1, 2);
            if (lq == 0) {
                float e0 = expf(p0), e1 = expf(p1);
                sEX[(wm * 16 + q) * 8 + head]     = e0;
                sEX[(wm * 16 + q + 8) * 8 + head] = e1;
                atomicAdd(&g_node_sum[s0 * 8 + head], e0);
                atomicAdd(&g_node_sum[s1 * 8 + head], e1);
            }
        } else {
            // fused aggregation: unnormalized ex*msg -> red.add into g_agg
            int cm0 = (nt - 4) * 64 + wn * 32;    // message col base (0..96)
#pragma unroll
            for (int f = 0; f < 4; f++) {
                int cm = cm0 + f * 8 + lq * 2;
                int head = cm >> 4;
                float ex0 = sEX[(wm * 16 + q) * 8 + head];
                float ex1 = sEX[(wm * 16 + q + 8) * 8 + head];
                float2 b2  = *(const float2*)(g_bE + 256 + cm);
                float2 nm0 = *(const float2*)(g_node_tbl + (size_t)d0 * 640 + 512 + cm);
                float2 nm1 = *(const float2*)(g_node_tbl + (size_t)d1 * 640 + 512 + cm);
                float v0x = (acc[f][0] + b2.x + nm0.x) * ex0;
                float v0y = (acc[f][1] + b2.y + nm0.y) * ex0;
                float v1x = (acc[f][2] + b2.x + nm1.x) * ex1;
                float v1y = (acc[f][3] + b2.y + nm1.y) * ex1;
                asm volatile("red.global.add.v2.f32 [%0], {%1,%2};"
                             :: "l"(g_agg + (size_t)s0 * 128 + cm), "f"(v0x), "f"(v0y) : "memory");
                asm volatile("red.global.add.v2.f32 [%0], {%1,%2};"
                             :: "l"(g_agg + (size_t)s1 * 128 + cm), "f"(v1x), "f"(v1y) : "memory");
            }
        }
    }
}

// ---------------- output GEMM with softmax normalization folded into A load ----------------
__global__ void out_gemm_kernel(const float* __restrict__ A, const float* __restrict__ B,
                                const float* __restrict__ bias, const float* __restrict__ sums,
                                float* __restrict__ C, int M) {
    __shared__ float As[16][64];
    __shared__ float Bs[16][64];
    int tid = threadIdx.x;
    int rt = tid >> 4, ct = tid & 15;
    int m0 = blockIdx.x * 64, n0 = blockIdx.y * 64;
    float acc[4][4] = {};
    int arow = tid >> 2, aq = tid & 3;
    int bk = tid >> 4, bq = tid & 15;
    for (int k0 = 0; k0 < 128; k0 += 16) {
        float4 av = make_float4(0.f, 0.f, 0.f, 0.f);
        int m = m0 + arow;
        if (m < M) {
            av = *(const float4*)(A + (size_t)m * 128 + k0 + aq * 4);
            float s = sums[m * 8 + (k0 >> 4)];
            float inv = 1.0f / s;
            av.x *= inv; av.y *= inv; av.z *= inv; av.w *= inv;
        }
        As[aq * 4 + 0][arow] = av.x; As[aq * 4 + 1][arow] = av.y;
        As[aq * 4 + 2][arow] = av.z; As[aq * 4 + 3][arow] = av.w;
        float4 bv = *(const float4*)(B + (size_t)(k0 + bk) * 128 + n0 + bq * 4);
        *(float4*)&Bs[bk][bq * 4] = bv;
        __syncthreads();
#pragma unroll
        for (int kk = 0; kk < 16; kk++) {
            float a[4], b[4];
            *(float4*)a = *(float4*)&As[kk][rt * 4];
            *(float4*)b = *(float4*)&Bs[kk][ct * 4];
#pragma unroll
            for (int i = 0; i < 4; i++)
#pragma unroll
                for (int j = 0; j < 4; j++)
                    acc[i][j] += a[i] * b[j];
        }
        __syncthreads();
    }
#pragma unroll
    for (int i = 0; i < 4; i++) {
        int m = m0 + rt * 4 + i;
        if (m < M) {
            int n = n0 + ct * 4;
            float4 o;
            o.x = acc[i][0] + bias[n + 0];
            o.y = acc[i][1] + bias[n + 1];
            o.z = acc[i][2] + bias[n + 2];
            o.w = acc[i][3] + bias[n + 3];
            *(float4*)(C + (size_t)m * 128 + n) = o;
        }
    }
}

// ---------------- launch ----------------
extern "C" void kernel_launch(void* const* d_in, const int* in_sizes, int n_in,
                              void* d_out, int out_size) {
    const float* node_features = (const float*)d_in[0];
    const float* edge_features = (const float*)d_in[1];
    const int*   edge_index    = (const int*)d_in[2];
    const float* Wni = (const float*)d_in[3];
    const float* bni = (const float*)d_in[4];
    const float* Wnj = (const float*)d_in[5];
    const float* bnj = (const float*)d_in[6];
    const float* We  = (const float*)d_in[7];
    const float* be  = (const float*)d_in[8];
    const float* attn_proj = (const float*)d_in[9];
    const float* Wm  = (const float*)d_in[10];
    const float* bm  = (const float*)d_in[11];
    const float* Wo  = (const float*)d_in[12];
    const float* bo  = (const float*)d_in[13];
    float* out = (float*)d_out;

    float *pAgg, *pWO, *pSum;
    cudaGetSymbolAddress((void**)&pAgg, g_agg);
    cudaGetSymbolAddress((void**)&pWO,  g_WO);
    cudaGetSymbolAddress((void**)&pSum, g_node_sum);

    static bool attr_set = false;
    if (!attr_set) {
        cudaFuncSetAttribute(mma_kernel, cudaFuncAttributeMaxDynamicSharedMemorySize, SM_TOT);
        attr_set = true;
    }

    const int ZTOT = N_NODES * NUM_HEADS + N_NODES * 128;
    zero_kernel<<<(ZTOT + 255) / 256, 256>>>();
    prepack_kernel<<<(81920 + 255) / 256, 256>>>(Wni, bni, Wnj, bnj, We, be, Wm, bm, Wo);

    // node tables: 157 M-tiles, 10 N-tiles of 64 looped in-kernel
    mma_kernel<<<(N_NODES + 127) / 128, 512, SM_TOT>>>(
        0, node_features, N_NODES, 10, edge_index, attn_proj);

    // edge pass (GEMM + attention + fused aggregation): 2500 M-tiles, 6 N-tiles
    mma_kernel<<<N_EDGES / 128, 512, SM_TOT>>>(
        1, edge_features, N_EDGES, 6, edge_index, attn_proj);

    // output projection with softmax normalization folded in
    out_gemm_kernel<<<dim3((N_NODES + 63) / 64, 2), 256>>>(pAgg, pWO, bo, pSum, out, N_NODES);
}

// round 10
// speedup vs baseline: 1.5863x; 1.2981x over previous
#include <cuda_runtime.h>
#include <cuda_bf16.h>
#include <cstdint>

#define N_NODES   20000
#define N_EDGES   320000
#define NUM_HEADS 8
#define NEG_SLOPE 0.2f

// ---------------- device scratch ----------------
__device__ float g_node_tbl[N_NODES * 640];   // [0:256)=ni_h, [256:512)=nj_h, [512:640)=node msg part
__device__ float g_node_sum[N_NODES * NUM_HEADS];   // softmax denominators
__device__ float g_agg[N_NODES * 128];              // UNNORMALIZED sum of ex*msg
// stage-1 prepack: bf16 hi/lo splits, [n][k] k-contiguous
__device__ __nv_bfloat16 g_WNh[640 * 128];
__device__ __nv_bfloat16 g_WNl[640 * 128];
__device__ __nv_bfloat16 g_WEh[384 * 128];
__device__ __nv_bfloat16 g_WEl[384 * 128];
// stage-2 prepack: fragment-major B for direct LDG.128 per lane
// index: (cf*8 + ks)*32 + lane  ->  {b0_hi, b1_hi, b0_lo, b1_lo}
__device__ uint4 g_WNf[80 * 8 * 32];          // 640/8 col-frags
__device__ uint4 g_WEf[48 * 8 * 32];          // 384/8 col-frags
__device__ float g_bN[640];
__device__ float g_bE[384];
__device__ float g_WO[128 * 128];             // [k][n] for FFMA out gemm

// ---------------- helpers ----------------
__device__ __forceinline__ uint32_t smem_u32(const void* p) {
    uint32_t a;
    asm("{ .reg .u64 t; cvta.to.shared.u64 t, %1; cvt.u32.u64 %0, t; }" : "=r"(a) : "l"(p));
    return a;
}

#define LDSM_X4(r0, r1, r2, r3, addr) \
    asm volatile("ldmatrix.sync.aligned.m8n8.x4.shared.b16 {%0,%1,%2,%3}, [%4];" \
                 : "=r"(r0), "=r"(r1), "=r"(r2), "=r"(r3) : "r"(addr))

#define MMA_BF16(c, a, b0, b1) \
    asm volatile("mma.sync.aligned.m16n8k16.row.col.f32.bf16.bf16.f32 " \
                 "{%0,%1,%2,%3}, {%4,%5,%6,%7}, {%8,%9}, {%0,%1,%2,%3};" \
                 : "+f"((c)[0]), "+f"((c)[1]), "+f"((c)[2]), "+f"((c)[3]) \
                 : "r"((a)[0]), "r"((a)[1]), "r"((a)[2]), "r"((a)[3]), \
                   "r"(b0), "r"(b1))

// smem layout (bytes): A hi/lo 128x128 bf16 (pitch 272 B) + sEX
#define APITCH_B 272
#define SM_AH 0
#define SM_AL 34816
#define SM_EX 69632       // float sEX[128][8] = 4096 B
#define SM_TOT 73728      // 72 KB -> 2 CTAs/SM

// ---------------- init kernels ----------------
__global__ void zero_kernel() {
    int i = blockIdx.x * blockDim.x + threadIdx.x;
    const int NS = N_NODES * NUM_HEADS;
    const int TOT = NS + N_NODES * 128;
    if (i < NS) g_node_sum[i] = 0.f;
    else if (i < TOT) g_agg[i - NS] = 0.f;
}

__device__ __forceinline__ void split_store(float v, __nv_bfloat16* hi, __nv_bfloat16* lo, int i) {
    __nv_bfloat16 h = __float2bfloat16(v);
    hi[i] = h;
    lo[i] = __float2bfloat16(v - __bfloat162float(h));
}

__global__ void prepack_kernel(const float* __restrict__ Wni, const float* __restrict__ bni,
                               const float* __restrict__ Wnj, const float* __restrict__ bnj,
                               const float* __restrict__ We,  const float* __restrict__ be,
                               const float* __restrict__ Wm,  const float* __restrict__ bm,
                               const float* __restrict__ Wo) {
    int i = blockIdx.x * blockDim.x + threadIdx.x;
    if (i < 81920) {                       // WN [640][128]
        int n = i >> 7, k = i & 127;
        float v;
        if (n < 256)      v = Wni[n * 128 + k];
        else if (n < 512) v = Wnj[(n - 256) * 128 + k];
        else              v = Wm[(n - 512) * 256 + k];
        split_store(v, g_WNh, g_WNl, i);
    }
    if (i < 49152) {                       // WE [384][128]
        int n = i >> 7, k = i & 127;
        float v = (n < 256) ? We[n * 128 + k] : Wm[(n - 256) * 256 + 128 + k];
        split_store(v, g_WEh, g_WEl, i);
    }
    if (i < 640) g_bN[i] = (i < 256) ? bni[i] : (i < 512 ? bnj[i - 256] : 0.f);
    if (i < 384) g_bE[i] = (i < 256) ? be[i] : bm[i - 256];
    if (i < 16384) {                       // WO [k][n]
        int k = i >> 7, n = i & 127;
        g_WO[i] = Wo[n * 128 + k];
    }
}

// stage 2: repack [n][k] bf16 hi/lo into fragment-major uint4
__global__ void prepack2_kernel() {
    int i = blockIdx.x * blockDim.x + threadIdx.x;
    int lane = i & 31;
    int ks   = (i >> 5) & 7;
    int cf   = i >> 8;
    int n  = (cf << 3) + (lane >> 2);
    int k0 = (ks << 4) + ((lane & 3) << 1);
    if (i < 80 * 8 * 32) {
        uint32_t b0h = *(const uint32_t*)(g_WNh + n * 128 + k0);
        uint32_t b1h = *(const uint32_t*)(g_WNh + n * 128 + k0 + 8);
        uint32_t b0l = *(const uint32_t*)(g_WNl + n * 128 + k0);
        uint32_t b1l = *(const uint32_t*)(g_WNl + n * 128 + k0 + 8);
        g_WNf[i] = make_uint4(b0h, b1h, b0l, b1l);
    }
    if (i < 48 * 8 * 32) {
        uint32_t b0h = *(const uint32_t*)(g_WEh + n * 128 + k0);
        uint32_t b1h = *(const uint32_t*)(g_WEh + n * 128 + k0 + 8);
        uint32_t b0l = *(const uint32_t*)(g_WEl + n * 128 + k0);
        uint32_t b1l = *(const uint32_t*)(g_WEl + n * 128 + k0 + 8);
        g_WEf[i] = make_uint4(b0h, b1h, b0l, b1l);
    }
}

// ---------------- HMMA split-bf16 GEMM, sync-free mainloop, 2 CTAs/SM ----------------
// 512 threads = 16 warps: wm = wid>>1 (16-row strip), wn = wid&1 (32-col half of 64-wide N-tile)
// B fragments loaded directly from fragment-major global (L1-hot), A from smem via ldmatrix.
// mode 0: node tables, NB=10 -> g_node_tbl (+bias); no syncs after A fill.
// mode 1: edge pass, NB=6; nt 0..3 -> attention (head = nt*2+wn) -> sEX + denom atomic;
//         one __syncthreads after nt=3; nt 4,5 -> messages scaled by ex -> red.add g_agg
__global__ void __launch_bounds__(512, 2) mma_kernel(
    int mode, const float* __restrict__ A, int M, int NB,
    const int* __restrict__ EI, const float* __restrict__ AP) {
    extern __shared__ char smem[];
    uint32_t sb = smem_u32(smem);
    float* sEX = (float*)(smem + SM_EX);
    int tid = threadIdx.x;
    int wid = tid >> 5, lid = tid & 31;
    int m0 = blockIdx.x * 128;

    const uint4* Bf = (mode == 0) ? g_WNf : g_WEf;

    // ---- fill A tile once: f32 -> hi/lo bf16 ----
#pragma unroll
    for (int u = tid; u < 4096; u += 512) {
        int r = u >> 5, c = (u & 31) << 2;
        int row = m0 + r;
        float4 v = make_float4(0.f, 0.f, 0.f, 0.f);
        if (row < M) v = *(const float4*)(A + (size_t)row * 128 + c);
        __nv_bfloat162 h01 = __floats2bfloat162_rn(v.x, v.y);
        __nv_bfloat162 h23 = __floats2bfloat162_rn(v.z, v.w);
        float2 f01 = __bfloat1622float2(h01);
        float2 f23 = __bfloat1622float2(h23);
        __nv_bfloat162 l01 = __floats2bfloat162_rn(v.x - f01.x, v.y - f01.y);
        __nv_bfloat162 l23 = __floats2bfloat162_rn(v.z - f23.x, v.w - f23.y);
        uint32_t off = r * APITCH_B + c * 2;
        *(uint2*)(smem + SM_AH + off) = make_uint2(*(uint32_t*)&h01, *(uint32_t*)&h23);
        *(uint2*)(smem + SM_AL + off) = make_uint2(*(uint32_t*)&l01, *(uint32_t*)&l23);
    }
    __syncthreads();   // the only barrier needed for the GEMM mainloop

    int wm = wid >> 1, wn = wid & 1;
    int lr = lid & 15, lc = lid >> 4;
    int q  = lid >> 2, lq = lid & 3;

    // per-lane edge rows (fixed across tiles)
    int r0 = m0 + wm * 16 + q;
    int r1 = r0 + 8;
    int s0 = 0, d0 = 0, s1 = 0, d1 = 0;
    if (mode == 1) {
        s0 = EI[r0]; d0 = EI[N_EDGES + r0];
        s1 = EI[r1]; d1 = EI[N_EDGES + r1];
    }

    for (int nt = 0; nt < NB; nt++) {
        // ---- MMA over K=128: warp tile 16 rows x 32 cols; B frags via LDG ----
        float acc[4][4];
#pragma unroll
        for (int f = 0; f < 4; f++)
#pragma unroll
            for (int j = 0; j < 4; j++) acc[f][j] = 0.f;

        const uint4* bp = Bf + (size_t)(nt * 8 + wn * 4) * 256 + lid;
#pragma unroll
        for (int ks = 0; ks < 8; ks++) {
            uint32_t ah[4], al[4];
            uint32_t aoff = (uint32_t)((wm * 16 + lr) * APITCH_B + (ks * 16 + lc * 8) * 2);
            LDSM_X4(ah[0], ah[1], ah[2], ah[3], sb + SM_AH + aoff);
            LDSM_X4(al[0], al[1], al[2], al[3], sb + SM_AL + aoff);
            uint4 bv0 = bp[0 * 256 + ks * 32];
            uint4 bv1 = bp[1 * 256 + ks * 32];
            uint4 bv2 = bp[2 * 256 + ks * 32];
            uint4 bv3 = bp[3 * 256 + ks * 32];
            MMA_BF16(acc[0], ah, bv0.x, bv0.y);
            MMA_BF16(acc[0], ah, bv0.z, bv0.w);
            MMA_BF16(acc[0], al, bv0.x, bv0.y);
            MMA_BF16(acc[1], ah, bv1.x, bv1.y);
            MMA_BF16(acc[1], ah, bv1.z, bv1.w);
            MMA_BF16(acc[1], al, bv1.x, bv1.y);
            MMA_BF16(acc[2], ah, bv2.x, bv2.y);
            MMA_BF16(acc[2], ah, bv2.z, bv2.w);
            MMA_BF16(acc[2], al, bv2.x, bv2.y);
            MMA_BF16(acc[3], ah, bv3.x, bv3.y);
            MMA_BF16(acc[3], ah, bv3.z, bv3.w);
            MMA_BF16(acc[3], al, bv3.x, bv3.y);
        }

        // ---- register epilogue ----
        if (mode == 0) {
            int cg0 = nt * 64 + wn * 32;
#pragma unroll
            for (int f = 0; f < 4; f++) {
                int cg = cg0 + f * 8 + lq * 2;
                float2 b2 = *(const float2*)(g_bN + cg);
                if (r0 < M)
                    *(float2*)(g_node_tbl + (size_t)r0 * 640 + cg) =
                        make_float2(acc[f][0] + b2.x, acc[f][1] + b2.y);
                if (r1 < M)
                    *(float2*)(g_node_tbl + (size_t)r1 * 640 + cg) =
                        make_float2(acc[f][2] + b2.x, acc[f][3] + b2.y);
            }
        } else if (nt < 4) {
            int head = nt * 2 + wn;
            int cg0 = nt * 64 + wn * 32;          // hidden col base (0..224)
            float p0 = 0.f, p1 = 0.f;
#pragma unroll
            for (int f = 0; f < 4; f++) {
                int cl = f * 8 + lq * 2;          // col within head (0..30)
                int cg = cg0 + cl;
                float2 b2  = *(const float2*)(g_bE + cg);
                float2 ap2 = *(const float2*)(AP + head * 32 + cl);
                float2 ni0 = *(const float2*)(g_node_tbl + (size_t)s0 * 640 + cg);
                float2 nj0 = *(const float2*)(g_node_tbl + (size_t)d0 * 640 + 256 + cg);
                float2 ni1 = *(const float2*)(g_node_tbl + (size_t)s1 * 640 + cg);
                float2 nj1 = *(const float2*)(g_node_tbl + (size_t)d1 * 640 + 256 + cg);
                float h;
                h = acc[f][0] + b2.x + ni0.x + nj0.x; h = (h >= 0.f) ? h : NEG_SLOPE * h; p0 += h * ap2.x;
                h = acc[f][1] + b2.y + ni0.y + nj0.y; h = (h >= 0.f) ? h : NEG_SLOPE * h; p0 += h * ap2.y;
                h = acc[f][2] + b2.x + ni1.x + nj1.x; h = (h >= 0.f) ? h : NEG_SLOPE * h; p1 += h * ap2.x;
                h = acc[f][3] + b2.y + ni1.y + nj1.y; h = (h >= 0.f) ? h : NEG_SLOPE * h; p1 += h * ap2.y;
            }
            p0 += __shfl_xor_sync(0xffffffffu, p0, 1);
            p0 += __shfl_xor_sync(0xffffffffu, p0, 2);
            p1 += __shfl_xor_sync(0xffffffffu, p1, 1);
            p1 += __shfl_xor_sync(0xffffffffu, p1, 2);
            if (lq == 0) {
                float e0 = expf(p0), e1 = expf(p1);
                sEX[(wm * 16 + q) * 8 + head]     = e0;
                sEX[(wm * 16 + q + 8) * 8 + head] = e1;
                atomicAdd(&g_node_sum[s0 * 8 + head], e0);
                atomicAdd(&g_node_sum[s1 * 8 + head], e1);
            }
            if (nt == 3) __syncthreads();   // publish sEX across warps before message phase
        } else {
            // fused aggregation: unnormalized ex*msg -> red.add into g_agg
            int cm0 = (nt - 4) * 64 + wn * 32;    // message col base (0..96)
#pragma unroll
            for (int f = 0; f < 4; f++) {
                int cm = cm0 + f * 8 + lq * 2;
                int head = cm >> 4;
                float ex0 = sEX[(wm * 16 + q) * 8 + head];
                float ex1 = sEX[(wm * 16 + q + 8) * 8 + head];
                float2 b2  = *(const float2*)(g_bE + 256 + cm);
                float2 nm0 = *(const float2*)(g_node_tbl + (size_t)d0 * 640 + 512 + cm);
                float2 nm1 = *(const float2*)(g_node_tbl + (size_t)d1 * 640 + 512 + cm);
                float v0x = (acc[f][0] + b2.x + nm0.x) * ex0;
                float v0y = (acc[f][1] + b2.y + nm0.y) * ex0;
                float v1x = (acc[f][2] + b2.x + nm1.x) * ex1;
                float v1y = (acc[f][3] + b2.y + nm1.y) * ex1;
                asm volatile("red.global.add.v2.f32 [%0], {%1,%2};"
                             :: "l"(g_agg + (size_t)s0 * 128 + cm), "f"(v0x), "f"(v0y) : "memory");
                asm volatile("red.global.add.v2.f32 [%0], {%1,%2};"
                             :: "l"(g_agg + (size_t)s1 * 128 + cm), "f"(v1x), "f"(v1y) : "memory");
            }
        }
    }
}

// ---------------- output GEMM with softmax normalization folded into A load ----------------
__global__ void out_gemm_kernel(const float* __restrict__ A, const float* __restrict__ B,
                                const float* __restrict__ bias, const float* __restrict__ sums,
                                float* __restrict__ C, int M) {
    __shared__ float As[16][64];
    __shared__ float Bs[16][64];
    int tid = threadIdx.x;
    int rt = tid >> 4, ct = tid & 15;
    int m0 = blockIdx.x * 64, n0 = blockIdx.y * 64;
    float acc[4][4] = {};
    int arow = tid >> 2, aq = tid & 3;
    int bk = tid >> 4, bq = tid & 15;
    for (int k0 = 0; k0 < 128; k0 += 16) {
        float4 av = make_float4(0.f, 0.f, 0.f, 0.f);
        int m = m0 + arow;
        if (m < M) {
            av = *(const float4*)(A + (size_t)m * 128 + k0 + aq * 4);
            float s = sums[m * 8 + (k0 >> 4)];
            float inv = 1.0f / s;
            av.x *= inv; av.y *= inv; av.z *= inv; av.w *= inv;
        }
        As[aq * 4 + 0][arow] = av.x; As[aq * 4 + 1][arow] = av.y;
        As[aq * 4 + 2][arow] = av.z; As[aq * 4 + 3][arow] = av.w;
        float4 bv = *(const float4*)(B + (size_t)(k0 + bk) * 128 + n0 + bq * 4);
        *(float4*)&Bs[bk][bq * 4] = bv;
        __syncthreads();
#pragma unroll
        for (int kk = 0; kk < 16; kk++) {
            float a[4], b[4];
            *(float4*)a = *(float4*)&As[kk][rt * 4];
            *(float4*)b = *(float4*)&Bs[kk][ct * 4];
#pragma unroll
            for (int i = 0; i < 4; i++)
#pragma unroll
                for (int j = 0; j < 4; j++)
                    acc[i][j] += a[i] * b[j];
        }
        __syncthreads();
    }
#pragma unroll
    for (int i = 0; i < 4; i++) {
        int m = m0 + rt * 4 + i;
        if (m < M) {
            int n = n0 + ct * 4;
            float4 o;
            o.x = acc[i][0] + bias[n + 0];
            o.y = acc[i][1] + bias[n + 1];
            o.z = acc[i][2] + bias[n + 2];
            o.w = acc[i][3] + bias[n + 3];
            *(float4*)(C + (size_t)m * 128 + n) = o;
        }
    }
}

// ---------------- launch ----------------
extern "C" void kernel_launch(void* const* d_in, const int* in_sizes, int n_in,
                              void* d_out, int out_size) {
    const float* node_features = (const float*)d_in[0];
    const float* edge_features = (const float*)d_in[1];
    const int*   edge_index    = (const int*)d_in[2];
    const float* Wni = (const float*)d_in[3];
    const float* bni = (const float*)d_in[4];
    const float* Wnj = (const float*)d_in[5];
    const float* bnj = (const float*)d_in[6];
    const float* We  = (const float*)d_in[7];
    const float* be  = (const float*)d_in[8];
    const float* attn_proj = (const float*)d_in[9];
    const float* Wm  = (const float*)d_in[10];
    const float* bm  = (const float*)d_in[11];
    const float* Wo  = (const float*)d_in[12];
    const float* bo  = (const float*)d_in[13];
    float* out = (float*)d_out;

    float *pAgg, *pWO, *pSum;
    cudaGetSymbolAddress((void**)&pAgg, g_agg);
    cudaGetSymbolAddress((void**)&pWO,  g_WO);
    cudaGetSymbolAddress((void**)&pSum, g_node_sum);

    static bool attr_set = false;
    if (!attr_set) {
        cudaFuncSetAttribute(mma_kernel, cudaFuncAttributeMaxDynamicSharedMemorySize, SM_TOT);
        attr_set = true;
    }

    const int ZTOT = N_NODES * NUM_HEADS + N_NODES * 128;
    zero_kernel<<<(ZTOT + 255) / 256, 256>>>();
    prepack_kernel<<<(81920 + 255) / 256, 256>>>(Wni, bni, Wnj, bnj, We, be, Wm, bm, Wo);
    prepack2_kernel<<<(80 * 8 * 32 + 255) / 256, 256>>>();

    // node tables: 157 M-tiles, 10 N-tiles of 64 looped in-kernel (sync-free)
    mma_kernel<<<(N_NODES + 127) / 128, 512, SM_TOT>>>(
        0, node_features, N_NODES, 10, edge_index, attn_proj);

    // edge pass (GEMM + attention + fused aggregation): 2500 M-tiles, 6 N-tiles
    mma_kernel<<<N_EDGES / 128, 512, SM_TOT>>>(
        1, edge_features, N_EDGES, 6, edge_index, attn_proj);

    // output projection with softmax normalization folded in
    out_gemm_kernel<<<dim3((N_NODES + 63) / 64, 2), 256>>>(pAgg, pWO, bo, pSum, out, N_NODES);
}

// round 11
// speedup vs baseline: 1.7857x; 1.1257x over previous
#include <cuda_runtime.h>
#include <cuda_bf16.h>
#include <cstdint>

#define N_NODES   20000
#define N_EDGES   320000
#define NUM_HEADS 8
#define NEG_SLOPE 0.2f

// ---------------- device scratch ----------------
__device__ float g_node_tbl[N_NODES * 640];   // [0:256)=ni_h, [256:512)=nj_h, [512:640)=node msg part
__device__ float g_node_sum[N_NODES * NUM_HEADS];   // softmax denominators
__device__ float g_agg[N_NODES * 128];              // UNNORMALIZED sum of ex*msg
// stage-1 prepack: bf16 hi/lo splits, [n][k] k-contiguous
__device__ __nv_bfloat16 g_WNh[640 * 128];
__device__ __nv_bfloat16 g_WNl[640 * 128];
__device__ __nv_bfloat16 g_WEh[384 * 128];
__device__ __nv_bfloat16 g_WEl[384 * 128];
// stage-2 prepack: fragment-major B for direct LDG.128 per lane
// index: (cf*8 + ks)*32 + lane  ->  {b0_hi, b1_hi, b0_lo, b1_lo}
__device__ uint4 g_WNf[80 * 8 * 32];          // 640/8 col-frags
__device__ uint4 g_WEf[48 * 8 * 32];          // 384/8 col-frags
__device__ float g_bN[640];
__device__ float g_bE[384];
__device__ float g_WO[128 * 128];             // [k][n] for FFMA out gemm

// ---------------- helpers ----------------
__device__ __forceinline__ uint32_t smem_u32(const void* p) {
    uint32_t a;
    asm("{ .reg .u64 t; cvta.to.shared.u64 t, %1; cvt.u32.u64 %0, t; }" : "=r"(a) : "l"(p));
    return a;
}

#define LDSM_X4(r0, r1, r2, r3, addr) \
    asm volatile("ldmatrix.sync.aligned.m8n8.x4.shared.b16 {%0,%1,%2,%3}, [%4];" \
                 : "=r"(r0), "=r"(r1), "=r"(r2), "=r"(r3) : "r"(addr))

#define MMA_BF16(c, a, b0, b1) \
    asm volatile("mma.sync.aligned.m16n8k16.row.col.f32.bf16.bf16.f32 " \
                 "{%0,%1,%2,%3}, {%4,%5,%6,%7}, {%8,%9}, {%0,%1,%2,%3};" \
                 : "+f"((c)[0]), "+f"((c)[1]), "+f"((c)[2]), "+f"((c)[3]) \
                 : "r"((a)[0]), "r"((a)[1]), "r"((a)[2]), "r"((a)[3]), \
                   "r"(b0), "r"(b1))

// 4x4 quad transpose of float2 elements via 2-stage shfl butterfly.
// In: e[f] = this lane's (col f*8 + lq*2, +1) values. Out: e[s] = cols (lq*8 + s*2, +1).
__device__ __forceinline__ void quad_transpose(float2 e[4], int lid) {
    {   // stage A: xor 2
        bool hi = (lid & 2);
        float2 s0 = hi ? e[0] : e[2];
        float2 s1 = hi ? e[1] : e[3];
        s0.x = __shfl_xor_sync(0xffffffffu, s0.x, 2);
        s0.y = __shfl_xor_sync(0xffffffffu, s0.y, 2);
        s1.x = __shfl_xor_sync(0xffffffffu, s1.x, 2);
        s1.y = __shfl_xor_sync(0xffffffffu, s1.y, 2);
        if (hi) { e[0] = s0; e[1] = s1; } else { e[2] = s0; e[3] = s1; }
    }
    {   // stage B: xor 1
        bool od = (lid & 1);
        float2 s0 = od ? e[0] : e[1];
        float2 s1 = od ? e[2] : e[3];
        s0.x = __shfl_xor_sync(0xffffffffu, s0.x, 1);
        s0.y = __shfl_xor_sync(0xffffffffu, s0.y, 1);
        s1.x = __shfl_xor_sync(0xffffffffu, s1.x, 1);
        s1.y = __shfl_xor_sync(0xffffffffu, s1.y, 1);
        if (od) { e[0] = s0; e[2] = s1; } else { e[1] = s0; e[3] = s1; }
    }
}

// smem layout (bytes): A hi/lo 128x128 bf16 (pitch 272 B) + sEX
#define APITCH_B 272
#define SM_AH 0
#define SM_AL 34816
#define SM_EX 69632       // float sEX[128][8] = 4096 B
#define SM_TOT 73728      // 72 KB -> 2 CTAs/SM

// ---------------- init kernels ----------------
__global__ void zero_kernel() {
    int i = blockIdx.x * blockDim.x + threadIdx.x;
    const int NS = N_NODES * NUM_HEADS;
    const int TOT = NS + N_NODES * 128;
    if (i < NS) g_node_sum[i] = 0.f;
    else if (i < TOT) g_agg[i - NS] = 0.f;
}

__device__ __forceinline__ void split_store(float v, __nv_bfloat16* hi, __nv_bfloat16* lo, int i) {
    __nv_bfloat16 h = __float2bfloat16(v);
    hi[i] = h;
    lo[i] = __float2bfloat16(v - __bfloat162float(h));
}

__global__ void prepack_kernel(const float* __restrict__ Wni, const float* __restrict__ bni,
                               const float* __restrict__ Wnj, const float* __restrict__ bnj,
                               const float* __restrict__ We,  const float* __restrict__ be,
                               const float* __restrict__ Wm,  const float* __restrict__ bm,
                               const float* __restrict__ Wo) {
    int i = blockIdx.x * blockDim.x + threadIdx.x;
    if (i < 81920) {                       // WN [640][128]
        int n = i >> 7, k = i & 127;
        float v;
        if (n < 256)      v = Wni[n * 128 + k];
        else if (n < 512) v = Wnj[(n - 256) * 128 + k];
        else              v = Wm[(n - 512) * 256 + k];
        split_store(v, g_WNh, g_WNl, i);
    }
    if (i < 49152) {                       // WE [384][128]
        int n = i >> 7, k = i & 127;
        float v = (n < 256) ? We[n * 128 + k] : Wm[(n - 256) * 256 + 128 + k];
        split_store(v, g_WEh, g_WEl, i);
    }
    if (i < 640) g_bN[i] = (i < 256) ? bni[i] : (i < 512 ? bnj[i - 256] : 0.f);
    if (i < 384) g_bE[i] = (i < 256) ? be[i] : bm[i - 256];
    if (i < 16384) {                       // WO [k][n]
        int k = i >> 7, n = i & 127;
        g_WO[i] = Wo[n * 128 + k];
    }
}

// stage 2: repack [n][k] bf16 hi/lo into fragment-major uint4
__global__ void prepack2_kernel() {
    int i = blockIdx.x * blockDim.x + threadIdx.x;
    int lane = i & 31;
    int ks   = (i >> 5) & 7;
    int cf   = i >> 8;
    int n  = (cf << 3) + (lane >> 2);
    int k0 = (ks << 4) + ((lane & 3) << 1);
    if (i < 80 * 8 * 32) {
        uint32_t b0h = *(const uint32_t*)(g_WNh + n * 128 + k0);
        uint32_t b1h = *(const uint32_t*)(g_WNh + n * 128 + k0 + 8);
        uint32_t b0l = *(const uint32_t*)(g_WNl + n * 128 + k0);
        uint32_t b1l = *(const uint32_t*)(g_WNl + n * 128 + k0 + 8);
        g_WNf[i] = make_uint4(b0h, b1h, b0l, b1l);
    }
    if (i < 48 * 8 * 32) {
        uint32_t b0h = *(const uint32_t*)(g_WEh + n * 128 + k0);
        uint32_t b1h = *(const uint32_t*)(g_WEh + n * 128 + k0 + 8);
        uint32_t b0l = *(const uint32_t*)(g_WEl + n * 128 + k0);
        uint32_t b1l = *(const uint32_t*)(g_WEl + n * 128 + k0 + 8);
        g_WEf[i] = make_uint4(b0h, b1h, b0l, b1l);
    }
}

// ---------------- HMMA split-bf16 GEMM, sync-free mainloop, 2 CTAs/SM ----------------
// 512 threads = 16 warps: wm = wid>>1 (16-row strip), wn = wid&1 (32-col half of 64-wide N-tile)
// mode 0: node tables, grid.y=2, 5 N-tiles each -> g_node_tbl (+bias)
// mode 1: edge pass, NB=6; nt 0..3 -> attention (head = nt*2+wn) -> sEX + denom atomic;
//         one __syncthreads after nt=3; nt 4,5 -> messages scaled by ex -> red.add.v4 g_agg
__global__ void __launch_bounds__(512, 2) mma_kernel(
    int mode, const float* __restrict__ A, int M, int NB,
    const int* __restrict__ EI, const float* __restrict__ AP) {
    extern __shared__ char smem[];
    uint32_t sb = smem_u32(smem);
    float* sEX = (float*)(smem + SM_EX);
    int tid = threadIdx.x;
    int wid = tid >> 5, lid = tid & 31;
    int m0 = blockIdx.x * 128;
    int nt0 = blockIdx.y * NB;

    const uint4* Bf = (mode == 0) ? g_WNf : g_WEf;

    // ---- fill A tile once: f32 -> hi/lo bf16 ----
#pragma unroll
    for (int u = tid; u < 4096; u += 512) {
        int r = u >> 5, c = (u & 31) << 2;
        int row = m0 + r;
        float4 v = make_float4(0.f, 0.f, 0.f, 0.f);
        if (row < M) v = *(const float4*)(A + (size_t)row * 128 + c);
        __nv_bfloat162 h01 = __floats2bfloat162_rn(v.x, v.y);
        __nv_bfloat162 h23 = __floats2bfloat162_rn(v.z, v.w);
        float2 f01 = __bfloat1622float2(h01);
        float2 f23 = __bfloat1622float2(h23);
        __nv_bfloat162 l01 = __floats2bfloat162_rn(v.x - f01.x, v.y - f01.y);
        __nv_bfloat162 l23 = __floats2bfloat162_rn(v.z - f23.x, v.w - f23.y);
        uint32_t off = r * APITCH_B + c * 2;
        *(uint2*)(smem + SM_AH + off) = make_uint2(*(uint32_t*)&h01, *(uint32_t*)&h23);
        *(uint2*)(smem + SM_AL + off) = make_uint2(*(uint32_t*)&l01, *(uint32_t*)&l23);
    }
    __syncthreads();   // the only barrier needed for the GEMM mainloop

    int wm = wid >> 1, wn = wid & 1;
    int lr = lid & 15, lc = lid >> 4;
    int q  = lid >> 2, lq = lid & 3;

    // per-lane edge rows (fixed across tiles)
    int r0 = m0 + wm * 16 + q;
    int r1 = r0 + 8;
    int s0 = 0, d0 = 0, s1 = 0, d1 = 0;
    if (mode == 1) {
        s0 = EI[r0]; d0 = EI[N_EDGES + r0];
        s1 = EI[r1]; d1 = EI[N_EDGES + r1];
    }

    for (int ntl = 0; ntl < NB; ntl++) {
        int nt = nt0 + ntl;
        // ---- MMA over K=128: warp tile 16 rows x 32 cols; B frags via LDG ----
        float acc[4][4];
#pragma unroll
        for (int f = 0; f < 4; f++)
#pragma unroll
            for (int j = 0; j < 4; j++) acc[f][j] = 0.f;

        const uint4* bp = Bf + (size_t)(nt * 8 + wn * 4) * 256 + lid;
#pragma unroll
        for (int ks = 0; ks < 8; ks++) {
            uint32_t ah[4], al[4];
            uint32_t aoff = (uint32_t)((wm * 16 + lr) * APITCH_B + (ks * 16 + lc * 8) * 2);
            LDSM_X4(ah[0], ah[1], ah[2], ah[3], sb + SM_AH + aoff);
            LDSM_X4(al[0], al[1], al[2], al[3], sb + SM_AL + aoff);
            uint4 bv0 = bp[0 * 256 + ks * 32];
            uint4 bv1 = bp[1 * 256 + ks * 32];
            uint4 bv2 = bp[2 * 256 + ks * 32];
            uint4 bv3 = bp[3 * 256 + ks * 32];
            MMA_BF16(acc[0], ah, bv0.x, bv0.y);
            MMA_BF16(acc[0], ah, bv0.z, bv0.w);
            MMA_BF16(acc[0], al, bv0.x, bv0.y);
            MMA_BF16(acc[1], ah, bv1.x, bv1.y);
            MMA_BF16(acc[1], ah, bv1.z, bv1.w);
            MMA_BF16(acc[1], al, bv1.x, bv1.y);
            MMA_BF16(acc[2], ah, bv2.x, bv2.y);
            MMA_BF16(acc[2], ah, bv2.z, bv2.w);
            MMA_BF16(acc[2], al, bv2.x, bv2.y);
            MMA_BF16(acc[3], ah, bv3.x, bv3.y);
            MMA_BF16(acc[3], ah, bv3.z, bv3.w);
            MMA_BF16(acc[3], al, bv3.x, bv3.y);
        }

        // ---- register epilogue (quad-transposed: lane owns 8 contiguous cols) ----
        int cg = nt * 64 + wn * 32 + lq * 8;   // this lane's global col base
        if (mode == 0) {
            float4 b0 = *(const float4*)(g_bN + cg);
            float4 b1 = *(const float4*)(g_bN + cg + 4);
            float2 e[4];
            e[0] = make_float2(acc[0][0], acc[0][1]);
            e[1] = make_float2(acc[1][0], acc[1][1]);
            e[2] = make_float2(acc[2][0], acc[2][1]);
            e[3] = make_float2(acc[3][0], acc[3][1]);
            quad_transpose(e, lid);
            if (r0 < M) {
                float* dst = g_node_tbl + (size_t)r0 * 640 + cg;
                *(float4*)dst       = make_float4(e[0].x + b0.x, e[0].y + b0.y, e[1].x + b0.z, e[1].y + b0.w);
                *(float4*)(dst + 4) = make_float4(e[2].x + b1.x, e[2].y + b1.y, e[3].x + b1.z, e[3].y + b1.w);
            }
            e[0] = make_float2(acc[0][2], acc[0][3]);
            e[1] = make_float2(acc[1][2], acc[1][3]);
            e[2] = make_float2(acc[2][2], acc[2][3]);
            e[3] = make_float2(acc[3][2], acc[3][3]);
            quad_transpose(e, lid);
            if (r1 < M) {
                float* dst = g_node_tbl + (size_t)r1 * 640 + cg;
                *(float4*)dst       = make_float4(e[0].x + b0.x, e[0].y + b0.y, e[1].x + b0.z, e[1].y + b0.w);
                *(float4*)(dst + 4) = make_float4(e[2].x + b1.x, e[2].y + b1.y, e[3].x + b1.z, e[3].y + b1.w);
            }
        } else if (nt < 4) {
            int head = nt * 2 + wn;
            float4 b0  = *(const float4*)(g_bE + cg);
            float4 b1  = *(const float4*)(g_bE + cg + 4);
            float4 ap0 = *(const float4*)(AP + head * 32 + lq * 8);
            float4 ap1 = *(const float4*)(AP + head * 32 + lq * 8 + 4);
            float p0, p1;
            {
                float2 e[4];
                e[0] = make_float2(acc[0][0], acc[0][1]);
                e[1] = make_float2(acc[1][0], acc[1][1]);
                e[2] = make_float2(acc[2][0], acc[2][1]);
                e[3] = make_float2(acc[3][0], acc[3][1]);
                quad_transpose(e, lid);
                const float* ni = g_node_tbl + (size_t)s0 * 640 + cg;
                const float* nj = g_node_tbl + (size_t)d0 * 640 + 256 + cg;
                float4 i0 = *(const float4*)ni, i1 = *(const float4*)(ni + 4);
                float4 j0 = *(const float4*)nj, j1 = *(const float4*)(nj + 4);
                float h; p0 = 0.f;
                h = e[0].x + b0.x + i0.x + j0.x; h = (h >= 0.f) ? h : NEG_SLOPE * h; p0 += h * ap0.x;
                h = e[0].y + b0.y + i0.y + j0.y; h = (h >= 0.f) ? h : NEG_SLOPE * h; p0 += h * ap0.y;
                h = e[1].x + b0.z + i0.z + j0.z; h = (h >= 0.f) ? h : NEG_SLOPE * h; p0 += h * ap0.z;
                h = e[1].y + b0.w + i0.w + j0.w; h = (h >= 0.f) ? h : NEG_SLOPE * h; p0 += h * ap0.w;
                h = e[2].x + b1.x + i1.x + j1.x; h = (h >= 0.f) ? h : NEG_SLOPE * h; p0 += h * ap1.x;
                h = e[2].y + b1.y + i1.y + j1.y; h = (h >= 0.f) ? h : NEG_SLOPE * h; p0 += h * ap1.y;
                h = e[3].x + b1.z + i1.z + j1.z; h = (h >= 0.f) ? h : NEG_SLOPE * h; p0 += h * ap1.z;
                h = e[3].y + b1.w + i1.w + j1.w; h = (h >= 0.f) ? h : NEG_SLOPE * h; p0 += h * ap1.w;
            }
            {
                float2 e[4];
                e[0] = make_float2(acc[0][2], acc[0][3]);
                e[1] = make_float2(acc[1][2], acc[1][3]);
                e[2] = make_float2(acc[2][2], acc[2][3]);
                e[3] = make_float2(acc[3][2], acc[3][3]);
                quad_transpose(e, lid);
                const float* ni = g_node_tbl + (size_t)s1 * 640 + cg;
                const float* nj = g_node_tbl + (size_t)d1 * 640 + 256 + cg;
                float4 i0 = *(const float4*)ni, i1 = *(const float4*)(ni + 4);
                float4 j0 = *(const float4*)nj, j1 = *(const float4*)(nj + 4);
                float h; p1 = 0.f;
                h = e[0].x + b0.x + i0.x + j0.x; h = (h >= 0.f) ? h : NEG_SLOPE * h; p1 += h * ap0.x;
                h = e[0].y + b0.y + i0.y + j0.y; h = (h >= 0.f) ? h : NEG_SLOPE * h; p1 += h * ap0.y;
                h = e[1].x + b0.z + i0.z + j0.z; h = (h >= 0.f) ? h : NEG_SLOPE * h; p1 += h * ap0.z;
                h = e[1].y + b0.w + i0.w + j0.w; h = (h >= 0.f) ? h : NEG_SLOPE * h; p1 += h * ap0.w;
                h = e[2].x + b1.x + i1.x + j1.x; h = (h >= 0.f) ? h : NEG_SLOPE * h; p1 += h * ap1.x;
                h = e[2].y + b1.y + i1.y + j1.y; h = (h >= 0.f) ? h : NEG_SLOPE * h; p1 += h * ap1.y;
                h = e[3].x + b1.z + i1.z + j1.z; h = (h >= 0.f) ? h : NEG_SLOPE * h; p1 += h * ap1.z;
                h = e[3].y + b1.w + i1.w + j1.w; h = (h >= 0.f) ? h : NEG_SLOPE * h; p1 += h * ap1.w;
            }
            p0 += __shfl_xor_sync(0xffffffffu, p0, 1);
            p0 += __shfl_xor_sync(0xffffffffu, p0, 2);
            p1 += __shfl_xor_sync(0xffffffffu, p1, 1);
            p1 += __shfl_xor_sync(0xffffffffu, p1, 2);
            if (lq == 0) {
                float e0 = expf(p0), e1 = expf(p1);
                sEX[(wm * 16 + q) * 8 + head]     = e0;
                sEX[(wm * 16 + q + 8) * 8 + head] = e1;
                atomicAdd(&g_node_sum[s0 * 8 + head], e0);
                atomicAdd(&g_node_sum[s1 * 8 + head], e1);
            }
            if (nt == 3) __syncthreads();   // publish sEX across warps before message phase
        } else {
            // fused aggregation: unnormalized ex*msg -> red.add.v4 into g_agg
            int cm = (nt - 4) * 64 + wn * 32 + lq * 8;    // message col base
            int head = cm >> 4;
            float4 b0 = *(const float4*)(g_bE + 256 + cm);
            float4 b1 = *(const float4*)(g_bE + 256 + cm + 4);
            {
                float2 e[4];
                e[0] = make_float2(acc[0][0], acc[0][1]);
                e[1] = make_float2(acc[1][0], acc[1][1]);
                e[2] = make_float2(acc[2][0], acc[2][1]);
                e[3] = make_float2(acc[3][0], acc[3][1]);
                quad_transpose(e, lid);
                float ex0 = sEX[(wm * 16 + q) * 8 + head];
                const float* nm = g_node_tbl + (size_t)d0 * 640 + 512 + cm;
                float4 n0 = *(const float4*)nm, n1 = *(const float4*)(nm + 4);
                float* dst = g_agg + (size_t)s0 * 128 + cm;
                asm volatile("red.global.add.v4.f32 [%0], {%1,%2,%3,%4};"
                             :: "l"(dst),
                                "f"((e[0].x + b0.x + n0.x) * ex0), "f"((e[0].y + b0.y + n0.y) * ex0),
                                "f"((e[1].x + b0.z + n0.z) * ex0), "f"((e[1].y + b0.w + n0.w) * ex0) : "memory");
                asm volatile("red.global.add.v4.f32 [%0], {%1,%2,%3,%4};"
                             :: "l"(dst + 4),
                                "f"((e[2].x + b1.x + n1.x) * ex0), "f"((e[2].y + b1.y + n1.y) * ex0),
                                "f"((e[3].x + b1.z + n1.z) * ex0), "f"((e[3].y + b1.w + n1.w) * ex0) : "memory");
            }
            {
                float2 e[4];
                e[0] = make_float2(acc[0][2], acc[0][3]);
                e[1] = make_float2(acc[1][2], acc[1][3]);
                e[2] = make_float2(acc[2][2], acc[2][3]);
                e[3] = make_float2(acc[3][2], acc[3][3]);
                quad_transpose(e, lid);
                float ex1 = sEX[(wm * 16 + q + 8) * 8 + head];
                const float* nm = g_node_tbl + (size_t)d1 * 640 + 512 + cm;
                float4 n0 = *(const float4*)nm, n1 = *(const float4*)(nm + 4);
                float* dst = g_agg + (size_t)s1 * 128 + cm;
                asm volatile("red.global.add.v4.f32 [%0], {%1,%2,%3,%4};"
                             :: "l"(dst),
                                "f"((e[0].x + b0.x + n0.x) * ex1), "f"((e[0].y + b0.y + n0.y) * ex1),
                                "f"((e[1].x + b0.z + n0.z) * ex1), "f"((e[1].y + b0.w + n0.w) * ex1) : "memory");
                asm volatile("red.global.add.v4.f32 [%0], {%1,%2,%3,%4};"
                             :: "l"(dst + 4),
                                "f"((e[2].x + b1.x + n1.x) * ex1), "f"((e[2].y + b1.y + n1.y) * ex1),
                                "f"((e[3].x + b1.z + n1.z) * ex1), "f"((e[3].y + b1.w + n1.w) * ex1) : "memory");
            }
        }
    }
}

// ---------------- output GEMM with softmax normalization folded into A load ----------------
__global__ void out_gemm_kernel(const float* __restrict__ A, const float* __restrict__ B,
                                const float* __restrict__ bias, const float* __restrict__ sums,
                                float* __restrict__ C, int M) {
    __shared__ float As[16][64];
    __shared__ float Bs[16][64];
    int tid = threadIdx.x;
    int rt = tid >> 4, ct = tid & 15;
    int m0 = blockIdx.x * 64, n0 = blockIdx.y * 64;
    float acc[4][4] = {};
    int arow = tid >> 2, aq = tid & 3;
    int bk = tid >> 4, bq = tid & 15;
    for (int k0 = 0; k0 < 128; k0 += 16) {
        float4 av = make_float4(0.f, 0.f, 0.f, 0.f);
        int m = m0 + arow;
        if (m < M) {
            av = *(const float4*)(A + (size_t)m * 128 + k0 + aq * 4);
            float s = sums[m * 8 + (k0 >> 4)];
            float inv = 1.0f / s;
            av.x *= inv; av.y *= inv; av.z *= inv; av.w *= inv;
        }
        As[aq * 4 + 0][arow] = av.x; As[aq * 4 + 1][arow] = av.y;
        As[aq * 4 + 2][arow] = av.z; As[aq * 4 + 3][arow] = av.w;
        float4 bv = *(const float4*)(B + (size_t)(k0 + bk) * 128 + n0 + bq * 4);
        *(float4*)&Bs[bk][bq * 4] = bv;
        __syncthreads();
#pragma unroll
        for (int kk = 0; kk < 16; kk++) {
            float a[4], b[4];
            *(float4*)a = *(float4*)&As[kk][rt * 4];
            *(float4*)b = *(float4*)&Bs[kk][ct * 4];
#pragma unroll
            for (int i = 0; i < 4; i++)
#pragma unroll
                for (int j = 0; j < 4; j++)
                    acc[i][j] += a[i] * b[j];
        }
        __syncthreads();
    }
#pragma unroll
    for (int i = 0; i < 4; i++) {
        int m = m0 + rt * 4 + i;
        if (m < M) {
            int n = n0 + ct * 4;
            float4 o;
            o.x = acc[i][0] + bias[n + 0];
            o.y = acc[i][1] + bias[n + 1];
            o.z = acc[i][2] + bias[n + 2];
            o.w = acc[i][3] + bias[n + 3];
            *(float4*)(C + (size_t)m * 128 + n) = o;
        }
    }
}

// ---------------- launch ----------------
extern "C" void kernel_launch(void* const* d_in, const int* in_sizes, int n_in,
                              void* d_out, int out_size) {
    const float* node_features = (const float*)d_in[0];
    const float* edge_features = (const float*)d_in[1];
    const int*   edge_index    = (const int*)d_in[2];
    const float* Wni = (const float*)d_in[3];
    const float* bni = (const float*)d_in[4];
    const float* Wnj = (const float*)d_in[5];
    const float* bnj = (const float*)d_in[6];
    const float* We  = (const float*)d_in[7];
    const float* be  = (const float*)d_in[8];
    const float* attn_proj = (const float*)d_in[9];
    const float* Wm  = (const float*)d_in[10];
    const float* bm  = (const float*)d_in[11];
    const float* Wo  = (const float*)d_in[12];
    const float* bo  = (const float*)d_in[13];
    float* out = (float*)d_out;

    float *pAgg, *pWO, *pSum;
    cudaGetSymbolAddress((void**)&pAgg, g_agg);
    cudaGetSymbolAddress((void**)&pWO,  g_WO);
    cudaGetSymbolAddress((void**)&pSum, g_node_sum);

    static bool attr_set = false;
    if (!attr_set) {
        cudaFuncSetAttribute(mma_kernel, cudaFuncAttributeMaxDynamicSharedMemorySize, SM_TOT);
        attr_set = true;
    }

    const int ZTOT = N_NODES * NUM_HEADS + N_NODES * 128;
    zero_kernel<<<(ZTOT + 255) / 256, 256>>>();
    prepack_kernel<<<(81920 + 255) / 256, 256>>>(Wni, bni, Wnj, bnj, We, be, Wm, bm, Wo);
    prepack2_kernel<<<(80 * 8 * 32 + 255) / 256, 256>>>();

    // node tables: 157 M-tiles x 2 halves, 5 N-tiles each (sync-free)
    mma_kernel<<<dim3((N_NODES + 127) / 128, 2), 512, SM_TOT>>>(
        0, node_features, N_NODES, 5, edge_index, attn_proj);

    // edge pass (GEMM + attention + fused aggregation): 2500 M-tiles, 6 N-tiles
    mma_kernel<<<N_EDGES / 128, 512, SM_TOT>>>(
        1, edge_features, N_EDGES, 6, edge_index, attn_proj);

    // output projection with softmax normalization folded in
    out_gemm_kernel<<<dim3((N_NODES + 63) / 64, 2), 256>>>(pAgg, pWO, bo, pSum, out, N_NODES);
}

// round 12
// speedup vs baseline: 1.8681x; 1.0462x over previous
#include <cuda_runtime.h>
#include <cuda_bf16.h>
#include <cuda_fp16.h>
#include <cstdint>

#define N_NODES   20000
#define N_EDGES   320000
#define NUM_HEADS 8
#define NEG_SLOPE 0.2f

// ---------------- device scratch ----------------
__device__ float g_node_tbl[N_NODES * 640];   // [0:256)=ni_h, [256:512)=nj_h, [512:640)=node msg part
__device__ float g_node_sum[N_NODES * NUM_HEADS];   // softmax denominators
__device__ float g_agg[N_NODES * 128];              // UNNORMALIZED sum of ex*msg
// stage-1 prepack (node weights only): bf16 hi/lo splits, [n][k] k-contiguous
__device__ __nv_bfloat16 g_WNh[640 * 128];
__device__ __nv_bfloat16 g_WNl[640 * 128];
// stage-2 prepack: fragment-major B for direct LDG.128 per lane
// index: (cf*8 + ks)*32 + lane  ->  {b0_hi, b1_hi, b0_lo, b1_lo}
__device__ uint4 g_WNf[80 * 8 * 32];          // bf16 split frags (3-term node path)
__device__ uint4 g_WEf[48 * 8 * 32];          // fp16 split frags (2-term edge path)
__device__ float g_bN[640];
__device__ float g_bE[384];
__device__ float g_WO[128 * 128];             // [k][n] for FFMA out gemm

// ---------------- helpers ----------------
__device__ __forceinline__ uint32_t smem_u32(const void* p) {
    uint32_t a;
    asm("{ .reg .u64 t; cvta.to.shared.u64 t, %1; cvt.u32.u64 %0, t; }" : "=r"(a) : "l"(p));
    return a;
}

#define LDSM_X4(r0, r1, r2, r3, addr) \
    asm volatile("ldmatrix.sync.aligned.m8n8.x4.shared.b16 {%0,%1,%2,%3}, [%4];" \
                 : "=r"(r0), "=r"(r1), "=r"(r2), "=r"(r3) : "r"(addr))

#define MMA_BF16(c, a, b0, b1) \
    asm volatile("mma.sync.aligned.m16n8k16.row.col.f32.bf16.bf16.f32 " \
                 "{%0,%1,%2,%3}, {%4,%5,%6,%7}, {%8,%9}, {%0,%1,%2,%3};" \
                 : "+f"((c)[0]), "+f"((c)[1]), "+f"((c)[2]), "+f"((c)[3]) \
                 : "r"((a)[0]), "r"((a)[1]), "r"((a)[2]), "r"((a)[3]), \
                   "r"(b0), "r"(b1))

#define MMA_F16(c, a, b0, b1) \
    asm volatile("mma.sync.aligned.m16n8k16.row.col.f32.f16.f16.f32 " \
                 "{%0,%1,%2,%3}, {%4,%5,%6,%7}, {%8,%9}, {%0,%1,%2,%3};" \
                 : "+f"((c)[0]), "+f"((c)[1]), "+f"((c)[2]), "+f"((c)[3]) \
                 : "r"((a)[0]), "r"((a)[1]), "r"((a)[2]), "r"((a)[3]), \
                   "r"(b0), "r"(b1))

// 4x4 quad transpose of float2 elements via 2-stage shfl butterfly.
__device__ __forceinline__ void quad_transpose(float2 e[4], int lid) {
    {
        bool hi = (lid & 2);
        float2 s0 = hi ? e[0] : e[2];
        float2 s1 = hi ? e[1] : e[3];
        s0.x = __shfl_xor_sync(0xffffffffu, s0.x, 2);
        s0.y = __shfl_xor_sync(0xffffffffu, s0.y, 2);
        s1.x = __shfl_xor_sync(0xffffffffu, s1.x, 2);
        s1.y = __shfl_xor_sync(0xffffffffu, s1.y, 2);
        if (hi) { e[0] = s0; e[1] = s1; } else { e[2] = s0; e[3] = s1; }
    }
    {
        bool od = (lid & 1);
        float2 s0 = od ? e[0] : e[1];
        float2 s1 = od ? e[2] : e[3];
        s0.x = __shfl_xor_sync(0xffffffffu, s0.x, 1);
        s0.y = __shfl_xor_sync(0xffffffffu, s0.y, 1);
        s1.x = __shfl_xor_sync(0xffffffffu, s1.x, 1);
        s1.y = __shfl_xor_sync(0xffffffffu, s1.y, 1);
        if (od) { e[0] = s0; e[2] = s1; } else { e[1] = s0; e[3] = s1; }
    }
}

// smem layout (bytes), pitch 272 B per 128-col bf16/fp16 row:
// node mode: AH [0,34816) + AL [34816,69632)            -> dyn smem 69632
// edge mode: AH [0,34816) + sEX [34816,38912)           -> dyn smem 38912
#define APITCH_B 272
#define SM_AH 0
#define SM_AL 34816
#define SM_EX 34816
#define SMEM_NODE 69632
#define SMEM_EDGE 38912

// ---------------- init kernels ----------------
__global__ void zero_kernel() {
    int i = blockIdx.x * blockDim.x + threadIdx.x;
    const int NS = N_NODES * NUM_HEADS;
    const int TOT = NS + N_NODES * 128;
    if (i < NS) g_node_sum[i] = 0.f;
    else if (i < TOT) g_agg[i - NS] = 0.f;
}

__device__ __forceinline__ void split_store(float v, __nv_bfloat16* hi, __nv_bfloat16* lo, int i) {
    __nv_bfloat16 h = __float2bfloat16(v);
    hi[i] = h;
    lo[i] = __float2bfloat16(v - __bfloat162float(h));
}

__global__ void prepack_kernel(const float* __restrict__ Wni, const float* __restrict__ bni,
                               const float* __restrict__ Wnj, const float* __restrict__ bnj,
                               const float* __restrict__ be,
                               const float* __restrict__ Wm,  const float* __restrict__ bm,
                               const float* __restrict__ Wo) {
    int i = blockIdx.x * blockDim.x + threadIdx.x;
    if (i < 81920) {                       // WN [640][128] bf16 hi/lo
        int n = i >> 7, k = i & 127;
        float v;
        if (n < 256)      v = Wni[n * 128 + k];
        else if (n < 512) v = Wnj[(n - 256) * 128 + k];
        else              v = Wm[(n - 512) * 256 + k];
        split_store(v, g_WNh, g_WNl, i);
    }
    if (i < 640) g_bN[i] = (i < 256) ? bni[i] : (i < 512 ? bnj[i - 256] : 0.f);
    if (i < 384) g_bE[i] = (i < 256) ? be[i] : bm[i - 256];
    if (i < 16384) {                       // WO [k][n]
        int k = i >> 7, n = i & 127;
        g_WO[i] = Wo[n * 128 + k];
    }
}

// stage 2: build fragment-major B. WN from bf16 stage-1; WE as fp16 split from raw weights.
__global__ void prepack2_kernel(const float* __restrict__ We, const float* __restrict__ Wm) {
    int i = blockIdx.x * blockDim.x + threadIdx.x;
    int lane = i & 31;
    int ks   = (i >> 5) & 7;
    int cf   = i >> 8;
    int n  = (cf << 3) + (lane >> 2);
    int k0 = (ks << 4) + ((lane & 3) << 1);
    if (i < 80 * 8 * 32) {
        uint32_t b0h = *(const uint32_t*)(g_WNh + n * 128 + k0);
        uint32_t b1h = *(const uint32_t*)(g_WNh + n * 128 + k0 + 8);
        uint32_t b0l = *(const uint32_t*)(g_WNl + n * 128 + k0);
        uint32_t b1l = *(const uint32_t*)(g_WNl + n * 128 + k0 + 8);
        g_WNf[i] = make_uint4(b0h, b1h, b0l, b1l);
    }
    if (i < 48 * 8 * 32) {
        // WE logical row n, cols k: n<256 -> We, else edge half of Wm
        const float* src0 = (n < 256) ? (We + n * 128) : (Wm + (n - 256) * 256 + 128);
        float v0 = src0[k0],     v1 = src0[k0 + 1];
        float v2 = src0[k0 + 8], v3 = src0[k0 + 9];
        __half h0 = __float2half_rn(v0), h1 = __float2half_rn(v1);
        __half h2 = __float2half_rn(v2), h3 = __float2half_rn(v3);
        __half l0 = __float2half_rn(v0 - __half2float(h0));
        __half l1 = __float2half_rn(v1 - __half2float(h1));
        __half l2 = __float2half_rn(v2 - __half2float(h2));
        __half l3 = __float2half_rn(v3 - __half2float(h3));
        __half2 b0h = __halves2half2(h0, h1), b1h = __halves2half2(h2, h3);
        __half2 b0l = __halves2half2(l0, l1), b1l = __halves2half2(l2, l3);
        g_WEf[i] = make_uint4(*(uint32_t*)&b0h, *(uint32_t*)&b1h,
                              *(uint32_t*)&b0l, *(uint32_t*)&b1l);
    }
}

// ---------------- HMMA GEMM, sync-free mainloop, 2 CTAs/SM ----------------
// 512 threads = 16 warps: wm = wid>>1 (16-row strip), wn = wid&1 (32-col half of 64-wide N-tile)
// mode 0: node tables, 3-term bf16 split, grid.y=2, NB=5 each -> g_node_tbl (+bias)
// mode 1: edge pass, 2-term fp16 split, NB=6; nt 0..3 attention; barrier; nt 4,5 messages->red.add
__global__ void __launch_bounds__(512, 2) mma_kernel(
    int mode, const float* __restrict__ A, int M, int NB,
    const int* __restrict__ EI, const float* __restrict__ AP) {
    extern __shared__ char smem[];
    uint32_t sb = smem_u32(smem);
    float* sEX = (float*)(smem + SM_EX);
    int tid = threadIdx.x;
    int wid = tid >> 5, lid = tid & 31;
    int m0 = blockIdx.x * 128;
    int nt0 = blockIdx.y * NB;

    // ---- fill A tile once ----
    if (mode == 0) {   // bf16 hi/lo
#pragma unroll
        for (int u = tid; u < 4096; u += 512) {
            int r = u >> 5, c = (u & 31) << 2;
            int row = m0 + r;
            float4 v = make_float4(0.f, 0.f, 0.f, 0.f);
            if (row < M) v = *(const float4*)(A + (size_t)row * 128 + c);
            __nv_bfloat162 h01 = __floats2bfloat162_rn(v.x, v.y);
            __nv_bfloat162 h23 = __floats2bfloat162_rn(v.z, v.w);
            float2 f01 = __bfloat1622float2(h01);
            float2 f23 = __bfloat1622float2(h23);
            __nv_bfloat162 l01 = __floats2bfloat162_rn(v.x - f01.x, v.y - f01.y);
            __nv_bfloat162 l23 = __floats2bfloat162_rn(v.z - f23.x, v.w - f23.y);
            uint32_t off = r * APITCH_B + c * 2;
            *(uint2*)(smem + SM_AH + off) = make_uint2(*(uint32_t*)&h01, *(uint32_t*)&h23);
            *(uint2*)(smem + SM_AL + off) = make_uint2(*(uint32_t*)&l01, *(uint32_t*)&l23);
        }
    } else {           // fp16 single
#pragma unroll
        for (int u = tid; u < 4096; u += 512) {
            int r = u >> 5, c = (u & 31) << 2;
            float4 v = *(const float4*)(A + (size_t)(m0 + r) * 128 + c);
            __half2 h01 = __floats2half2_rn(v.x, v.y);
            __half2 h23 = __floats2half2_rn(v.z, v.w);
            uint32_t off = r * APITCH_B + c * 2;
            *(uint2*)(smem + SM_AH + off) = make_uint2(*(uint32_t*)&h01, *(uint32_t*)&h23);
        }
    }
    __syncthreads();   // the only barrier needed for the GEMM mainloop

    int wm = wid >> 1, wn = wid & 1;
    int lr = lid & 15, lc = lid >> 4;
    int q  = lid >> 2, lq = lid & 3;

    int r0 = m0 + wm * 16 + q;
    int r1 = r0 + 8;
    int s0 = 0, d0 = 0, s1 = 0, d1 = 0;
    if (mode == 1) {
        s0 = EI[r0]; d0 = EI[N_EDGES + r0];
        s1 = EI[r1]; d1 = EI[N_EDGES + r1];
    }

    for (int ntl = 0; ntl < NB; ntl++) {
        int nt = nt0 + ntl;
        float acc[4][4];
#pragma unroll
        for (int f = 0; f < 4; f++)
#pragma unroll
            for (int j = 0; j < 4; j++) acc[f][j] = 0.f;

        if (mode == 0) {
            const uint4* bp = g_WNf + (size_t)(nt * 8 + wn * 4) * 256 + lid;
#pragma unroll
            for (int ks = 0; ks < 8; ks++) {
                uint32_t ah[4], al[4];
                uint32_t aoff = (uint32_t)((wm * 16 + lr) * APITCH_B + (ks * 16 + lc * 8) * 2);
                LDSM_X4(ah[0], ah[1], ah[2], ah[3], sb + SM_AH + aoff);
                LDSM_X4(al[0], al[1], al[2], al[3], sb + SM_AL + aoff);
                uint4 bv0 = bp[0 * 256 + ks * 32];
                uint4 bv1 = bp[1 * 256 + ks * 32];
                uint4 bv2 = bp[2 * 256 + ks * 32];
                uint4 bv3 = bp[3 * 256 + ks * 32];
                MMA_BF16(acc[0], ah, bv0.x, bv0.y);
                MMA_BF16(acc[0], ah, bv0.z, bv0.w);
                MMA_BF16(acc[0], al, bv0.x, bv0.y);
                MMA_BF16(acc[1], ah, bv1.x, bv1.y);
                MMA_BF16(acc[1], ah, bv1.z, bv1.w);
                MMA_BF16(acc[1], al, bv1.x, bv1.y);
                MMA_BF16(acc[2], ah, bv2.x, bv2.y);
                MMA_BF16(acc[2], ah, bv2.z, bv2.w);
                MMA_BF16(acc[2], al, bv2.x, bv2.y);
                MMA_BF16(acc[3], ah, bv3.x, bv3.y);
                MMA_BF16(acc[3], ah, bv3.z, bv3.w);
                MMA_BF16(acc[3], al, bv3.x, bv3.y);
            }
        } else {
            const uint4* bp = g_WEf + (size_t)(nt * 8 + wn * 4) * 256 + lid;
#pragma unroll
            for (int ks = 0; ks < 8; ks++) {
                uint32_t ah[4];
                uint32_t aoff = (uint32_t)((wm * 16 + lr) * APITCH_B + (ks * 16 + lc * 8) * 2);
                LDSM_X4(ah[0], ah[1], ah[2], ah[3], sb + SM_AH + aoff);
                uint4 bv0 = bp[0 * 256 + ks * 32];
                uint4 bv1 = bp[1 * 256 + ks * 32];
                uint4 bv2 = bp[2 * 256 + ks * 32];
                uint4 bv3 = bp[3 * 256 + ks * 32];
                MMA_F16(acc[0], ah, bv0.x, bv0.y);
                MMA_F16(acc[0], ah, bv0.z, bv0.w);
                MMA_F16(acc[1], ah, bv1.x, bv1.y);
                MMA_F16(acc[1], ah, bv1.z, bv1.w);
                MMA_F16(acc[2], ah, bv2.x, bv2.y);
                MMA_F16(acc[2], ah, bv2.z, bv2.w);
                MMA_F16(acc[3], ah, bv3.x, bv3.y);
                MMA_F16(acc[3], ah, bv3.z, bv3.w);
            }
        }

        // ---- register epilogue (quad-transposed: lane owns 8 contiguous cols) ----
        int cg = nt * 64 + wn * 32 + lq * 8;
        if (mode == 0) {
            float4 b0 = *(const float4*)(g_bN + cg);
            float4 b1 = *(const float4*)(g_bN + cg + 4);
            float2 e[4];
            e[0] = make_float2(acc[0][0], acc[0][1]);
            e[1] = make_float2(acc[1][0], acc[1][1]);
            e[2] = make_float2(acc[2][0], acc[2][1]);
            e[3] = make_float2(acc[3][0], acc[3][1]);
            quad_transpose(e, lid);
            if (r0 < M) {
                float* dst = g_node_tbl + (size_t)r0 * 640 + cg;
                *(float4*)dst       = make_float4(e[0].x + b0.x, e[0].y + b0.y, e[1].x + b0.z, e[1].y + b0.w);
                *(float4*)(dst + 4) = make_float4(e[2].x + b1.x, e[2].y + b1.y, e[3].x + b1.z, e[3].y + b1.w);
            }
            e[0] = make_float2(acc[0][2], acc[0][3]);
            e[1] = make_float2(acc[1][2], acc[1][3]);
            e[2] = make_float2(acc[2][2], acc[2][3]);
            e[3] = make_float2(acc[3][2], acc[3][3]);
            quad_transpose(e, lid);
            if (r1 < M) {
                float* dst = g_node_tbl + (size_t)r1 * 640 + cg;
                *(float4*)dst       = make_float4(e[0].x + b0.x, e[0].y + b0.y, e[1].x + b0.z, e[1].y + b0.w);
                *(float4*)(dst + 4) = make_float4(e[2].x + b1.x, e[2].y + b1.y, e[3].x + b1.z, e[3].y + b1.w);
            }
        } else if (nt < 4) {
            int head = nt * 2 + wn;
            float4 b0  = *(const float4*)(g_bE + cg);
            float4 b1  = *(const float4*)(g_bE + cg + 4);
            float4 ap0 = *(const float4*)(AP + head * 32 + lq * 8);
            float4 ap1 = *(const float4*)(AP + head * 32 + lq * 8 + 4);
            float p0, p1;
            {
                float2 e[4];
                e[0] = make_float2(acc[0][0], acc[0][1]);
                e[1] = make_float2(acc[1][0], acc[1][1]);
                e[2] = make_float2(acc[2][0], acc[2][1]);
                e[3] = make_float2(acc[3][0], acc[3][1]);
                quad_transpose(e, lid);
                const float* ni = g_node_tbl + (size_t)s0 * 640 + cg;
                const float* nj = g_node_tbl + (size_t)d0 * 640 + 256 + cg;
                float4 i0 = *(const float4*)ni, i1 = *(const float4*)(ni + 4);
                float4 j0 = *(const float4*)nj, j1 = *(const float4*)(nj + 4);
                float h; p0 = 0.f;
                h = e[0].x + b0.x + i0.x + j0.x; h = (h >= 0.f) ? h : NEG_SLOPE * h; p0 += h * ap0.x;
                h = e[0].y + b0.y + i0.y + j0.y; h = (h >= 0.f) ? h : NEG_SLOPE * h; p0 += h * ap0.y;
                h = e[1].x + b0.z + i0.z + j0.z; h = (h >= 0.f) ? h : NEG_SLOPE * h; p0 += h * ap0.z;
                h = e[1].y + b0.w + i0.w + j0.w; h = (h >= 0.f) ? h : NEG_SLOPE * h; p0 += h * ap0.w;
                h = e[2].x + b1.x + i1.x + j1.x; h = (h >= 0.f) ? h : NEG_SLOPE * h; p0 += h * ap1.x;
                h = e[2].y + b1.y + i1.y + j1.y; h = (h >= 0.f) ? h : NEG_SLOPE * h; p0 += h * ap1.y;
                h = e[3].x + b1.z + i1.z + j1.z; h = (h >= 0.f) ? h : NEG_SLOPE * h; p0 += h * ap1.z;
                h = e[3].y + b1.w + i1.w + j1.w; h = (h >= 0.f) ? h : NEG_SLOPE * h; p0 += h * ap1.w;
            }
            {
                float2 e[4];
                e[0] = make_float2(acc[0][2], acc[0][3]);
                e[1] = make_float2(acc[1][2], acc[1][3]);
                e[2] = make_float2(acc[2][2], acc[2][3]);
                e[3] = make_float2(acc[3][2], acc[3][3]);
                quad_transpose(e, lid);
                const float* ni = g_node_tbl + (size_t)s1 * 640 + cg;
                const float* nj = g_node_tbl + (size_t)d1 * 640 + 256 + cg;
                float4 i0 = *(const float4*)ni, i1 = *(const float4*)(ni + 4);
                float4 j0 = *(const float4*)nj, j1 = *(const float4*)(nj + 4);
                float h; p1 = 0.f;
                h = e[0].x + b0.x + i0.x + j0.x; h = (h >= 0.f) ? h : NEG_SLOPE * h; p1 += h * ap0.x;
                h = e[0].y + b0.y + i0.y + j0.y; h = (h >= 0.f) ? h : NEG_SLOPE * h; p1 += h * ap0.y;
                h = e[1].x + b0.z + i0.z + j0.z; h = (h >= 0.f) ? h : NEG_SLOPE * h; p1 += h * ap0.z;
                h = e[1].y + b0.w + i0.w + j0.w; h = (h >= 0.f) ? h : NEG_SLOPE * h; p1 += h * ap0.w;
                h = e[2].x + b1.x + i1.x + j1.x; h = (h >= 0.f) ? h : NEG_SLOPE * h; p1 += h * ap1.x;
                h = e[2].y + b1.y + i1.y + j1.y; h = (h >= 0.f) ? h : NEG_SLOPE * h; p1 += h * ap1.y;
                h = e[3].x + b1.z + i1.z + j1.z; h = (h >= 0.f) ? h : NEG_SLOPE * h; p1 += h * ap1.z;
                h = e[3].y + b1.w + i1.w + j1.w; h = (h >= 0.f) ? h : NEG_SLOPE * h; p1 += h * ap1.w;
            }
            p0 += __shfl_xor_sync(0xffffffffu, p0, 1);
            p0 += __shfl_xor_sync(0xffffffffu, p0, 2);
            p1 += __shfl_xor_sync(0xffffffffu, p1, 1);
            p1 += __shfl_xor_sync(0xffffffffu, p1, 2);
            if (lq == 0) {
                float e0 = expf(p0), e1 = expf(p1);
                sEX[(wm * 16 + q) * 8 + head]     = e0;
                sEX[(wm * 16 + q + 8) * 8 + head] = e1;
                atomicAdd(&g_node_sum[s0 * 8 + head], e0);
                atomicAdd(&g_node_sum[s1 * 8 + head], e1);
            }
            if (nt == 3) __syncthreads();   // publish sEX before message phase
        } else {
            int cm = (nt - 4) * 64 + wn * 32 + lq * 8;
            int head = cm >> 4;
            float4 b0 = *(const float4*)(g_bE + 256 + cm);
            float4 b1 = *(const float4*)(g_bE + 256 + cm + 4);
            {
                float2 e[4];
                e[0] = make_float2(acc[0][0], acc[0][1]);
                e[1] = make_float2(acc[1][0], acc[1][1]);
                e[2] = make_float2(acc[2][0], acc[2][1]);
                e[3] = make_float2(acc[3][0], acc[3][1]);
                quad_transpose(e, lid);
                float ex0 = sEX[(wm * 16 + q) * 8 + head];
                const float* nm = g_node_tbl + (size_t)d0 * 640 + 512 + cm;
                float4 n0 = *(const float4*)nm, n1 = *(const float4*)(nm + 4);
                float* dst = g_agg + (size_t)s0 * 128 + cm;
                asm volatile("red.global.add.v4.f32 [%0], {%1,%2,%3,%4};"
                             :: "l"(dst),
                                "f"((e[0].x + b0.x + n0.x) * ex0), "f"((e[0].y + b0.y + n0.y) * ex0),
                                "f"((e[1].x + b0.z + n0.z) * ex0), "f"((e[1].y + b0.w + n0.w) * ex0) : "memory");
                asm volatile("red.global.add.v4.f32 [%0], {%1,%2,%3,%4};"
                             :: "l"(dst + 4),
                                "f"((e[2].x + b1.x + n1.x) * ex0), "f"((e[2].y + b1.y + n1.y) * ex0),
                                "f"((e[3].x + b1.z + n1.z) * ex0), "f"((e[3].y + b1.w + n1.w) * ex0) : "memory");
            }
            {
                float2 e[4];
                e[0] = make_float2(acc[0][2], acc[0][3]);
                e[1] = make_float2(acc[1][2], acc[1][3]);
                e[2] = make_float2(acc[2][2], acc[2][3]);
                e[3] = make_float2(acc[3][2], acc[3][3]);
                quad_transpose(e, lid);
                float ex1 = sEX[(wm * 16 + q + 8) * 8 + head];
                const float* nm = g_node_tbl + (size_t)d1 * 640 + 512 + cm;
                float4 n0 = *(const float4*)nm, n1 = *(const float4*)(nm + 4);
                float* dst = g_agg + (size_t)s1 * 128 + cm;
                asm volatile("red.global.add.v4.f32 [%0], {%1,%2,%3,%4};"
                             :: "l"(dst),
                                "f"((e[0].x + b0.x + n0.x) * ex1), "f"((e[0].y + b0.y + n0.y) * ex1),
                                "f"((e[1].x + b0.z + n0.z) * ex1), "f"((e[1].y + b0.w + n0.w) * ex1) : "memory");
                asm volatile("red.global.add.v4.f32 [%0], {%1,%2,%3,%4};"
                             :: "l"(dst + 4),
                                "f"((e[2].x + b1.x + n1.x) * ex1), "f"((e[2].y + b1.y + n1.y) * ex1),
                                "f"((e[3].x + b1.z + n1.z) * ex1), "f"((e[3].y + b1.w + n1.w) * ex1) : "memory");
            }
        }
    }
}

// ---------------- output GEMM with softmax normalization folded into A load ----------------
__global__ void out_gemm_kernel(const float* __restrict__ A, const float* __restrict__ B,
                                const float* __restrict__ bias, const float* __restrict__ sums,
                                float* __restrict__ C, int M) {
    __shared__ float As[16][64];
    __shared__ float Bs[16][64];
    int tid = threadIdx.x;
    int rt = tid >> 4, ct = tid & 15;
    int m0 = blockIdx.x * 64, n0 = blockIdx.y * 64;
    float acc[4][4] = {};
    int arow = tid >> 2, aq = tid & 3;
    int bk = tid >> 4, bq = tid & 15;
    for (int k0 = 0; k0 < 128; k0 += 16) {
        float4 av = make_float4(0.f, 0.f, 0.f, 0.f);
        int m = m0 + arow;
        if (m < M) {
            av = *(const float4*)(A + (size_t)m * 128 + k0 + aq * 4);
            float s = sums[m * 8 + (k0 >> 4)];
            float inv = 1.0f / s;
            av.x *= inv; av.y *= inv; av.z *= inv; av.w *= inv;
        }
        As[aq * 4 + 0][arow] = av.x; As[aq * 4 + 1][arow] = av.y;
        As[aq * 4 + 2][arow] = av.z; As[aq * 4 + 3][arow] = av.w;
        float4 bv = *(const float4*)(B + (size_t)(k0 + bk) * 128 + n0 + bq * 4);
        *(float4*)&Bs[bk][bq * 4] = bv;
        __syncthreads();
#pragma unroll
        for (int kk = 0; kk < 16; kk++) {
            float a[4], b[4];
            *(float4*)a = *(float4*)&As[kk][rt * 4];
            *(float4*)b = *(float4*)&Bs[kk][ct * 4];
#pragma unroll
            for (int i = 0; i < 4; i++)
#pragma unroll
                for (int j = 0; j < 4; j++)
                    acc[i][j] += a[i] * b[j];
        }
        __syncthreads();
    }
#pragma unroll
    for (int i = 0; i < 4; i++) {
        int m = m0 + rt * 4 + i;
        if (m < M) {
            int n = n0 + ct * 4;
            float4 o;
            o.x = acc[i][0] + bias[n + 0];
            o.y = acc[i][1] + bias[n + 1];
            o.z = acc[i][2] + bias[n + 2];
            o.w = acc[i][3] + bias[n + 3];
            *(float4*)(C + (size_t)m * 128 + n) = o;
        }
    }
}

// ---------------- launch ----------------
extern "C" void kernel_launch(void* const* d_in, const int* in_sizes, int n_in,
                              void* d_out, int out_size) {
    const float* node_features = (const float*)d_in[0];
    const float* edge_features = (const float*)d_in[1];
    const int*   edge_index    = (const int*)d_in[2];
    const float* Wni = (const float*)d_in[3];
    const float* bni = (const float*)d_in[4];
    const float* Wnj = (const float*)d_in[5];
    const float* bnj = (const float*)d_in[6];
    const float* We  = (const float*)d_in[7];
    const float* be  = (const float*)d_in[8];
    const float* attn_proj = (const float*)d_in[9];
    const float* Wm  = (const float*)d_in[10];
    const float* bm  = (const float*)d_in[11];
    const float* Wo  = (const float*)d_in[12];
    const float* bo  = (const float*)d_in[13];
    float* out = (float*)d_out;

    float *pAgg, *pWO, *pSum;
    cudaGetSymbolAddress((void**)&pAgg, g_agg);
    cudaGetSymbolAddress((void**)&pWO,  g_WO);
    cudaGetSymbolAddress((void**)&pSum, g_node_sum);

    static bool attr_set = false;
    if (!attr_set) {
        cudaFuncSetAttribute(mma_kernel, cudaFuncAttributeMaxDynamicSharedMemorySize, SMEM_NODE);
        attr_set = true;
    }

    const int ZTOT = N_NODES * NUM_HEADS + N_NODES * 128;
    zero_kernel<<<(ZTOT + 255) / 256, 256>>>();
    prepack_kernel<<<(81920 + 255) / 256, 256>>>(Wni, bni, Wnj, bnj, be, Wm, bm, Wo);
    prepack2_kernel<<<(80 * 8 * 32 + 255) / 256, 256>>>(We, Wm);

    // node tables: 157 M-tiles x 2 halves, 5 N-tiles each (3-term bf16)
    mma_kernel<<<dim3((N_NODES + 127) / 128, 2), 512, SMEM_NODE>>>(
        0, node_features, N_NODES, 5, edge_index, attn_proj);

    // edge pass (2-term fp16 GEMM + attention + fused aggregation): 2500 M-tiles, 6 N-tiles
    mma_kernel<<<N_EDGES / 128, 512, SMEM_EDGE>>>(
        1, edge_features, N_EDGES, 6, edge_index, attn_proj);

    // output projection with softmax normalization folded in
    out_gemm_kernel<<<dim3((N_NODES + 63) / 64, 2), 256>>>(pAgg, pWO, bo, pSum, out, N_NODES);
}

// round 13
// speedup vs baseline: 1.9363x; 1.0365x over previous
#include <cuda_runtime.h>
#include <cuda_bf16.h>
#include <cuda_fp16.h>
#include <cstdint>

#define N_NODES   20000
#define N_EDGES   320000
#define NUM_HEADS 8
#define NEG_SLOPE 0.2f

// ---------------- device scratch ----------------
__device__ float g_node_tbl[N_NODES * 640];   // [0:256)=ni_h, [256:512)=nj_h, [512:640)=node msg part
__device__ float g_node_sum[N_NODES * NUM_HEADS];
__device__ float g_agg[N_NODES * 128];              // UNNORMALIZED sum of ex*msg
__device__ __nv_bfloat16 g_WNh[640 * 128];
__device__ __nv_bfloat16 g_WNl[640 * 128];
// fragment-major B: (cf*8 + ks)*32 + lane -> {b0_hi, b1_hi, b0_lo, b1_lo}
__device__ uint4 g_WNf[80 * 8 * 32];          // bf16 split (3-term node path)
__device__ uint4 g_WEf[48 * 8 * 32];          // fp16 split (2-term edge path)
__device__ float g_bN[640];
__device__ float g_bE[384];
__device__ float g_WO[128 * 128];

// ---------------- helpers ----------------
__device__ __forceinline__ uint32_t smem_u32(const void* p) {
    uint32_t a;
    asm("{ .reg .u64 t; cvta.to.shared.u64 t, %1; cvt.u32.u64 %0, t; }" : "=r"(a) : "l"(p));
    return a;
}

#define LDSM_X4(r0, r1, r2, r3, addr) \
    asm volatile("ldmatrix.sync.aligned.m8n8.x4.shared.b16 {%0,%1,%2,%3}, [%4];" \
                 : "=r"(r0), "=r"(r1), "=r"(r2), "=r"(r3) : "r"(addr))

#define MMA_BF16(c, a, b0, b1) \
    asm volatile("mma.sync.aligned.m16n8k16.row.col.f32.bf16.bf16.f32 " \
                 "{%0,%1,%2,%3}, {%4,%5,%6,%7}, {%8,%9}, {%0,%1,%2,%3};" \
                 : "+f"((c)[0]), "+f"((c)[1]), "+f"((c)[2]), "+f"((c)[3]) \
                 : "r"((a)[0]), "r"((a)[1]), "r"((a)[2]), "r"((a)[3]), \
                   "r"(b0), "r"(b1))

#define MMA_F16(c, a, b0, b1) \
    asm volatile("mma.sync.aligned.m16n8k16.row.col.f32.f16.f16.f32 " \
                 "{%0,%1,%2,%3}, {%4,%5,%6,%7}, {%8,%9}, {%0,%1,%2,%3};" \
                 : "+f"((c)[0]), "+f"((c)[1]), "+f"((c)[2]), "+f"((c)[3]) \
                 : "r"((a)[0]), "r"((a)[1]), "r"((a)[2]), "r"((a)[3]), \
                   "r"(b0), "r"(b1))

__device__ __forceinline__ void quad_transpose(float2 e[4], int lid) {
    {
        bool hi = (lid & 2);
        float2 s0 = hi ? e[0] : e[2];
        float2 s1 = hi ? e[1] : e[3];
        s0.x = __shfl_xor_sync(0xffffffffu, s0.x, 2);
        s0.y = __shfl_xor_sync(0xffffffffu, s0.y, 2);
        s1.x = __shfl_xor_sync(0xffffffffu, s1.x, 2);
        s1.y = __shfl_xor_sync(0xffffffffu, s1.y, 2);
        if (hi) { e[0] = s0; e[1] = s1; } else { e[2] = s0; e[3] = s1; }
    }
    {
        bool od = (lid & 1);
        float2 s0 = od ? e[0] : e[1];
        float2 s1 = od ? e[2] : e[3];
        s0.x = __shfl_xor_sync(0xffffffffu, s0.x, 1);
        s0.y = __shfl_xor_sync(0xffffffffu, s0.y, 1);
        s1.x = __shfl_xor_sync(0xffffffffu, s1.x, 1);
        s1.y = __shfl_xor_sync(0xffffffffu, s1.y, 1);
        if (od) { e[0] = s0; e[2] = s1; } else { e[1] = s0; e[3] = s1; }
    }
}

#define APITCH_B 272
#define SM_AH 0
#define SM_AL 34816
#define SM_EX 34816
#define SMEM_NODE 69632
#define SMEM_EDGE 38912

// ---------------- init kernels ----------------
__global__ void zero_kernel() {
    int i = blockIdx.x * blockDim.x + threadIdx.x;
    const int NS = N_NODES * NUM_HEADS;
    const int TOT = NS + N_NODES * 128;
    if (i < NS) g_node_sum[i] = 0.f;
    else if (i < TOT) g_agg[i - NS] = 0.f;
}

__device__ __forceinline__ void split_store(float v, __nv_bfloat16* hi, __nv_bfloat16* lo, int i) {
    __nv_bfloat16 h = __float2bfloat16(v);
    hi[i] = h;
    lo[i] = __float2bfloat16(v - __bfloat162float(h));
}

__global__ void prepack_kernel(const float* __restrict__ Wni, const float* __restrict__ bni,
                               const float* __restrict__ Wnj, const float* __restrict__ bnj,
                               const float* __restrict__ be,
                               const float* __restrict__ Wm,  const float* __restrict__ bm,
                               const float* __restrict__ Wo) {
    int i = blockIdx.x * blockDim.x + threadIdx.x;
    if (i < 81920) {
        int n = i >> 7, k = i & 127;
        float v;
        if (n < 256)      v = Wni[n * 128 + k];
        else if (n < 512) v = Wnj[(n - 256) * 128 + k];
        else              v = Wm[(n - 512) * 256 + k];
        split_store(v, g_WNh, g_WNl, i);
    }
    if (i < 640) g_bN[i] = (i < 256) ? bni[i] : (i < 512 ? bnj[i - 256] : 0.f);
    if (i < 384) g_bE[i] = (i < 256) ? be[i] : bm[i - 256];
    if (i < 16384) {
        int k = i >> 7, n = i & 127;
        g_WO[i] = Wo[n * 128 + k];
    }
}

__global__ void prepack2_kernel(const float* __restrict__ We, const float* __restrict__ Wm) {
    int i = blockIdx.x * blockDim.x + threadIdx.x;
    int lane = i & 31;
    int ks   = (i >> 5) & 7;
    int cf   = i >> 8;
    int n  = (cf << 3) + (lane >> 2);
    int k0 = (ks << 4) + ((lane & 3) << 1);
    if (i < 80 * 8 * 32) {
        uint32_t b0h = *(const uint32_t*)(g_WNh + n * 128 + k0);
        uint32_t b1h = *(const uint32_t*)(g_WNh + n * 128 + k0 + 8);
        uint32_t b0l = *(const uint32_t*)(g_WNl + n * 128 + k0);
        uint32_t b1l = *(const uint32_t*)(g_WNl + n * 128 + k0 + 8);
        g_WNf[i] = make_uint4(b0h, b1h, b0l, b1l);
    }
    if (i < 48 * 8 * 32) {
        const float* src0 = (n < 256) ? (We + n * 128) : (Wm + (n - 256) * 256 + 128);
        float v0 = src0[k0],     v1 = src0[k0 + 1];
        float v2 = src0[k0 + 8], v3 = src0[k0 + 9];
        __half h0 = __float2half_rn(v0), h1 = __float2half_rn(v1);
        __half h2 = __float2half_rn(v2), h3 = __float2half_rn(v3);
        __half l0 = __float2half_rn(v0 - __half2float(h0));
        __half l1 = __float2half_rn(v1 - __half2float(h1));
        __half l2 = __float2half_rn(v2 - __half2float(h2));
        __half l3 = __float2half_rn(v3 - __half2float(h3));
        __half2 b0h = __halves2half2(h0, h1), b1h = __halves2half2(h2, h3);
        __half2 b0l = __halves2half2(l0, l1), b1l = __halves2half2(l2, l3);
        g_WEf[i] = make_uint4(*(uint32_t*)&b0h, *(uint32_t*)&b1h,
                              *(uint32_t*)&b0l, *(uint32_t*)&b1l);
    }
}

// ---------------- node-table kernel: 512 threads, 3-term bf16, warp 16x32 ----------------
__global__ void __launch_bounds__(512, 2) node_kernel(
    const float* __restrict__ A, int M, int NB) {
    extern __shared__ char smem[];
    uint32_t sb = smem_u32(smem);
    int tid = threadIdx.x;
    int wid = tid >> 5, lid = tid & 31;
    int m0 = blockIdx.x * 128;
    int nt0 = blockIdx.y * NB;

#pragma unroll
    for (int u = tid; u < 4096; u += 512) {
        int r = u >> 5, c = (u & 31) << 2;
        int row = m0 + r;
        float4 v = make_float4(0.f, 0.f, 0.f, 0.f);
        if (row < M) v = *(const float4*)(A + (size_t)row * 128 + c);
        __nv_bfloat162 h01 = __floats2bfloat162_rn(v.x, v.y);
        __nv_bfloat162 h23 = __floats2bfloat162_rn(v.z, v.w);
        float2 f01 = __bfloat1622float2(h01);
        float2 f23 = __bfloat1622float2(h23);
        __nv_bfloat162 l01 = __floats2bfloat162_rn(v.x - f01.x, v.y - f01.y);
        __nv_bfloat162 l23 = __floats2bfloat162_rn(v.z - f23.x, v.w - f23.y);
        uint32_t off = r * APITCH_B + c * 2;
        *(uint2*)(smem + SM_AH + off) = make_uint2(*(uint32_t*)&h01, *(uint32_t*)&h23);
        *(uint2*)(smem + SM_AL + off) = make_uint2(*(uint32_t*)&l01, *(uint32_t*)&l23);
    }
    __syncthreads();

    int wm = wid >> 1, wn = wid & 1;
    int lr = lid & 15, lc = lid >> 4;
    int q  = lid >> 2, lq = lid & 3;
    int r0 = m0 + wm * 16 + q;
    int r1 = r0 + 8;

    for (int ntl = 0; ntl < NB; ntl++) {
        int nt = nt0 + ntl;
        float acc[4][4];
#pragma unroll
        for (int f = 0; f < 4; f++)
#pragma unroll
            for (int j = 0; j < 4; j++) acc[f][j] = 0.f;

        const uint4* bp = g_WNf + (size_t)(nt * 8 + wn * 4) * 256 + lid;
#pragma unroll
        for (int ks = 0; ks < 8; ks++) {
            uint32_t ah[4], al[4];
            uint32_t aoff = (uint32_t)((wm * 16 + lr) * APITCH_B + (ks * 16 + lc * 8) * 2);
            LDSM_X4(ah[0], ah[1], ah[2], ah[3], sb + SM_AH + aoff);
            LDSM_X4(al[0], al[1], al[2], al[3], sb + SM_AL + aoff);
            uint4 bv0 = bp[0 * 256 + ks * 32];
            uint4 bv1 = bp[1 * 256 + ks * 32];
            uint4 bv2 = bp[2 * 256 + ks * 32];
            uint4 bv3 = bp[3 * 256 + ks * 32];
            MMA_BF16(acc[0], ah, bv0.x, bv0.y);
            MMA_BF16(acc[0], ah, bv0.z, bv0.w);
            MMA_BF16(acc[0], al, bv0.x, bv0.y);
            MMA_BF16(acc[1], ah, bv1.x, bv1.y);
            MMA_BF16(acc[1], ah, bv1.z, bv1.w);
            MMA_BF16(acc[1], al, bv1.x, bv1.y);
            MMA_BF16(acc[2], ah, bv2.x, bv2.y);
            MMA_BF16(acc[2], ah, bv2.z, bv2.w);
            MMA_BF16(acc[2], al, bv2.x, bv2.y);
            MMA_BF16(acc[3], ah, bv3.x, bv3.y);
            MMA_BF16(acc[3], ah, bv3.z, bv3.w);
            MMA_BF16(acc[3], al, bv3.x, bv3.y);
        }

        int cg = nt * 64 + wn * 32 + lq * 8;
        float4 b0 = *(const float4*)(g_bN + cg);
        float4 b1 = *(const float4*)(g_bN + cg + 4);
        float2 e[4];
        e[0] = make_float2(acc[0][0], acc[0][1]);
        e[1] = make_float2(acc[1][0], acc[1][1]);
        e[2] = make_float2(acc[2][0], acc[2][1]);
        e[3] = make_float2(acc[3][0], acc[3][1]);
        quad_transpose(e, lid);
        if (r0 < M) {
            float* dst = g_node_tbl + (size_t)r0 * 640 + cg;
            *(float4*)dst       = make_float4(e[0].x + b0.x, e[0].y + b0.y, e[1].x + b0.z, e[1].y + b0.w);
            *(float4*)(dst + 4) = make_float4(e[2].x + b1.x, e[2].y + b1.y, e[3].x + b1.z, e[3].y + b1.w);
        }
        e[0] = make_float2(acc[0][2], acc[0][3]);
        e[1] = make_float2(acc[1][2], acc[1][3]);
        e[2] = make_float2(acc[2][2], acc[2][3]);
        e[3] = make_float2(acc[3][2], acc[3][3]);
        quad_transpose(e, lid);
        if (r1 < M) {
            float* dst = g_node_tbl + (size_t)r1 * 640 + cg;
            *(float4*)dst       = make_float4(e[0].x + b0.x, e[0].y + b0.y, e[1].x + b0.z, e[1].y + b0.w);
            *(float4*)(dst + 4) = make_float4(e[2].x + b1.x, e[2].y + b1.y, e[3].x + b1.z, e[3].y + b1.w);
        }
    }
}

// ---------------- edge kernel: 256 threads, 2-term fp16, warp 32x32 (B redundancy 4x) ----
__global__ void __launch_bounds__(256, 3) edge_kernel(
    const float* __restrict__ A, const int* __restrict__ EI, const float* __restrict__ AP) {
    extern __shared__ char smem[];
    uint32_t sb = smem_u32(smem);
    float* sEX = (float*)(smem + SM_EX);
    int tid = threadIdx.x;
    int wid = tid >> 5, lid = tid & 31;
    int m0 = blockIdx.x * 128;

    // ---- fill A tile fp16 ----
#pragma unroll
    for (int u = tid; u < 4096; u += 256) {
        int r = u >> 5, c = (u & 31) << 2;
        float4 v = *(const float4*)(A + (size_t)(m0 + r) * 128 + c);
        __half2 h01 = __floats2half2_rn(v.x, v.y);
        __half2 h23 = __floats2half2_rn(v.z, v.w);
        uint32_t off = r * APITCH_B + c * 2;
        *(uint2*)(smem + SM_AH + off) = make_uint2(*(uint32_t*)&h01, *(uint32_t*)&h23);
    }
    __syncthreads();

    int wm = wid >> 1, wn = wid & 1;         // warp tile: rows wm*32..+32, cols wn*32 of 64-wide nt
    int lr = lid & 15, lc = lid >> 4;
    int q  = lid >> 2, lq = lid & 3;

    // 4 rows per lane: local rows wm*32 + {q, q+8, q+16, q+24}
    int lrow[4];
    lrow[0] = wm * 32 + q;  lrow[1] = lrow[0] + 8;
    lrow[2] = lrow[0] + 16; lrow[3] = lrow[0] + 24;
    int ss[4], dd[4];
#pragma unroll
    for (int i = 0; i < 4; i++) {
        int e = m0 + lrow[i];
        ss[i] = EI[e]; dd[i] = EI[N_EDGES + e];
    }

    for (int nt = 0; nt < 6; nt++) {
        float acc[2][4][4];
#pragma unroll
        for (int mf = 0; mf < 2; mf++)
#pragma unroll
            for (int f = 0; f < 4; f++)
#pragma unroll
                for (int j = 0; j < 4; j++) acc[mf][f][j] = 0.f;

        const uint4* bp = g_WEf + (size_t)(nt * 8 + wn * 4) * 256 + lid;
#pragma unroll
        for (int ks = 0; ks < 8; ks++) {
            uint32_t a0[4], a1[4];
            uint32_t aoff = (uint32_t)((wm * 32 + lr) * APITCH_B + (ks * 16 + lc * 8) * 2);
            LDSM_X4(a0[0], a0[1], a0[2], a0[3], sb + SM_AH + aoff);
            LDSM_X4(a1[0], a1[1], a1[2], a1[3], sb + SM_AH + aoff + 16 * APITCH_B);
            uint4 bv0 = bp[0 * 256 + ks * 32];
            uint4 bv1 = bp[1 * 256 + ks * 32];
            uint4 bv2 = bp[2 * 256 + ks * 32];
            uint4 bv3 = bp[3 * 256 + ks * 32];
            MMA_F16(acc[0][0], a0, bv0.x, bv0.y);
            MMA_F16(acc[0][0], a0, bv0.z, bv0.w);
            MMA_F16(acc[0][1], a0, bv1.x, bv1.y);
            MMA_F16(acc[0][1], a0, bv1.z, bv1.w);
            MMA_F16(acc[0][2], a0, bv2.x, bv2.y);
            MMA_F16(acc[0][2], a0, bv2.z, bv2.w);
            MMA_F16(acc[0][3], a0, bv3.x, bv3.y);
            MMA_F16(acc[0][3], a0, bv3.z, bv3.w);
            MMA_F16(acc[1][0], a1, bv0.x, bv0.y);
            MMA_F16(acc[1][0], a1, bv0.z, bv0.w);
            MMA_F16(acc[1][1], a1, bv1.x, bv1.y);
            MMA_F16(acc[1][1], a1, bv1.z, bv1.w);
            MMA_F16(acc[1][2], a1, bv2.x, bv2.y);
            MMA_F16(acc[1][2], a1, bv2.z, bv2.w);
            MMA_F16(acc[1][3], a1, bv3.x, bv3.y);
            MMA_F16(acc[1][3], a1, bv3.z, bv3.w);
        }

        int cg = nt * 64 + wn * 32 + lq * 8;
        if (nt < 4) {
            int head = nt * 2 + wn;
            float4 b0  = *(const float4*)(g_bE + cg);
            float4 b1  = *(const float4*)(g_bE + cg + 4);
            float4 ap0 = *(const float4*)(AP + head * 32 + lq * 8);
            float4 ap1 = *(const float4*)(AP + head * 32 + lq * 8 + 4);
#pragma unroll
            for (int mf = 0; mf < 2; mf++) {
                float p0, p1;
                {
                    float2 e[4];
                    e[0] = make_float2(acc[mf][0][0], acc[mf][0][1]);
                    e[1] = make_float2(acc[mf][1][0], acc[mf][1][1]);
                    e[2] = make_float2(acc[mf][2][0], acc[mf][2][1]);
                    e[3] = make_float2(acc[mf][3][0], acc[mf][3][1]);
                    quad_transpose(e, lid);
                    const float* ni = g_node_tbl + (size_t)ss[2 * mf] * 640 + cg;
                    const float* nj = g_node_tbl + (size_t)dd[2 * mf] * 640 + 256 + cg;
                    float4 i0 = *(const float4*)ni, i1 = *(const float4*)(ni + 4);
                    float4 j0 = *(const float4*)nj, j1 = *(const float4*)(nj + 4);
                    float h; p0 = 0.f;
                    h = e[0].x + b0.x + i0.x + j0.x; h = (h >= 0.f) ? h : NEG_SLOPE * h; p0 += h * ap0.x;
                    h = e[0].y + b0.y + i0.y + j0.y; h = (h >= 0.f) ? h : NEG_SLOPE * h; p0 += h * ap0.y;
                    h = e[1].x + b0.z + i0.z + j0.z; h = (h >= 0.f) ? h : NEG_SLOPE * h; p0 += h * ap0.z;
                    h = e[1].y + b0.w + i0.w + j0.w; h = (h >= 0.f) ? h : NEG_SLOPE * h; p0 += h * ap0.w;
                    h = e[2].x + b1.x + i1.x + j1.x; h = (h >= 0.f) ? h : NEG_SLOPE * h; p0 += h * ap1.x;
                    h = e[2].y + b1.y + i1.y + j1.y; h = (h >= 0.f) ? h : NEG_SLOPE * h; p0 += h * ap1.y;
                    h = e[3].x + b1.z + i1.z + j1.z; h = (h >= 0.f) ? h : NEG_SLOPE * h; p0 += h * ap1.z;
                    h = e[3].y + b1.w + i1.w + j1.w; h = (h >= 0.f) ? h : NEG_SLOPE * h; p0 += h * ap1.w;
                }
                {
                    float2 e[4];
                    e[0] = make_float2(acc[mf][0][2], acc[mf][0][3]);
                    e[1] = make_float2(acc[mf][1][2], acc[mf][1][3]);
                    e[2] = make_float2(acc[mf][2][2], acc[mf][2][3]);
                    e[3] = make_float2(acc[mf][3][2], acc[mf][3][3]);
                    quad_transpose(e, lid);
                    const float* ni = g_node_tbl + (size_t)ss[2 * mf + 1] * 640 + cg;
                    const float* nj = g_node_tbl + (size_t)dd[2 * mf + 1] * 640 + 256 + cg;
                    float4 i0 = *(const float4*)ni, i1 = *(const float4*)(ni + 4);
                    float4 j0 = *(const float4*)nj, j1 = *(const float4*)(nj + 4);
                    float h; p1 = 0.f;
                    h = e[0].x + b0.x + i0.x + j0.x; h = (h >= 0.f) ? h : NEG_SLOPE * h; p1 += h * ap0.x;
                    h = e[0].y + b0.y + i0.y + j0.y; h = (h >= 0.f) ? h : NEG_SLOPE * h; p1 += h * ap0.y;
                    h = e[1].x + b0.z + i0.z + j0.z; h = (h >= 0.f) ? h : NEG_SLOPE * h; p1 += h * ap0.z;
                    h = e[1].y + b0.w + i0.w + j0.w; h = (h >= 0.f) ? h : NEG_SLOPE * h; p1 += h * ap0.w;
                    h = e[2].x + b1.x + i1.x + j1.x; h = (h >= 0.f) ? h : NEG_SLOPE * h; p1 += h * ap1.x;
                    h = e[2].y + b1.y + i1.y + j1.y; h = (h >= 0.f) ? h : NEG_SLOPE * h; p1 += h * ap1.y;
                    h = e[3].x + b1.z + i1.z + j1.z; h = (h >= 0.f) ? h : NEG_SLOPE * h; p1 += h * ap1.z;
                    h = e[3].y + b1.w + i1.w + j1.w; h = (h >= 0.f) ? h : NEG_SLOPE * h; p1 += h * ap1.w;
                }
                p0 += __shfl_xor_sync(0xffffffffu, p0, 1);
                p0 += __shfl_xor_sync(0xffffffffu, p0, 2);
                p1 += __shfl_xor_sync(0xffffffffu, p1, 1);
                p1 += __shfl_xor_sync(0xffffffffu, p1, 2);
                if (lq == 0) {
                    float e0 = expf(p0), e1 = expf(p1);
                    sEX[lrow[2 * mf] * 8 + head]     = e0;
                    sEX[lrow[2 * mf + 1] * 8 + head] = e1;
                    atomicAdd(&g_node_sum[ss[2 * mf] * 8 + head], e0);
                    atomicAdd(&g_node_sum[ss[2 * mf + 1] * 8 + head], e1);
                }
            }
            if (nt == 3) __syncthreads();   // publish sEX before message phase
        } else {
            int cm = (nt - 4) * 64 + wn * 32 + lq * 8;
            int head = cm >> 4;
            float4 b0 = *(const float4*)(g_bE + 256 + cm);
            float4 b1 = *(const float4*)(g_bE + 256 + cm + 4);
#pragma unroll
            for (int mf = 0; mf < 2; mf++) {
#pragma unroll
                for (int hh = 0; hh < 2; hh++) {
                    int ri = 2 * mf + hh;
                    float2 e[4];
                    e[0] = make_float2(acc[mf][0][2 * hh], acc[mf][0][2 * hh + 1]);
                    e[1] = make_float2(acc[mf][1][2 * hh], acc[mf][1][2 * hh + 1]);
                    e[2] = make_float2(acc[mf][2][2 * hh], acc[mf][2][2 * hh + 1]);
                    e[3] = make_float2(acc[mf][3][2 * hh], acc[mf][3][2 * hh + 1]);
                    quad_transpose(e, lid);
                    float ex = sEX[lrow[ri] * 8 + head];
                    const float* nm = g_node_tbl + (size_t)dd[ri] * 640 + 512 + cm;
                    float4 n0 = *(const float4*)nm, n1 = *(const float4*)(nm + 4);
                    float* dst = g_agg + (size_t)ss[ri] * 128 + cm;
                    asm volatile("red.global.add.v4.f32 [%0], {%1,%2,%3,%4};"
                                 :: "l"(dst),
                                    "f"((e[0].x + b0.x + n0.x) * ex), "f"((e[0].y + b0.y + n0.y) * ex),
                                    "f"((e[1].x + b0.z + n0.z) * ex), "f"((e[1].y + b0.w + n0.w) * ex) : "memory");
                    asm volatile("red.global.add.v4.f32 [%0], {%1,%2,%3,%4};"
                                 :: "l"(dst + 4),
                                    "f"((e[2].x + b1.x + n1.x) * ex), "f"((e[2].y + b1.y + n1.y) * ex),
                                    "f"((e[3].x + b1.z + n1.z) * ex), "f"((e[3].y + b1.w + n1.w) * ex) : "memory");
                }
            }
        }
    }
}

// ---------------- output GEMM with softmax normalization folded into A load ----------------
__global__ void out_gemm_kernel(const float* __restrict__ A, const float* __restrict__ B,
                                const float* __restrict__ bias, const float* __restrict__ sums,
                                float* __restrict__ C, int M) {
    __shared__ float As[16][64];
    __shared__ float Bs[16][64];
    int tid = threadIdx.x;
    int rt = tid >> 4, ct = tid & 15;
    int m0 = blockIdx.x * 64, n0 = blockIdx.y * 64;
    float acc[4][4] = {};
    int arow = tid >> 2, aq = tid & 3;
    int bk = tid >> 4, bq = tid & 15;
    for (int k0 = 0; k0 < 128; k0 += 16) {
        float4 av = make_float4(0.f, 0.f, 0.f, 0.f);
        int m = m0 + arow;
        if (m < M) {
            av = *(const float4*)(A + (size_t)m * 128 + k0 + aq * 4);
            float s = sums[m * 8 + (k0 >> 4)];
            float inv = 1.0f / s;
            av.x *= inv; av.y *= inv; av.z *= inv; av.w *= inv;
        }
        As[aq * 4 + 0][arow] = av.x; As[aq * 4 + 1][arow] = av.y;
        As[aq * 4 + 2][arow] = av.z; As[aq * 4 + 3][arow] = av.w;
        float4 bv = *(const float4*)(B + (size_t)(k0 + bk) * 128 + n0 + bq * 4);
        *(float4*)&Bs[bk][bq * 4] = bv;
        __syncthreads();
#pragma unroll
        for (int kk = 0; kk < 16; kk++) {
            float a[4], b[4];
            *(float4*)a = *(float4*)&As[kk][rt * 4];
            *(float4*)b = *(float4*)&Bs[kk][ct * 4];
#pragma unroll
            for (int i = 0; i < 4; i++)
#pragma unroll
                for (int j = 0; j < 4; j++)
                    acc[i][j] += a[i] * b[j];
        }
        __syncthreads();
    }
#pragma unroll
    for (int i = 0; i < 4; i++) {
        int m = m0 + rt * 4 + i;
        if (m < M) {
            int n = n0 + ct * 4;
            float4 o;
            o.x = acc[i][0] + bias[n + 0];
            o.y = acc[i][1] + bias[n + 1];
            o.z = acc[i][2] + bias[n + 2];
            o.w = acc[i][3] + bias[n + 3];
            *(float4*)(C + (size_t)m * 128 + n) = o;
        }
    }
}

// ---------------- launch ----------------
extern "C" void kernel_launch(void* const* d_in, const int* in_sizes, int n_in,
                              void* d_out, int out_size) {
    const float* node_features = (const float*)d_in[0];
    const float* edge_features = (const float*)d_in[1];
    const int*   edge_index    = (const int*)d_in[2];
    const float* Wni = (const float*)d_in[3];
    const float* bni = (const float*)d_in[4];
    const float* Wnj = (const float*)d_in[5];
    const float* bnj = (const float*)d_in[6];
    const float* We  = (const float*)d_in[7];
    const float* be  = (const float*)d_in[8];
    const float* attn_proj = (const float*)d_in[9];
    const float* Wm  = (const float*)d_in[10];
    const float* bm  = (const float*)d_in[11];
    const float* Wo  = (const float*)d_in[12];
    const float* bo  = (const float*)d_in[13];
    float* out = (float*)d_out;

    float *pAgg, *pWO, *pSum;
    cudaGetSymbolAddress((void**)&pAgg, g_agg);
    cudaGetSymbolAddress((void**)&pWO,  g_WO);
    cudaGetSymbolAddress((void**)&pSum, g_node_sum);

    static bool attr_set = false;
    if (!attr_set) {
        cudaFuncSetAttribute(node_kernel, cudaFuncAttributeMaxDynamicSharedMemorySize, SMEM_NODE);
        cudaFuncSetAttribute(edge_kernel, cudaFuncAttributeMaxDynamicSharedMemorySize, SMEM_EDGE);
        attr_set = true;
    }

    const int ZTOT = N_NODES * NUM_HEADS + N_NODES * 128;
    zero_kernel<<<(ZTOT + 255) / 256, 256>>>();
    prepack_kernel<<<(81920 + 255) / 256, 256>>>(Wni, bni, Wnj, bnj, be, Wm, bm, Wo);
    prepack2_kernel<<<(80 * 8 * 32 + 255) / 256, 256>>>(We, Wm);

    // node tables: 157 M-tiles x 2 halves, 5 N-tiles each (3-term bf16)
    node_kernel<<<dim3((N_NODES + 127) / 128, 2), 512, SMEM_NODE>>>(
        node_features, N_NODES, 5);

    // edge pass: 2500 M-tiles, 256 threads, warp 32x32, 6 N-tiles
    edge_kernel<<<N_EDGES / 128, 256, SMEM_EDGE>>>(
        edge_features, edge_index, attn_proj);

    // output projection with softmax normalization folded in
    out_gemm_kernel<<<dim3((N_NODES + 63) / 64, 2), 256>>>(pAgg, pWO, bo, pSum, out, N_NODES);
}

// round 15
// speedup vs baseline: 2.5182x; 1.3005x over previous
#include <cuda_runtime.h>
#include <cuda_bf16.h>
#include <cuda_fp16.h>
#include <cstdint>

#define N_NODES   20000
#define N_EDGES   320000
#define NUM_HEADS 8
#define NEG_SLOPE 0.2f

// ---------------- device scratch ----------------
__device__ __half g_node_tbl[N_NODES * 640];  // fp16 table: [0:256) ni_h, [256:512) nj_h, [512:640) msg part
__device__ float g_node_sum[N_NODES * NUM_HEADS];
__device__ float g_agg[N_NODES * 128];        // UNNORMALIZED sum of ex*msg
// fragment-major B (fp16 hi/lo): (cf*8 + ks)*32 + lane -> {b0_hi, b1_hi, b0_lo, b1_lo}
__device__ uint4 g_WNf[80 * 8 * 32];
__device__ uint4 g_WEf[48 * 8 * 32];
__device__ float g_bN[640];
__device__ float g_bE[384];
__device__ float g_WO[128 * 128];

// ---------------- helpers ----------------
__device__ __forceinline__ uint32_t smem_u32(const void* p) {
    uint32_t a;
    asm("{ .reg .u64 t; cvta.to.shared.u64 t, %1; cvt.u32.u64 %0, t; }" : "=r"(a) : "l"(p));
    return a;
}

#define LDSM_X4(r0, r1, r2, r3, addr) \
    asm volatile("ldmatrix.sync.aligned.m8n8.x4.shared.b16 {%0,%1,%2,%3}, [%4];" \
                 : "=r"(r0), "=r"(r1), "=r"(r2), "=r"(r3) : "r"(addr))

#define MMA_F16(c, a, b0, b1) \
    asm volatile("mma.sync.aligned.m16n8k16.row.col.f32.f16.f16.f32 " \
                 "{%0,%1,%2,%3}, {%4,%5,%6,%7}, {%8,%9}, {%0,%1,%2,%3};" \
                 : "+f"((c)[0]), "+f"((c)[1]), "+f"((c)[2]), "+f"((c)[3]) \
                 : "r"((a)[0]), "r"((a)[1]), "r"((a)[2]), "r"((a)[3]), \
                   "r"(b0), "r"(b1))

__device__ __forceinline__ void quad_transpose(float2 e[4], int lid) {
    {
        bool hi = (lid & 2);
        float2 s0 = hi ? e[0] : e[2];
        float2 s1 = hi ? e[1] : e[3];
        s0.x = __shfl_xor_sync(0xffffffffu, s0.x, 2);
        s0.y = __shfl_xor_sync(0xffffffffu, s0.y, 2);
        s1.x = __shfl_xor_sync(0xffffffffu, s1.x, 2);
        s1.y = __shfl_xor_sync(0xffffffffu, s1.y, 2);
        if (hi) { e[0] = s0; e[1] = s1; } else { e[2] = s0; e[3] = s1; }
    }
    {
        bool od = (lid & 1);
        float2 s0 = od ? e[0] : e[1];
        float2 s1 = od ? e[2] : e[3];
        s0.x = __shfl_xor_sync(0xffffffffu, s0.x, 1);
        s0.y = __shfl_xor_sync(0xffffffffu, s0.y, 1);
        s1.x = __shfl_xor_sync(0xffffffffu, s1.x, 1);
        s1.y = __shfl_xor_sync(0xffffffffu, s1.y, 1);
        if (od) { e[0] = s0; e[2] = s1; } else { e[1] = s0; e[3] = s1; }
    }
}

// load 8 fp16 -> two float4
__device__ __forceinline__ void ld_h8(const __half* p, float4& a, float4& b) {
    uint4 v = *(const uint4*)p;
    float2 f0 = __half22float2(*(__half2*)&v.x);
    float2 f1 = __half22float2(*(__half2*)&v.y);
    float2 f2 = __half22float2(*(__half2*)&v.z);
    float2 f3 = __half22float2(*(__half2*)&v.w);
    a = make_float4(f0.x, f0.y, f1.x, f1.y);
    b = make_float4(f2.x, f2.y, f3.x, f3.y);
}

#define APITCH_B 272
#define SM_AH 0
#define SM_EX 34816
#define SMEM_NODE 34816
#define SMEM_EDGE 38912

// ---------------- init kernels ----------------
__global__ void zero_kernel() {
    int i = blockIdx.x * blockDim.x + threadIdx.x;
    const int NS = N_NODES * NUM_HEADS;
    const int TOT = NS + N_NODES * 128;
    if (i < NS) g_node_sum[i] = 0.f;
    else if (i < TOT) g_agg[i - NS] = 0.f;
}

__global__ void prepack_kernel(const float* __restrict__ bni, const float* __restrict__ bnj,
                               const float* __restrict__ be,  const float* __restrict__ bm,
                               const float* __restrict__ Wo) {
    int i = blockIdx.x * blockDim.x + threadIdx.x;
    if (i < 640) g_bN[i] = (i < 256) ? bni[i] : (i < 512 ? bnj[i - 256] : 0.f);
    if (i < 384) g_bE[i] = (i < 256) ? be[i] : bm[i - 256];
    if (i < 16384) {
        int k = i >> 7, n = i & 127;
        g_WO[i] = Wo[n * 128 + k];
    }
}

// build fragment-major fp16 hi/lo tables directly from raw weights
__global__ void prepack2_kernel(const float* __restrict__ Wni, const float* __restrict__ Wnj,
                                const float* __restrict__ We,  const float* __restrict__ Wm) {
    int i = blockIdx.x * blockDim.x + threadIdx.x;
    int lane = i & 31;
    int ks   = (i >> 5) & 7;
    int cf   = i >> 8;
    int n  = (cf << 3) + (lane >> 2);
    int k0 = (ks << 4) + ((lane & 3) << 1);

    if (i < 80 * 8 * 32) {     // WN: 640 logical rows
        const float* row;
        if (n < 256)      row = Wni + (size_t)n * 128;
        else if (n < 512) row = Wnj + (size_t)(n - 256) * 128;
        else              row = Wm + (size_t)(n - 512) * 256;          // node half
        float v0 = row[k0],     v1 = row[k0 + 1];
        float v2 = row[k0 + 8], v3 = row[k0 + 9];
        __half h0 = __float2half_rn(v0), h1 = __float2half_rn(v1);
        __half h2 = __float2half_rn(v2), h3 = __float2half_rn(v3);
        __half l0 = __float2half_rn(v0 - __half2float(h0));
        __half l1 = __float2half_rn(v1 - __half2float(h1));
        __half l2 = __float2half_rn(v2 - __half2float(h2));
        __half l3 = __float2half_rn(v3 - __half2float(h3));
        __half2 b0h = __halves2half2(h0, h1), b1h = __halves2half2(h2, h3);
        __half2 b0l = __halves2half2(l0, l1), b1l = __halves2half2(l2, l3);
        g_WNf[i] = make_uint4(*(uint32_t*)&b0h, *(uint32_t*)&b1h,
                              *(uint32_t*)&b0l, *(uint32_t*)&b1l);
    }
    if (i < 48 * 8 * 32) {     // WE: 384 logical rows
        const float* row = (n < 256) ? (We + (size_t)n * 128)
                                     : (Wm + (size_t)(n - 256) * 256 + 128);
        float v0 = row[k0],     v1 = row[k0 + 1];
        float v2 = row[k0 + 8], v3 = row[k0 + 9];
        __half h0 = __float2half_rn(v0), h1 = __float2half_rn(v1);
        __half h2 = __float2half_rn(v2), h3 = __float2half_rn(v3);
        __half l0 = __float2half_rn(v0 - __half2float(h0));
        __half l1 = __float2half_rn(v1 - __half2float(h1));
        __half l2 = __float2half_rn(v2 - __half2float(h2));
        __half l3 = __float2half_rn(v3 - __half2float(h3));
        __half2 b0h = __halves2half2(h0, h1), b1h = __halves2half2(h2, h3);
        __half2 b0l = __halves2half2(l0, l1), b1l = __halves2half2(l2, l3);
        g_WEf[i] = make_uint4(*(uint32_t*)&b0h, *(uint32_t*)&b1h,
                              *(uint32_t*)&b0l, *(uint32_t*)&b1l);
    }
}

// ---------------- node kernel: 256 threads, 2-term fp16, warp 32x32, fp16 table out ----
__global__ void __launch_bounds__(256, 3) node_kernel(
    const float* __restrict__ A, int M, int NB) {
    extern __shared__ char smem[];
    uint32_t sb = smem_u32(smem);
    int tid = threadIdx.x;
    int wid = tid >> 5, lid = tid & 31;
    int m0 = blockIdx.x * 128;
    int nt0 = blockIdx.y * NB;

#pragma unroll
    for (int u = tid; u < 4096; u += 256) {
        int r = u >> 5, c = (u & 31) << 2;
        int row = m0 + r;
        float4 v = make_float4(0.f, 0.f, 0.f, 0.f);
        if (row < M) v = *(const float4*)(A + (size_t)row * 128 + c);
        __half2 h01 = __floats2half2_rn(v.x, v.y);
        __half2 h23 = __floats2half2_rn(v.z, v.w);
        uint32_t off = r * APITCH_B + c * 2;
        *(uint2*)(smem + SM_AH + off) = make_uint2(*(uint32_t*)&h01, *(uint32_t*)&h23);
    }
    __syncthreads();

    int wm = wid >> 1, wn = wid & 1;
    int lr = lid & 15, lc = lid >> 4;
    int q  = lid >> 2, lq = lid & 3;

    int lrow[4];
    lrow[0] = wm * 32 + q;  lrow[1] = lrow[0] + 8;
    lrow[2] = lrow[0] + 16; lrow[3] = lrow[0] + 24;

    for (int ntl = 0; ntl < NB; ntl++) {
        int nt = nt0 + ntl;
        float acc[2][4][4];
#pragma unroll
        for (int mf = 0; mf < 2; mf++)
#pragma unroll
            for (int f = 0; f < 4; f++)
#pragma unroll
                for (int j = 0; j < 4; j++) acc[mf][f][j] = 0.f;

        const uint4* bp = g_WNf + (size_t)(nt * 8 + wn * 4) * 256 + lid;
#pragma unroll
        for (int ks = 0; ks < 8; ks++) {
            uint32_t a0[4], a1[4];
            uint32_t aoff = (uint32_t)((wm * 32 + lr) * APITCH_B + (ks * 16 + lc * 8) * 2);
            LDSM_X4(a0[0], a0[1], a0[2], a0[3], sb + SM_AH + aoff);
            LDSM_X4(a1[0], a1[1], a1[2], a1[3], sb + SM_AH + aoff + 16 * APITCH_B);
            uint4 bv0 = bp[0 * 256 + ks * 32];
            uint4 bv1 = bp[1 * 256 + ks * 32];
            uint4 bv2 = bp[2 * 256 + ks * 32];
            uint4 bv3 = bp[3 * 256 + ks * 32];
            MMA_F16(acc[0][0], a0, bv0.x, bv0.y);
            MMA_F16(acc[0][0], a0, bv0.z, bv0.w);
            MMA_F16(acc[0][1], a0, bv1.x, bv1.y);
            MMA_F16(acc[0][1], a0, bv1.z, bv1.w);
            MMA_F16(acc[0][2], a0, bv2.x, bv2.y);
            MMA_F16(acc[0][2], a0, bv2.z, bv2.w);
            MMA_F16(acc[0][3], a0, bv3.x, bv3.y);
            MMA_F16(acc[0][3], a0, bv3.z, bv3.w);
            MMA_F16(acc[1][0], a1, bv0.x, bv0.y);
            MMA_F16(acc[1][0], a1, bv0.z, bv0.w);
            MMA_F16(acc[1][1], a1, bv1.x, bv1.y);
            MMA_F16(acc[1][1], a1, bv1.z, bv1.w);
            MMA_F16(acc[1][2], a1, bv2.x, bv2.y);
            MMA_F16(acc[1][2], a1, bv2.z, bv2.w);
            MMA_F16(acc[1][3], a1, bv3.x, bv3.y);
            MMA_F16(acc[1][3], a1, bv3.z, bv3.w);
        }

        int cg = nt * 64 + wn * 32 + lq * 8;
        float4 b0 = *(const float4*)(g_bN + cg);
        float4 b1 = *(const float4*)(g_bN + cg + 4);
#pragma unroll
        for (int mf = 0; mf < 2; mf++) {
#pragma unroll
            for (int hh = 0; hh < 2; hh++) {
                int ri = 2 * mf + hh;
                float2 e[4];
                e[0] = make_float2(acc[mf][0][2 * hh], acc[mf][0][2 * hh + 1]);
                e[1] = make_float2(acc[mf][1][2 * hh], acc[mf][1][2 * hh + 1]);
                e[2] = make_float2(acc[mf][2][2 * hh], acc[mf][2][2 * hh + 1]);
                e[3] = make_float2(acc[mf][3][2 * hh], acc[mf][3][2 * hh + 1]);
                quad_transpose(e, lid);
                int row = m0 + lrow[ri];
                if (row < M) {
                    __half2 p0 = __floats2half2_rn(e[0].x + b0.x, e[0].y + b0.y);
                    __half2 p1 = __floats2half2_rn(e[1].x + b0.z, e[1].y + b0.w);
                    __half2 p2 = __floats2half2_rn(e[2].x + b1.x, e[2].y + b1.y);
                    __half2 p3 = __floats2half2_rn(e[3].x + b1.z, e[3].y + b1.w);
                    *(uint4*)(g_node_tbl + (size_t)row * 640 + cg) =
                        make_uint4(*(uint32_t*)&p0, *(uint32_t*)&p1,
                                   *(uint32_t*)&p2, *(uint32_t*)&p3);
                }
            }
        }
    }
}

// ---------------- edge kernel: 256 threads, 2-term fp16, warp 32x32, fp16 gathers ----
__global__ void __launch_bounds__(256, 3) edge_kernel(
    const float* __restrict__ A, const int* __restrict__ EI, const float* __restrict__ AP) {
    extern __shared__ char smem[];
    uint32_t sb = smem_u32(smem);
    float* sEX = (float*)(smem + SM_EX);
    int tid = threadIdx.x;
    int wid = tid >> 5, lid = tid & 31;
    int m0 = blockIdx.x * 128;

#pragma unroll
    for (int u = tid; u < 4096; u += 256) {
        int r = u >> 5, c = (u & 31) << 2;
        float4 v = *(const float4*)(A + (size_t)(m0 + r) * 128 + c);
        __half2 h01 = __floats2half2_rn(v.x, v.y);
        __half2 h23 = __floats2half2_rn(v.z, v.w);
        uint32_t off = r * APITCH_B + c * 2;
        *(uint2*)(smem + SM_AH + off) = make_uint2(*(uint32_t*)&h01, *(uint32_t*)&h23);
    }
    __syncthreads();

    int wm = wid >> 1, wn = wid & 1;
    int lr = lid & 15, lc = lid >> 4;
    int q  = lid >> 2, lq = lid & 3;

    int lrow[4];
    lrow[0] = wm * 32 + q;  lrow[1] = lrow[0] + 8;
    lrow[2] = lrow[0] + 16; lrow[3] = lrow[0] + 24;
    int ss[4], dd[4];
#pragma unroll
    for (int i = 0; i < 4; i++) {
        int e = m0 + lrow[i];
        ss[i] = EI[e]; dd[i] = EI[N_EDGES + e];
    }

    for (int nt = 0; nt < 6; nt++) {
        float acc[2][4][4];
#pragma unroll
        for (int mf = 0; mf < 2; mf++)
#pragma unroll
            for (int f = 0; f < 4; f++)
#pragma unroll
                for (int j = 0; j < 4; j++) acc[mf][f][j] = 0.f;

        const uint4* bp = g_WEf + (size_t)(nt * 8 + wn * 4) * 256 + lid;
#pragma unroll
        for (int ks = 0; ks < 8; ks++) {
            uint32_t a0[4], a1[4];
            uint32_t aoff = (uint32_t)((wm * 32 + lr) * APITCH_B + (ks * 16 + lc * 8) * 2);
            LDSM_X4(a0[0], a0[1], a0[2], a0[3], sb + SM_AH + aoff);
            LDSM_X4(a1[0], a1[1], a1[2], a1[3], sb + SM_AH + aoff + 16 * APITCH_B);
            uint4 bv0 = bp[0 * 256 + ks * 32];
            uint4 bv1 = bp[1 * 256 + ks * 32];
            uint4 bv2 = bp[2 * 256 + ks * 32];
            uint4 bv3 = bp[3 * 256 + ks * 32];
            MMA_F16(acc[0][0], a0, bv0.x, bv0.y);
            MMA_F16(acc[0][0], a0, bv0.z, bv0.w);
            MMA_F16(acc[0][1], a0, bv1.x, bv1.y);
            MMA_F16(acc[0][1], a0, bv1.z, bv1.w);
            MMA_F16(acc[0][2], a0, bv2.x, bv2.y);
            MMA_F16(acc[0][2], a0, bv2.z, bv2.w);
            MMA_F16(acc[0][3], a0, bv3.x, bv3.y);
            MMA_F16(acc[0][3], a0, bv3.z, bv3.w);
            MMA_F16(acc[1][0], a1, bv0.x, bv0.y);
            MMA_F16(acc[1][0], a1, bv0.z, bv0.w);
            MMA_F16(acc[1][1], a1, bv1.x, bv1.y);
            MMA_F16(acc[1][1], a1, bv1.z, bv1.w);
            MMA_F16(acc[1][2], a1, bv2.x, bv2.y);
            MMA_F16(acc[1][2], a1, bv2.z, bv2.w);
            MMA_F16(acc[1][3], a1, bv3.x, bv3.y);
            MMA_F16(acc[1][3], a1, bv3.z, bv3.w);
        }

        int cg = nt * 64 + wn * 32 + lq * 8;
        if (nt < 4) {
            int head = nt * 2 + wn;
            float4 b0  = *(const float4*)(g_bE + cg);
            float4 b1  = *(const float4*)(g_bE + cg + 4);
            float4 ap0 = *(const float4*)(AP + head * 32 + lq * 8);
            float4 ap1 = *(const float4*)(AP + head * 32 + lq * 8 + 4);
#pragma unroll
            for (int mf = 0; mf < 2; mf++) {
                float p0, p1;
                {
                    float2 e[4];
                    e[0] = make_float2(acc[mf][0][0], acc[mf][0][1]);
                    e[1] = make_float2(acc[mf][1][0], acc[mf][1][1]);
                    e[2] = make_float2(acc[mf][2][0], acc[mf][2][1]);
                    e[3] = make_float2(acc[mf][3][0], acc[mf][3][1]);
                    quad_transpose(e, lid);
                    float4 i0, i1, j0, j1;
                    ld_h8(g_node_tbl + (size_t)ss[2 * mf] * 640 + cg, i0, i1);
                    ld_h8(g_node_tbl + (size_t)dd[2 * mf] * 640 + 256 + cg, j0, j1);
                    float h; p0 = 0.f;
                    h = e[0].x + b0.x + i0.x + j0.x; h = (h >= 0.f) ? h : NEG_SLOPE * h; p0 += h * ap0.x;
                    h = e[0].y + b0.y + i0.y + j0.y; h = (h >= 0.f) ? h : NEG_SLOPE * h; p0 += h * ap0.y;
                    h = e[1].x + b0.z + i0.z + j0.z; h = (h >= 0.f) ? h : NEG_SLOPE * h; p0 += h * ap0.z;
                    h = e[1].y + b0.w + i0.w + j0.w; h = (h >= 0.f) ? h : NEG_SLOPE * h; p0 += h * ap0.w;
                    h = e[2].x + b1.x + i1.x + j1.x; h = (h >= 0.f) ? h : NEG_SLOPE * h; p0 += h * ap1.x;
                    h = e[2].y + b1.y + i1.y + j1.y; h = (h >= 0.f) ? h : NEG_SLOPE * h; p0 += h * ap1.y;
                    h = e[3].x + b1.z + i1.z + j1.z; h = (h >= 0.f) ? h : NEG_SLOPE * h; p0 += h * ap1.z;
                    h = e[3].y + b1.w + i1.w + j1.w; h = (h >= 0.f) ? h : NEG_SLOPE * h; p0 += h * ap1.w;
                }
                {
                    float2 e[4];
                    e[0] = make_float2(acc[mf][0][2], acc[mf][0][3]);
                    e[1] = make_float2(acc[mf][1][2], acc[mf][1][3]);
                    e[2] = make_float2(acc[mf][2][2], acc[mf][2][3]);
                    e[3] = make_float2(acc[mf][3][2], acc[mf][3][3]);
                    quad_transpose(e, lid);
                    float4 i0, i1, j0, j1;
                    ld_h8(g_node_tbl + (size_t)ss[2 * mf + 1] * 640 + cg, i0, i1);
                    ld_h8(g_node_tbl + (size_t)dd[2 * mf + 1] * 640 + 256 + cg, j0, j1);
                    float h; p1 = 0.f;
                    h = e[0].x + b0.x + i0.x + j0.x; h = (h >= 0.f) ? h : NEG_SLOPE * h; p1 += h * ap0.x;
                    h = e[0].y + b0.y + i0.y + j0.y; h = (h >= 0.f) ? h : NEG_SLOPE * h; p1 += h * ap0.y;
                    h = e[1].x + b0.z + i0.z + j0.z; h = (h >= 0.f) ? h : NEG_SLOPE * h; p1 += h * ap0.z;
                    h = e[1].y + b0.w + i0.w + j0.w; h = (h >= 0.f) ? h : NEG_SLOPE * h; p1 += h * ap0.w;
                    h = e[2].x + b1.x + i1.x + j1.x; h = (h >= 0.f) ? h : NEG_SLOPE * h; p1 += h * ap1.x;
                    h = e[2].y + b1.y + i1.y + j1.y; h = (h >= 0.f) ? h : NEG_SLOPE * h; p1 += h * ap1.y;
                    h = e[3].x + b1.z + i1.z + j1.z; h = (h >= 0.f) ? h : NEG_SLOPE * h; p1 += h * ap1.z;
                    h = e[3].y + b1.w + i1.w + j1.w; h = (h >= 0.f) ? h : NEG_SLOPE * h; p1 += h * ap1.w;
                }
                p0 += __shfl_xor_sync(0xffffffffu, p0, 1);
                p0 += __shfl_xor_sync(0xffffffffu, p0, 2);
                p1 += __shfl_xor_sync(0xffffffffu, p1, 1);
                p1 += __shfl_xor_sync(0xffffffffu, p1, 2);
                if (lq == 0) {
                    float e0 = expf(p0), e1 = expf(p1);
                    sEX[lrow[2 * mf] * 8 + head]     = e0;
                    sEX[lrow[2 * mf + 1] * 8 + head] = e1;
                    atomicAdd(&g_node_sum[ss[2 * mf] * 8 + head], e0);
                    atomicAdd(&g_node_sum[ss[2 * mf + 1] * 8 + head], e1);
                }
            }
            if (nt == 3) __syncthreads();   // publish sEX before message phase
        } else {
            int cm = (nt - 4) * 64 + wn * 32 + lq * 8;
            int head = cm >> 4;
            float4 b0 = *(const float4*)(g_bE + 256 + cm);
            float4 b1 = *(const float4*)(g_bE + 256 + cm + 4);
#pragma unroll
            for (int mf = 0; mf < 2; mf++) {
#pragma unroll
                for (int hh = 0; hh < 2; hh++) {
                    int ri = 2 * mf + hh;
                    float2 e[4];
                    e[0] = make_float2(acc[mf][0][2 * hh], acc[mf][0][2 * hh + 1]);
                    e[1] = make_float2(acc[mf][1][2 * hh], acc[mf][1][2 * hh + 1]);
                    e[2] = make_float2(acc[mf][2][2 * hh], acc[mf][2][2 * hh + 1]);
                    e[3] = make_float2(acc[mf][3][2 * hh], acc[mf][3][2 * hh + 1]);
                    quad_transpose(e, lid);
                    float ex = sEX[lrow[ri] * 8 + head];
                    float4 n0, n1;
                    ld_h8(g_node_tbl + (size_t)dd[ri] * 640 + 512 + cm, n0, n1);
                    float* dst = g_agg + (size_t)ss[ri] * 128 + cm;
                    asm volatile("red.global.add.v4.f32 [%0], {%1,%2,%3,%4};"
                                 :: "l"(dst),
                                    "f"((e[0].x + b0.x + n0.x) * ex), "f"((e[0].y + b0.y + n0.y) * ex),
                                    "f"((e[1].x + b0.z + n0.z) * ex), "f"((e[1].y + b0.w + n0.w) * ex) : "memory");
                    asm volatile("red.global.add.v4.f32 [%0], {%1,%2,%3,%4};"
                                 :: "l"(dst + 4),
                                    "f"((e[2].x + b1.x + n1.x) * ex), "f"((e[2].y + b1.y + n1.y) * ex),
                                    "f"((e[3].x + b1.z + n1.z) * ex), "f"((e[3].y + b1.w + n1.w) * ex) : "memory");
                }
            }
        }
    }
}

// ---------------- output GEMM with softmax normalization folded into A load ----------------
__global__ void out_gemm_kernel(const float* __restrict__ A, const float* __restrict__ B,
                                const float* __restrict__ bias, const float* __restrict__ sums,
                                float* __restrict__ C, int M) {
    __shared__ float As[16][64];
    __shared__ float Bs[16][64];
    int tid = threadIdx.x;
    int rt = tid >> 4, ct = tid & 15;
    int m0 = blockIdx.x * 64, n0 = blockIdx.y * 64;
    float acc[4][4] = {};
    int arow = tid >> 2, aq = tid & 3;
    int bk = tid >> 4, bq = tid & 15;
    for (int k0 = 0; k0 < 128; k0 += 16) {
        float4 av = make_float4(0.f, 0.f, 0.f, 0.f);
        int m = m0 + arow;
        if (m < M) {
            av = *(const float4*)(A + (size_t)m * 128 + k0 + aq * 4);
            float s = sums[m * 8 + (k0 >> 4)];
            float inv = 1.0f / s;
            av.x *= inv; av.y *= inv; av.z *= inv; av.w *= inv;
        }
        As[aq * 4 + 0][arow] = av.x; As[aq * 4 + 1][arow] = av.y;
        As[aq * 4 + 2][arow] = av.z; As[aq * 4 + 3][arow] = av.w;
        float4 bv = *(const float4*)(B + (size_t)(k0 + bk) * 128 + n0 + bq * 4);
        *(float4*)&Bs[bk][bq * 4] = bv;
        __syncthreads();
#pragma unroll
        for (int kk = 0; kk < 16; kk++) {
            float a[4], b[4];
            *(float4*)a = *(float4*)&As[kk][rt * 4];
            *(float4*)b = *(float4*)&Bs[kk][ct * 4];
#pragma unroll
            for (int i = 0; i < 4; i++)
#pragma unroll
                for (int j = 0; j < 4; j++)
                    acc[i][j] += a[i] * b[j];
        }
        __syncthreads();
    }
#pragma unroll
    for (int i = 0; i < 4; i++) {
        int m = m0 + rt * 4 + i;
        if (m < M) {
            int n = n0 + ct * 4;
            float4 o;
            o.x = acc[i][0] + bias[n + 0];
            o.y = acc[i][1] + bias[n + 1];
            o.z = acc[i][2] + bias[n + 2];
            o.w = acc[i][3] + bias[n + 3];
            *(float4*)(C + (size_t)m * 128 + n) = o;
        }
    }
}

// ---------------- launch ----------------
extern "C" void kernel_launch(void* const* d_in, const int* in_sizes, int n_in,
                              void* d_out, int out_size) {
    const float* node_features = (const float*)d_in[0];
    const float* edge_features = (const float*)d_in[1];
    const int*   edge_index    = (const int*)d_in[2];
    const float* Wni = (const float*)d_in[3];
    const float* bni = (const float*)d_in[4];
    const float* Wnj = (const float*)d_in[5];
    const float* bnj = (const float*)d_in[6];
    const float* We  = (const float*)d_in[7];
    const float* be  = (const float*)d_in[8];
    const float* attn_proj = (const float*)d_in[9];
    const float* Wm  = (const float*)d_in[10];
    const float* bm  = (const float*)d_in[11];
    const float* Wo  = (const float*)d_in[12];
    const float* bo  = (const float*)d_in[13];
    float* out = (float*)d_out;

    float *pAgg, *pWO, *pSum;
    cudaGetSymbolAddress((void**)&pAgg, g_agg);
    cudaGetSymbolAddress((void**)&pWO,  g_WO);
    cudaGetSymbolAddress((void**)&pSum, g_node_sum);

    static bool attr_set = false;
    if (!attr_set) {
        cudaFuncSetAttribute(node_kernel, cudaFuncAttributeMaxDynamicSharedMemorySize, SMEM_NODE);
        cudaFuncSetAttribute(edge_kernel, cudaFuncAttributeMaxDynamicSharedMemorySize, SMEM_EDGE);
        attr_set = true;
    }

    const int ZTOT = N_NODES * NUM_HEADS + N_NODES * 128;
    zero_kernel<<<(ZTOT + 255) / 256, 256>>>();
    prepack_kernel<<<(16384 + 255) / 256, 256>>>(bni, bnj, be, bm, Wo);
    prepack2_kernel<<<(80 * 8 * 32 + 255) / 256, 256>>>(Wni, Wnj, We, Wm);

    // node tables: 157 M-tiles x 2 halves, 5 N-tiles each (2-term fp16, fp16 table out)
    node_kernel<<<dim3((N_NODES + 127) / 128, 2), 256, SMEM_NODE>>>(
        node_features, N_NODES, 5);

    // edge pass: 2500 M-tiles, warp 32x32, 6 N-tiles, fp16 gathers
    edge_kernel<<<N_EDGES / 128, 256, SMEM_EDGE>>>(
        edge_features, edge_index, attn_proj);

    // output projection with softmax normalization folded in
    out_gemm_kernel<<<dim3((N_NODES + 63) / 64, 2), 256>>>(pAgg, pWO, bo, pSum, out, N_NODES);
}

// round 16
// speedup vs baseline: 3.0667x; 1.2178x over previous
#include <cuda_runtime.h>
#include <cuda_bf16.h>
#include <cuda_fp16.h>
#include <cstdint>

#define N_NODES   20000
#define N_EDGES   320000
#define NUM_HEADS 8
#define NEG_SLOPE 0.2f

// ---------------- device scratch ----------------
__device__ __half g_node_tbl[N_NODES * 640];  // fp16 table: [0:256) ni_h, [256:512) nj_h, [512:640) msg part
__device__ float g_node_sum[N_NODES * NUM_HEADS];
__device__ float g_agg[N_NODES * 128];        // UNNORMALIZED sum of ex*msg
// fragment-major B (fp16, 1-term): (cf*8 + ks)*32 + lane -> {b0, b1}
__device__ uint2 g_WNf[80 * 8 * 32];
__device__ uint2 g_WEf[48 * 8 * 32];
__device__ float g_bN[640];
__device__ float g_bE[384];
__device__ float g_WO[128 * 128];

// ---------------- helpers ----------------
__device__ __forceinline__ uint32_t smem_u32(const void* p) {
    uint32_t a;
    asm("{ .reg .u64 t; cvta.to.shared.u64 t, %1; cvt.u32.u64 %0, t; }" : "=r"(a) : "l"(p));
    return a;
}

#define LDSM_X4(r0, r1, r2, r3, addr) \
    asm volatile("ldmatrix.sync.aligned.m8n8.x4.shared.b16 {%0,%1,%2,%3}, [%4];" \
                 : "=r"(r0), "=r"(r1), "=r"(r2), "=r"(r3) : "r"(addr))

#define MMA_F16(c, a, b0, b1) \
    asm volatile("mma.sync.aligned.m16n8k16.row.col.f32.f16.f16.f32 " \
                 "{%0,%1,%2,%3}, {%4,%5,%6,%7}, {%8,%9}, {%0,%1,%2,%3};" \
                 : "+f"((c)[0]), "+f"((c)[1]), "+f"((c)[2]), "+f"((c)[3]) \
                 : "r"((a)[0]), "r"((a)[1]), "r"((a)[2]), "r"((a)[3]), \
                   "r"(b0), "r"(b1))

__device__ __forceinline__ void quad_transpose(float2 e[4], int lid) {
    {
        bool hi = (lid & 2);
        float2 s0 = hi ? e[0] : e[2];
        float2 s1 = hi ? e[1] : e[3];
        s0.x = __shfl_xor_sync(0xffffffffu, s0.x, 2);
        s0.y = __shfl_xor_sync(0xffffffffu, s0.y, 2);
        s1.x = __shfl_xor_sync(0xffffffffu, s1.x, 2);
        s1.y = __shfl_xor_sync(0xffffffffu, s1.y, 2);
        if (hi) { e[0] = s0; e[1] = s1; } else { e[2] = s0; e[3] = s1; }
    }
    {
        bool od = (lid & 1);
        float2 s0 = od ? e[0] : e[1];
        float2 s1 = od ? e[2] : e[3];
        s0.x = __shfl_xor_sync(0xffffffffu, s0.x, 1);
        s0.y = __shfl_xor_sync(0xffffffffu, s0.y, 1);
        s1.x = __shfl_xor_sync(0xffffffffu, s1.x, 1);
        s1.y = __shfl_xor_sync(0xffffffffu, s1.y, 1);
        if (od) { e[0] = s0; e[2] = s1; } else { e[1] = s0; e[3] = s1; }
    }
}

// load 8 fp16 -> two float4
__device__ __forceinline__ void ld_h8(const __half* p, float4& a, float4& b) {
    uint4 v = *(const uint4*)p;
    float2 f0 = __half22float2(*(__half2*)&v.x);
    float2 f1 = __half22float2(*(__half2*)&v.y);
    float2 f2 = __half22float2(*(__half2*)&v.z);
    float2 f3 = __half22float2(*(__half2*)&v.w);
    a = make_float4(f0.x, f0.y, f1.x, f1.y);
    b = make_float4(f2.x, f2.y, f3.x, f3.y);
}

#define APITCH_B 272
#define SM_AH 0
#define SM_EX 34816
#define SMEM_NODE 34816
#define SMEM_EDGE 38912

// ---------------- init kernels ----------------
__global__ void zero_kernel() {
    int i = blockIdx.x * blockDim.x + threadIdx.x;
    const int NS = N_NODES * NUM_HEADS;
    const int TOT = NS + N_NODES * 128;
    if (i < NS) g_node_sum[i] = 0.f;
    else if (i < TOT) g_agg[i - NS] = 0.f;
}

__global__ void prepack_kernel(const float* __restrict__ bni, const float* __restrict__ bnj,
                               const float* __restrict__ be,  const float* __restrict__ bm,
                               const float* __restrict__ Wo) {
    int i = blockIdx.x * blockDim.x + threadIdx.x;
    if (i < 640) g_bN[i] = (i < 256) ? bni[i] : (i < 512 ? bnj[i - 256] : 0.f);
    if (i < 384) g_bE[i] = (i < 256) ? be[i] : bm[i - 256];
    if (i < 16384) {
        int k = i >> 7, n = i & 127;
        g_WO[i] = Wo[n * 128 + k];
    }
}

// build fragment-major fp16 (1-term) tables directly from raw weights
__global__ void prepack2_kernel(const float* __restrict__ Wni, const float* __restrict__ Wnj,
                                const float* __restrict__ We,  const float* __restrict__ Wm) {
    int i = blockIdx.x * blockDim.x + threadIdx.x;
    int lane = i & 31;
    int ks   = (i >> 5) & 7;
    int cf   = i >> 8;
    int n  = (cf << 3) + (lane >> 2);
    int k0 = (ks << 4) + ((lane & 3) << 1);

    if (i < 80 * 8 * 32) {     // WN: 640 logical rows
        const float* row;
        if (n < 256)      row = Wni + (size_t)n * 128;
        else if (n < 512) row = Wnj + (size_t)(n - 256) * 128;
        else              row = Wm + (size_t)(n - 512) * 256;          // node half
        __half2 b0 = __floats2half2_rn(row[k0],     row[k0 + 1]);
        __half2 b1 = __floats2half2_rn(row[k0 + 8], row[k0 + 9]);
        g_WNf[i] = make_uint2(*(uint32_t*)&b0, *(uint32_t*)&b1);
    }
    if (i < 48 * 8 * 32) {     // WE: 384 logical rows
        const float* row = (n < 256) ? (We + (size_t)n * 128)
                                     : (Wm + (size_t)(n - 256) * 256 + 128);
        __half2 b0 = __floats2half2_rn(row[k0],     row[k0 + 1]);
        __half2 b1 = __floats2half2_rn(row[k0 + 8], row[k0 + 9]);
        g_WEf[i] = make_uint2(*(uint32_t*)&b0, *(uint32_t*)&b1);
    }
}

// ---------------- node kernel: 256 threads, 1-term fp16, warp 32x32, fp16 table out ----
__global__ void __launch_bounds__(256, 3) node_kernel(
    const float* __restrict__ A, int M, int NB) {
    extern __shared__ char smem[];
    uint32_t sb = smem_u32(smem);
    int tid = threadIdx.x;
    int wid = tid >> 5, lid = tid & 31;
    int m0 = blockIdx.x * 128;
    int nt0 = blockIdx.y * NB;

#pragma unroll
    for (int u = tid; u < 4096; u += 256) {
        int r = u >> 5, c = (u & 31) << 2;
        int row = m0 + r;
        float4 v = make_float4(0.f, 0.f, 0.f, 0.f);
        if (row < M) v = *(const float4*)(A + (size_t)row * 128 + c);
        __half2 h01 = __floats2half2_rn(v.x, v.y);
        __half2 h23 = __floats2half2_rn(v.z, v.w);
        uint32_t off = r * APITCH_B + c * 2;
        *(uint2*)(smem + SM_AH + off) = make_uint2(*(uint32_t*)&h01, *(uint32_t*)&h23);
    }
    __syncthreads();

    int wm = wid >> 1, wn = wid & 1;
    int lr = lid & 15, lc = lid >> 4;
    int q  = lid >> 2, lq = lid & 3;

    int lrow[4];
    lrow[0] = wm * 32 + q;  lrow[1] = lrow[0] + 8;
    lrow[2] = lrow[0] + 16; lrow[3] = lrow[0] + 24;

    for (int ntl = 0; ntl < NB; ntl++) {
        int nt = nt0 + ntl;
        float acc[2][4][4];
#pragma unroll
        for (int mf = 0; mf < 2; mf++)
#pragma unroll
            for (int f = 0; f < 4; f++)
#pragma unroll
                for (int j = 0; j < 4; j++) acc[mf][f][j] = 0.f;

        const uint2* bp = g_WNf + (size_t)(nt * 8 + wn * 4) * 256 + lid;
#pragma unroll
        for (int ks = 0; ks < 8; ks++) {
            uint32_t a0[4], a1[4];
            uint32_t aoff = (uint32_t)((wm * 32 + lr) * APITCH_B + (ks * 16 + lc * 8) * 2);
            LDSM_X4(a0[0], a0[1], a0[2], a0[3], sb + SM_AH + aoff);
            LDSM_X4(a1[0], a1[1], a1[2], a1[3], sb + SM_AH + aoff + 16 * APITCH_B);
            uint2 bv0 = bp[0 * 256 + ks * 32];
            uint2 bv1 = bp[1 * 256 + ks * 32];
            uint2 bv2 = bp[2 * 256 + ks * 32];
            uint2 bv3 = bp[3 * 256 + ks * 32];
            MMA_F16(acc[0][0], a0, bv0.x, bv0.y);
            MMA_F16(acc[0][1], a0, bv1.x, bv1.y);
            MMA_F16(acc[0][2], a0, bv2.x, bv2.y);
            MMA_F16(acc[0][3], a0, bv3.x, bv3.y);
            MMA_F16(acc[1][0], a1, bv0.x, bv0.y);
            MMA_F16(acc[1][1], a1, bv1.x, bv1.y);
            MMA_F16(acc[1][2], a1, bv2.x, bv2.y);
            MMA_F16(acc[1][3], a1, bv3.x, bv3.y);
        }

        int cg = nt * 64 + wn * 32 + lq * 8;
        float4 b0 = *(const float4*)(g_bN + cg);
        float4 b1 = *(const float4*)(g_bN + cg + 4);
#pragma unroll
        for (int mf = 0; mf < 2; mf++) {
#pragma unroll
            for (int hh = 0; hh < 2; hh++) {
                int ri = 2 * mf + hh;
                float2 e[4];
                e[0] = make_float2(acc[mf][0][2 * hh], acc[mf][0][2 * hh + 1]);
                e[1] = make_float2(acc[mf][1][2 * hh], acc[mf][1][2 * hh + 1]);
                e[2] = make_float2(acc[mf][2][2 * hh], acc[mf][2][2 * hh + 1]);
                e[3] = make_float2(acc[mf][3][2 * hh], acc[mf][3][2 * hh + 1]);
                quad_transpose(e, lid);
                int row = m0 + lrow[ri];
                if (row < M) {
                    __half2 p0 = __floats2half2_rn(e[0].x + b0.x, e[0].y + b0.y);
                    __half2 p1 = __floats2half2_rn(e[1].x + b0.z, e[1].y + b0.w);
                    __half2 p2 = __floats2half2_rn(e[2].x + b1.x, e[2].y + b1.y);
                    __half2 p3 = __floats2half2_rn(e[3].x + b1.z, e[3].y + b1.w);
                    *(uint4*)(g_node_tbl + (size_t)row * 640 + cg) =
                        make_uint4(*(uint32_t*)&p0, *(uint32_t*)&p1,
                                   *(uint32_t*)&p2, *(uint32_t*)&p3);
                }
            }
        }
    }
}

// ---------------- edge kernel: 256 threads, 1-term fp16, warp 32x32, fp16 gathers ----
__global__ void __launch_bounds__(256, 3) edge_kernel(
    const float* __restrict__ A, const int* __restrict__ EI, const float* __restrict__ AP) {
    extern __shared__ char smem[];
    uint32_t sb = smem_u32(smem);
    float* sEX = (float*)(smem + SM_EX);
    int tid = threadIdx.x;
    int wid = tid >> 5, lid = tid & 31;
    int m0 = blockIdx.x * 128;

#pragma unroll
    for (int u = tid; u < 4096; u += 256) {
        int r = u >> 5, c = (u & 31) << 2;
        float4 v = *(const float4*)(A + (size_t)(m0 + r) * 128 + c);
        __half2 h01 = __floats2half2_rn(v.x, v.y);
        __half2 h23 = __floats2half2_rn(v.z, v.w);
        uint32_t off = r * APITCH_B + c * 2;
        *(uint2*)(smem + SM_AH + off) = make_uint2(*(uint32_t*)&h01, *(uint32_t*)&h23);
    }
    __syncthreads();

    int wm = wid >> 1, wn = wid & 1;
    int lr = lid & 15, lc = lid >> 4;
    int q  = lid >> 2, lq = lid & 3;

    int lrow[4];
    lrow[0] = wm * 32 + q;  lrow[1] = lrow[0] + 8;
    lrow[2] = lrow[0] + 16; lrow[3] = lrow[0] + 24;
    int ss[4], dd[4];
#pragma unroll
    for (int i = 0; i < 4; i++) {
        int e = m0 + lrow[i];
        ss[i] = EI[e]; dd[i] = EI[N_EDGES + e];
    }

    for (int nt = 0; nt < 6; nt++) {
        float acc[2][4][4];
#pragma unroll
        for (int mf = 0; mf < 2; mf++)
#pragma unroll
            for (int f = 0; f < 4; f++)
#pragma unroll
                for (int j = 0; j < 4; j++) acc[mf][f][j] = 0.f;

        const uint2* bp = g_WEf + (size_t)(nt * 8 + wn * 4) * 256 + lid;
#pragma unroll
        for (int ks = 0; ks < 8; ks++) {
            uint32_t a0[4], a1[4];
            uint32_t aoff = (uint32_t)((wm * 32 + lr) * APITCH_B + (ks * 16 + lc * 8) * 2);
            LDSM_X4(a0[0], a0[1], a0[2], a0[3], sb + SM_AH + aoff);
            LDSM_X4(a1[0], a1[1], a1[2], a1[3], sb + SM_AH + aoff + 16 * APITCH_B);
            uint2 bv0 = bp[0 * 256 + ks * 32];
            uint2 bv1 = bp[1 * 256 + ks * 32];
            uint2 bv2 = bp[2 * 256 + ks * 32];
            uint2 bv3 = bp[3 * 256 + ks * 32];
            MMA_F16(acc[0][0], a0, bv0.x, bv0.y);
            MMA_F16(acc[0][1], a0, bv1.x, bv1.y);
            MMA_F16(acc[0][2], a0, bv2.x, bv2.y);
            MMA_F16(acc[0][3], a0, bv3.x, bv3.y);
            MMA_F16(acc[1][0], a1, bv0.x, bv0.y);
            MMA_F16(acc[1][1], a1, bv1.x, bv1.y);
            MMA_F16(acc[1][2], a1, bv2.x, bv2.y);
            MMA_F16(acc[1][3], a1, bv3.x, bv3.y);
        }

        int cg = nt * 64 + wn * 32 + lq * 8;
        if (nt < 4) {
            int head = nt * 2 + wn;
            float4 b0  = *(const float4*)(g_bE + cg);
            float4 b1  = *(const float4*)(g_bE + cg + 4);
            float4 ap0 = *(const float4*)(AP + head * 32 + lq * 8);
            float4 ap1 = *(const float4*)(AP + head * 32 + lq * 8 + 4);
#pragma unroll
            for (int mf = 0; mf < 2; mf++) {
                float p0, p1;
                {
                    float2 e[4];
                    e[0] = make_float2(acc[mf][0][0], acc[mf][0][1]);
                    e[1] = make_float2(acc[mf][1][0], acc[mf][1][1]);
                    e[2] = make_float2(acc[mf][2][0], acc[mf][2][1]);
                    e[3] = make_float2(acc[mf][3][0], acc[mf][3][1]);
                    quad_transpose(e, lid);
                    float4 i0, i1, j0, j1;
                    ld_h8(g_node_tbl + (size_t)ss[2 * mf] * 640 + cg, i0, i1);
                    ld_h8(g_node_tbl + (size_t)dd[2 * mf] * 640 + 256 + cg, j0, j1);
                    float h; p0 = 0.f;
                    h = e[0].x + b0.x + i0.x + j0.x; h = (h >= 0.f) ? h : NEG_SLOPE * h; p0 += h * ap0.x;
                    h = e[0].y + b0.y + i0.y + j0.y; h = (h >= 0.f) ? h : NEG_SLOPE * h; p0 += h * ap0.y;
                    h = e[1].x + b0.z + i0.z + j0.z; h = (h >= 0.f) ? h : NEG_SLOPE * h; p0 += h * ap0.z;
                    h = e[1].y + b0.w + i0.w + j0.w; h = (h >= 0.f) ? h : NEG_SLOPE * h; p0 += h * ap0.w;
                    h = e[2].x + b1.x + i1.x + j1.x; h = (h >= 0.f) ? h : NEG_SLOPE * h; p0 += h * ap1.x;
                    h = e[2].y + b1.y + i1.y + j1.y; h = (h >= 0.f) ? h : NEG_SLOPE * h; p0 += h * ap1.y;
                    h = e[3].x + b1.z + i1.z + j1.z; h = (h >= 0.f) ? h : NEG_SLOPE * h; p0 += h * ap1.z;
                    h = e[3].y + b1.w + i1.w + j1.w; h = (h >= 0.f) ? h : NEG_SLOPE * h; p0 += h * ap1.w;
                }
                {
                    float2 e[4];
                    e[0] = make_float2(acc[mf][0][2], acc[mf][0][3]);
                    e[1] = make_float2(acc[mf][1][2], acc[mf][1][3]);
                    e[2] = make_float2(acc[mf][2][2], acc[mf][2][3]);
                    e[3] = make_float2(acc[mf][3][2], acc[mf][3][3]);
                    quad_transpose(e, lid);
                    float4 i0, i1, j0, j1;
                    ld_h8(g_node_tbl + (size_t)ss[2 * mf + 1] * 640 + cg, i0, i1);
                    ld_h8(g_node_tbl + (size_t)dd[2 * mf + 1] * 640 + 256 + cg, j0, j1);
                    float h; p1 = 0.f;
                    h = e[0].x + b0.x + i0.x + j0.x; h = (h >= 0.f) ? h : NEG_SLOPE * h; p1 += h * ap0.x;
                    h = e[0].y + b0.y + i0.y + j0.y; h = (h >= 0.f) ? h : NEG_SLOPE * h; p1 += h * ap0.y;
                    h = e[1].x + b0.z + i0.z + j0.z; h = (h >= 0.f) ? h : NEG_SLOPE * h; p1 += h * ap0.z;
                    h = e[1].y + b0.w + i0.w + j0.w; h = (h >= 0.f) ? h : NEG_SLOPE * h; p1 += h * ap0.w;
                    h = e[2].x + b1.x + i1.x + j1.x; h = (h >= 0.f) ? h : NEG_SLOPE * h; p1 += h * ap1.x;
                    h = e[2].y + b1.y + i1.y + j1.y; h = (h >= 0.f) ? h : NEG_SLOPE * h; p1 += h * ap1.y;
                    h = e[3].x + b1.z + i1.z + j1.z; h = (h >= 0.f) ? h : NEG_SLOPE * h; p1 += h * ap1.z;
                    h = e[3].y + b1.w + i1.w + j1.w; h = (h >= 0.f) ? h : NEG_SLOPE * h; p1 += h * ap1.w;
                }
                p0 += __shfl_xor_sync(0xffffffffu, p0, 1);
                p0 += __shfl_xor_sync(0xffffffffu, p0, 2);
                p1 += __shfl_xor_sync(0xffffffffu, p1, 1);
                p1 += __shfl_xor_sync(0xffffffffu, p1, 2);
                if (lq == 0) {
                    float e0 = expf(p0), e1 = expf(p1);
                    sEX[lrow[2 * mf] * 8 + head]     = e0;
                    sEX[lrow[2 * mf + 1] * 8 + head] = e1;
                    atomicAdd(&g_node_sum[ss[2 * mf] * 8 + head], e0);
                    atomicAdd(&g_node_sum[ss[2 * mf + 1] * 8 + head], e1);
                }
            }
            if (nt == 3) __syncthreads();   // publish sEX before message phase
        } else {
            int cm = (nt - 4) * 64 + wn * 32 + lq * 8;
            int head = cm >> 4;
            float4 b0 = *(const float4*)(g_bE + 256 + cm);
            float4 b1 = *(const float4*)(g_bE + 256 + cm + 4);
#pragma unroll
            for (int mf = 0; mf < 2; mf++) {
#pragma unroll
                for (int hh = 0; hh < 2; hh++) {
                    int ri = 2 * mf + hh;
                    float2 e[4];
                    e[0] = make_float2(acc[mf][0][2 * hh], acc[mf][0][2 * hh + 1]);
                    e[1] = make_float2(acc[mf][1][2 * hh], acc[mf][1][2 * hh + 1]);
                    e[2] = make_float2(acc[mf][2][2 * hh], acc[mf][2][2 * hh + 1]);
                    e[3] = make_float2(acc[mf][3][2 * hh], acc[mf][3][2 * hh + 1]);
                    quad_transpose(e, lid);
                    float ex = sEX[lrow[ri] * 8 + head];
                    float4 n0, n1;
                    ld_h8(g_node_tbl + (size_t)dd[ri] * 640 + 512 + cm, n0, n1);
                    float* dst = g_agg + (size_t)ss[ri] * 128 + cm;
                    asm volatile("red.global.add.v4.f32 [%0], {%1,%2,%3,%4};"
                                 :: "l"(dst),
                                    "f"((e[0].x + b0.x + n0.x) * ex), "f"((e[0].y + b0.y + n0.y) * ex),
                                    "f"((e[1].x + b0.z + n0.z) * ex), "f"((e[1].y + b0.w + n0.w) * ex) : "memory");
                    asm volatile("red.global.add.v4.f32 [%0], {%1,%2,%3,%4};"
                                 :: "l"(dst + 4),
                                    "f"((e[2].x + b1.x + n1.x) * ex), "f"((e[2].y + b1.y + n1.y) * ex),
                                    "f"((e[3].x + b1.z + n1.z) * ex), "f"((e[3].y + b1.w + n1.w) * ex) : "memory");
                }
            }
        }
    }
}

// ---------------- output GEMM with softmax normalization folded into A load ----------------
__global__ void out_gemm_kernel(const float* __restrict__ A, const float* __restrict__ B,
                                const float* __restrict__ bias, const float* __restrict__ sums,
                                float* __restrict__ C, int M) {
    __shared__ float As[16][64];
    __shared__ float Bs[16][64];
    int tid = threadIdx.x;
    int rt = tid >> 4, ct = tid & 15;
    int m0 = blockIdx.x * 64, n0 = blockIdx.y * 64;
    float acc[4][4] = {};
    int arow = tid >> 2, aq = tid & 3;
    int bk = tid >> 4, bq = tid & 15;
    for (int k0 = 0; k0 < 128; k0 += 16) {
        float4 av = make_float4(0.f, 0.f, 0.f, 0.f);
        int m = m0 + arow;
        if (m < M) {
            av = *(const float4*)(A + (size_t)m * 128 + k0 + aq * 4);
            float s = sums[m * 8 + (k0 >> 4)];
            float inv = 1.0f / s;
            av.x *= inv; av.y *= inv; av.z *= inv; av.w *= inv;
        }
        As[aq * 4 + 0][arow] = av.x; As[aq * 4 + 1][arow] = av.y;
        As[aq * 4 + 2][arow] = av.z; As[aq * 4 + 3][arow] = av.w;
        float4 bv = *(const float4*)(B + (size_t)(k0 + bk) * 128 + n0 + bq * 4);
        *(float4*)&Bs[bk][bq * 4] = bv;
        __syncthreads();
#pragma unroll
        for (int kk = 0; kk < 16; kk++) {
            float a[4], b[4];
            *(float4*)a = *(float4*)&As[kk][rt * 4];
            *(float4*)b = *(float4*)&Bs[kk][ct * 4];
#pragma unroll
            for (int i = 0; i < 4; i++)
#pragma unroll
                for (int j = 0; j < 4; j++)
                    acc[i][j] += a[i] * b[j];
        }
        __syncthreads();
    }
#pragma unroll
    for (int i = 0; i < 4; i++) {
        int m = m0 + rt * 4 + i;
        if (m < M) {
            int n = n0 + ct * 4;
            float4 o;
            o.x = acc[i][0] + bias[n + 0];
            o.y = acc[i][1] + bias[n + 1];
            o.z = acc[i][2] + bias[n + 2];
            o.w = acc[i][3] + bias[n + 3];
            *(float4*)(C + (size_t)m * 128 + n) = o;
        }
    }
}

// ---------------- launch ----------------
extern "C" void kernel_launch(void* const* d_in, const int* in_sizes, int n_in,
                              void* d_out, int out_size) {
    const float* node_features = (const float*)d_in[0];
    const float* edge_features = (const float*)d_in[1];
    const int*   edge_index    = (const int*)d_in[2];
    const float* Wni = (const float*)d_in[3];
    const float* bni = (const float*)d_in[4];
    const float* Wnj = (const float*)d_in[5];
    const float* bnj = (const float*)d_in[6];
    const float* We  = (const float*)d_in[7];
    const float* be  = (const float*)d_in[8];
    const float* attn_proj = (const float*)d_in[9];
    const float* Wm  = (const float*)d_in[10];
    const float* bm  = (const float*)d_in[11];
    const float* Wo  = (const float*)d_in[12];
    const float* bo  = (const float*)d_in[13];
    float* out = (float*)d_out;

    float *pAgg, *pWO, *pSum;
    cudaGetSymbolAddress((void**)&pAgg, g_agg);
    cudaGetSymbolAddress((void**)&pWO,  g_WO);
    cudaGetSymbolAddress((void**)&pSum, g_node_sum);

    static bool attr_set = false;
    if (!attr_set) {
        cudaFuncSetAttribute(node_kernel, cudaFuncAttributeMaxDynamicSharedMemorySize, SMEM_NODE);
        cudaFuncSetAttribute(edge_kernel, cudaFuncAttributeMaxDynamicSharedMemorySize, SMEM_EDGE);
        attr_set = true;
    }

    const int ZTOT = N_NODES * NUM_HEADS + N_NODES * 128;
    zero_kernel<<<(ZTOT + 255) / 256, 256>>>();
    prepack_kernel<<<(16384 + 255) / 256, 256>>>(bni, bnj, be, bm, Wo);
    prepack2_kernel<<<(80 * 8 * 32 + 255) / 256, 256>>>(Wni, Wnj, We, Wm);

    // node tables: 157 M-tiles x 2 halves, 5 N-tiles each (1-term fp16, fp16 table out)
    node_kernel<<<dim3((N_NODES + 127) / 128, 2), 256, SMEM_NODE>>>(
        node_features, N_NODES, 5);

    // edge pass: 2500 M-tiles, warp 32x32, 6 N-tiles, 1-term fp16, fp16 gathers
    edge_kernel<<<N_EDGES / 128, 256, SMEM_EDGE>>>(
        edge_features, edge_index, attn_proj);

    // output projection with softmax normalization folded in
    out_gemm_kernel<<<dim3((N_NODES + 63) / 64, 2), 256>>>(pAgg, pWO, bo, pSum, out, N_NODES);
}